// round 1
// baseline (speedup 1.0000x reference)
#include <cuda_runtime.h>
#include <math.h>

#define BATCH 8
#define CIN   64
#define COUT  128
#define HH    128
#define WW    128
#define KH    5
#define KW    5
#define CKW   (CIN*KW)   // 320

// ---------------- scratch (device globals; no allocation) ----------------
__device__ float g_D[HH*HH];                 // forward DCT matrix  D[k][h]
__device__ float g_M[HH*HH];                 // inverse DCT matrix  M[n][k]
__device__ float g_xd[BATCH*CIN*HH*WW];      // DCT(x) along H      [b][c][k][w]
__device__ float g_wd[HH*COUT*CKW];          // DCT(weight) along H [k][o][c*5+j]
__device__ float g_y [BATCH*COUT*HH*WW];     // post-conv           [b][o][k][w]

// ---------------- constants: D and M ----------------
__global__ void k_consts() {
    int i = blockIdx.x * blockDim.x + threadIdx.x;
    if (i >= HH*HH) return;
    int r = i / HH, c = i % HH;
    // D[k=r][h=c] = 2*cos(pi*(2h+1)*k/(2N))
    double angD = M_PI * (2.0*c + 1.0) * r / (2.0*HH);
    g_D[i] = (float)(2.0 * cos(angD));
    // M[n=r][k=c] = cos(pi*(2n+1)*k/(2N)) * w_k / (2N), w_0 = 0.5
    double angM = M_PI * (2.0*r + 1.0) * c / (2.0*HH);
    double wk = (c == 0) ? 0.5 : 1.0;
    g_M[i] = (float)(cos(angM) * wk / (2.0*HH));
}

// ---------------- weight transform: wd[k][o][c*5+j] = sum_{h<5} D[k,h]*W[o,c,h,j] ----------------
__global__ void k_wtrans(const float* __restrict__ wgt) {
    int k = blockIdx.x;
    float d[KH];
#pragma unroll
    for (int h = 0; h < KH; h++) d[h] = g_D[k*HH + h];
    for (int idx = threadIdx.x; idx < COUT*CKW; idx += blockDim.x) {
        int o  = idx / CKW;
        int cj = idx % CKW;
        int c = cj / KW, j = cj % KW;
        float acc = 0.f;
#pragma unroll
        for (int h = 0; h < KH; h++)
            acc = fmaf(d[h], wgt[((o*CIN + c)*KH + h)*KW + j], acc);
        g_wd[(k*COUT + o)*CKW + cj] = acc;
    }
}

// ---------------- generic 128x128x128 GEMM: C = A @ B (+ bias) ----------------
// 256 threads, 8x8 register tile per thread. Cols strided by 16 -> conflict-free LDS.
__device__ __forceinline__ void gemm128(const float* __restrict__ A,
                                        const float* __restrict__ Bm,
                                        float* __restrict__ Cm,
                                        float biasv)
{
    __shared__ float sA[128][33];   // [row][kchunk] padded
    __shared__ float sB[32][128];
    int tid = threadIdx.x;
    int tx = tid & 15, ty = tid >> 4;
    int r0 = ty * 8;

    float acc[8][8];
#pragma unroll
    for (int i = 0; i < 8; i++)
#pragma unroll
        for (int l = 0; l < 8; l++) acc[i][l] = 0.f;

    for (int k0 = 0; k0 < 128; k0 += 32) {
#pragma unroll
        for (int s = 0; s < 16; s++) {
            int i = tid + 256*s;            // 0..4095
            int r = i >> 5, kc = i & 31;
            sA[r][kc] = A[r*128 + k0 + kc];
        }
#pragma unroll
        for (int s = 0; s < 16; s++) {
            int i = tid + 256*s;
            int kr = i >> 7, w = i & 127;
            sB[kr][w] = Bm[(k0 + kr)*128 + w];
        }
        __syncthreads();
#pragma unroll 8
        for (int kc = 0; kc < 32; kc++) {
            float a[8], b[8];
#pragma unroll
            for (int i = 0; i < 8; i++) a[i] = sA[r0 + i][kc];
#pragma unroll
            for (int l = 0; l < 8; l++) b[l] = sB[kc][tx + 16*l];
#pragma unroll
            for (int i = 0; i < 8; i++)
#pragma unroll
                for (int l = 0; l < 8; l++) acc[i][l] = fmaf(a[i], b[l], acc[i][l]);
        }
        __syncthreads();
    }
#pragma unroll
    for (int i = 0; i < 8; i++)
#pragma unroll
        for (int l = 0; l < 8; l++)
            Cm[(r0 + i)*128 + tx + 16*l] = acc[i][l] + biasv;
}

// ---------------- stage 1: xd[b,c] = D @ x[b,c] ----------------
__global__ void k_dct(const float* __restrict__ x) {
    int bc = blockIdx.x;                    // 0..511
    gemm128(g_D, x + (size_t)bc * HH * WW, g_xd + (size_t)bc * HH * WW, 0.f);
}

// ---------------- stage 3: per (b,k): y[o,w] = sum_{c,j} wd[k,o,cj] * xd[b,c,k,(w-j)&127] ----------------
__global__ void k_conv() {
    __shared__ float sX[CIN][WW];           // 32 KB: xd[b,:,k,:]
    __shared__ float sA[COUT][21];          // 20-col chunk of wd[k], padded

    int bk = blockIdx.x;                    // 0..1023
    int b = bk >> 7, k = bk & 127;
    int tid = threadIdx.x;
    int tx = tid & 15, ty = tid >> 4;
    int r0 = ty * 8;

    for (int i = tid; i < CIN*WW; i += 256) {
        int c = i >> 7, w = i & 127;
        sX[c][w] = g_xd[(((size_t)(b*CIN + c))*HH + k)*WW + w];
    }

    float acc[8][8];
#pragma unroll
    for (int i = 0; i < 8; i++)
#pragma unroll
        for (int l = 0; l < 8; l++) acc[i][l] = 0.f;

    const float* wdk = g_wd + (size_t)k * COUT * CKW;

    for (int cc = 0; cc < 16; cc++) {       // 16 chunks of (4 c's x 5 j) = 20 cols
        __syncthreads();                    // also covers initial sX load on cc==0
        for (int i = tid; i < COUT*20; i += 256) {
            int o = i / 20, t = i % 20;
            sA[o][t] = wdk[o*CKW + cc*20 + t];
        }
        __syncthreads();
#pragma unroll
        for (int c4 = 0; c4 < 4; c4++) {
            int c = cc*4 + c4;
#pragma unroll
            for (int j = 0; j < KW; j++) {
                float a[8], bb[8];
#pragma unroll
                for (int i = 0; i < 8; i++) a[i] = sA[r0 + i][c4*5 + j];
#pragma unroll
                for (int l = 0; l < 8; l++) bb[l] = sX[c][(tx + 16*l - j) & 127];
#pragma unroll
                for (int i = 0; i < 8; i++)
#pragma unroll
                    for (int l = 0; l < 8; l++) acc[i][l] = fmaf(a[i], bb[l], acc[i][l]);
            }
        }
    }

#pragma unroll
    for (int i = 0; i < 8; i++)
#pragma unroll
        for (int l = 0; l < 8; l++)
            g_y[(((size_t)(b*COUT + r0 + i))*HH + k)*WW + tx + 16*l] = acc[i][l];
}

// ---------------- stage 4: out[b,o] = M @ y[b,o] + bias[o] ----------------
__global__ void k_idct(const float* __restrict__ bias, float* __restrict__ out) {
    int bo = blockIdx.x;                    // 0..1023
    int o = bo & 127;
    gemm128(g_M, g_y + (size_t)bo * HH * WW, out + (size_t)bo * HH * WW, bias[o]);
}

// ---------------- launch ----------------
extern "C" void kernel_launch(void* const* d_in, const int* in_sizes, int n_in,
                              void* d_out, int out_size) {
    const float* x    = (const float*)d_in[0];   // (8,64,128,128)
    const float* wgt  = (const float*)d_in[1];   // (128,64,5,5)
    const float* bias = (const float*)d_in[2];   // (128,)
    float* out = (float*)d_out;                  // (8,128,128,128)

    k_consts<<<(HH*HH + 255)/256, 256>>>();
    k_wtrans<<<HH, 256>>>(wgt);
    k_dct  <<<BATCH*CIN, 256>>>(x);
    k_conv <<<BATCH*HH, 256>>>();
    k_idct <<<BATCH*COUT, 256>>>(bias, out);
}

// round 2
// speedup vs baseline: 1.5274x; 1.5274x over previous
#include <cuda_runtime.h>
#include <math.h>

#define BATCH 8
#define CIN   64
#define COUT  128
#define HH    128
#define WW    128
#define KH    5
#define KW    5
#define CKW   (CIN*KW)   // 320

// ---------------- scratch (device globals; no allocation) ----------------
__device__ float g_D[HH*HH];                 // forward DCT matrix  D[k][h]
__device__ float g_M[HH*HH];                 // inverse DCT matrix  M[n][k]
__device__ float g_xd[BATCH*CIN*HH*WW];      // DCT(x) along H      [b][c][k][w]
__device__ float g_wd[HH*COUT*CKW];          // DCT(weight) along H [k][o][c*5+j]
__device__ float g_y [BATCH*COUT*HH*WW];     // post-conv           [b][o][k][w]

// ---------------- constants: D and M ----------------
__global__ void k_consts() {
    int i = blockIdx.x * blockDim.x + threadIdx.x;
    if (i >= HH*HH) return;
    int r = i / HH, c = i % HH;
    // D[k=r][h=c] = 2*cos(pi*(2h+1)*k/(2N))
    double angD = M_PI * (2.0*c + 1.0) * r / (2.0*HH);
    g_D[i] = (float)(2.0 * cos(angD));
    // M[n=r][k=c] = cos(pi*(2n+1)*k/(2N)) * w_k / (2N), w_0 = 0.5
    double angM = M_PI * (2.0*r + 1.0) * c / (2.0*HH);
    double wk = (c == 0) ? 0.5 : 1.0;
    g_M[i] = (float)(cos(angM) * wk / (2.0*HH));
}

// ---------------- weight transform: wd[k][o][c*5+j] = sum_{h<5} D[k,h]*W[o,c,h,j] ----------------
__global__ void k_wtrans(const float* __restrict__ wgt) {
    int k = blockIdx.x;
    float d[KH];
#pragma unroll
    for (int h = 0; h < KH; h++) d[h] = g_D[k*HH + h];
    for (int idx = threadIdx.x; idx < COUT*CKW; idx += blockDim.x) {
        int o  = idx / CKW;
        int cj = idx % CKW;
        int c = cj / KW, j = cj % KW;
        float acc = 0.f;
#pragma unroll
        for (int h = 0; h < KH; h++)
            acc = fmaf(d[h], wgt[((o*CIN + c)*KH + h)*KW + j], acc);
        g_wd[(k*COUT + o)*CKW + cj] = acc;
    }
}

// ---------------- generic 128x128x128 GEMM: C = A @ B (+ bias) ----------------
// 256 threads, 8x8 register tile per thread. Cols strided by 16 -> conflict-free LDS.
__device__ __forceinline__ void gemm128(const float* __restrict__ A,
                                        const float* __restrict__ Bm,
                                        float* __restrict__ Cm,
                                        float biasv)
{
    __shared__ float sA[128][33];   // [row][kchunk] padded
    __shared__ float sB[32][128];
    int tid = threadIdx.x;
    int tx = tid & 15, ty = tid >> 4;
    int r0 = ty * 8;

    float acc[8][8];
#pragma unroll
    for (int i = 0; i < 8; i++)
#pragma unroll
        for (int l = 0; l < 8; l++) acc[i][l] = 0.f;

    for (int k0 = 0; k0 < 128; k0 += 32) {
#pragma unroll
        for (int s = 0; s < 16; s++) {
            int i = tid + 256*s;            // 0..4095
            int r = i >> 5, kc = i & 31;
            sA[r][kc] = A[r*128 + k0 + kc];
        }
#pragma unroll
        for (int s = 0; s < 16; s++) {
            int i = tid + 256*s;
            int kr = i >> 7, w = i & 127;
            sB[kr][w] = Bm[(k0 + kr)*128 + w];
        }
        __syncthreads();
#pragma unroll 8
        for (int kc = 0; kc < 32; kc++) {
            float a[8], b[8];
#pragma unroll
            for (int i = 0; i < 8; i++) a[i] = sA[r0 + i][kc];
#pragma unroll
            for (int l = 0; l < 8; l++) b[l] = sB[kc][tx + 16*l];
#pragma unroll
            for (int i = 0; i < 8; i++)
#pragma unroll
                for (int l = 0; l < 8; l++) acc[i][l] = fmaf(a[i], b[l], acc[i][l]);
        }
        __syncthreads();
    }
#pragma unroll
    for (int i = 0; i < 8; i++)
#pragma unroll
        for (int l = 0; l < 8; l++)
            Cm[(r0 + i)*128 + tx + 16*l] = acc[i][l] + biasv;
}

// ---------------- stage 1: xd[b,c] = D @ x[b,c] ----------------
__global__ void k_dct(const float* __restrict__ x) {
    int bc = blockIdx.x;                    // 0..511
    gemm128(g_D, x + (size_t)bc * HH * WW, g_xd + (size_t)bc * HH * WW, 0.f);
}

// ---------------- stage 3: per (b,k): y[o,w] = sum_{c,j} wd[k,o,cj] * xd[b,c,k,(w-j)&127] ----------------
__global__ void k_conv() {
    __shared__ float sX[CIN][WW];           // 32 KB: xd[b,:,k,:]
    __shared__ float sA[COUT][21];          // 20-col chunk of wd[k], padded

    int bk = blockIdx.x;                    // 0..1023
    int b = bk >> 7, k = bk & 127;
    int tid = threadIdx.x;
    int tx = tid & 15, ty = tid >> 4;
    int r0 = ty * 8;

    for (int i = tid; i < CIN*WW; i += 256) {
        int c = i >> 7, w = i & 127;
        sX[c][w] = g_xd[(((size_t)(b*CIN + c))*HH + k)*WW + w];
    }

    float acc[8][8];
#pragma unroll
    for (int i = 0; i < 8; i++)
#pragma unroll
        for (int l = 0; l < 8; l++) acc[i][l] = 0.f;

    const float* wdk = g_wd + (size_t)k * COUT * CKW;

    for (int cc = 0; cc < 16; cc++) {       // 16 chunks of (4 c's x 5 j) = 20 cols
        __syncthreads();                    // also covers initial sX load on cc==0
        for (int i = tid; i < COUT*20; i += 256) {
            int o = i / 20, t = i % 20;
            sA[o][t] = wdk[o*CKW + cc*20 + t];
        }
        __syncthreads();
#pragma unroll
        for (int c4 = 0; c4 < 4; c4++) {
            int c = cc*4 + c4;
#pragma unroll
            for (int j = 0; j < KW; j++) {
                float a[8], bb[8];
#pragma unroll
                for (int i = 0; i < 8; i++) a[i] = sA[r0 + i][c4*5 + j];
#pragma unroll
                for (int l = 0; l < 8; l++) bb[l] = sX[c][(tx + 16*l - j) & 127];
#pragma unroll
                for (int i = 0; i < 8; i++)
#pragma unroll
                    for (int l = 0; l < 8; l++) acc[i][l] = fmaf(a[i], bb[l], acc[i][l]);
            }
        }
    }

#pragma unroll
    for (int i = 0; i < 8; i++)
#pragma unroll
        for (int l = 0; l < 8; l++)
            g_y[(((size_t)(b*COUT + r0 + i))*HH + k)*WW + tx + 16*l] = acc[i][l];
}

// ---------------- stage 4: out[b,o] = M @ y[b,o] + bias[o] ----------------
__global__ void k_idct(const float* __restrict__ bias, float* __restrict__ out) {
    int bo = blockIdx.x;                    // 0..1023
    int o = bo & 127;
    gemm128(g_M, g_y + (size_t)bo * HH * WW, out + (size_t)bo * HH * WW, bias[o]);
}

// ---------------- launch ----------------
extern "C" void kernel_launch(void* const* d_in, const int* in_sizes, int n_in,
                              void* d_out, int out_size) {
    const float* x    = (const float*)d_in[0];   // (8,64,128,128)
    const float* wgt  = (const float*)d_in[1];   // (128,64,5,5)
    const float* bias = (const float*)d_in[2];   // (128,)
    float* out = (float*)d_out;                  // (8,128,128,128)

    k_consts<<<(HH*HH + 255)/256, 256>>>();
    k_wtrans<<<HH, 256>>>(wgt);
    k_dct  <<<BATCH*CIN, 256>>>(x);
    k_conv <<<BATCH*HH, 256>>>();
    k_idct <<<BATCH*COUT, 256>>>(bias, out);
}

// round 6
// speedup vs baseline: 2.3174x; 1.5172x over previous
#include <cuda_runtime.h>
#include <cuda_bf16.h>
#include <math.h>

typedef unsigned int       u32;
typedef unsigned short     u16;
typedef unsigned long long u64;

#define BATCH 8
#define CIN   64
#define COUT  128
#define HH    128
#define WW    128

// ---------------- device globals (packed bf16 split planes; u32 = 2 bf16 along last dim) ----------------
__device__ u32 g_Dh[8192], g_Dl[8192];        // DCT matrix  [k][h/2]
__device__ u32 g_Mh[8192], g_Ml[8192];        // iDCT matrix [n][k/2]
__device__ float g_D5[640];                   // first 5 cols of D
__device__ u32 g_wdh[128*5*4096], g_wdl[128*5*4096];              // [k][j] tiles of [o][c/2] (128x32 u32)
__device__ u32 g_xdh[BATCH*CIN*HH*64],  g_xdl[BATCH*CIN*HH*64];   // [b][c][k][w/2]
__device__ u32 g_yh [BATCH*COUT*HH*64], g_yl [BATCH*COUT*HH*64];  // [b][o][k][w/2]

// ---------------- helpers ----------------
__device__ __forceinline__ u32 smem_u32(const void* p) {
    u32 a; asm("{ .reg .u64 t; cvta.to.shared.u64 t, %1; cvt.u32.u64 %0, t; }" : "=r"(a) : "l"(p));
    return a;
}
__device__ __forceinline__ void ldsm_x4(u32& r0, u32& r1, u32& r2, u32& r3, u32 addr) {
    asm volatile("ldmatrix.sync.aligned.m8n8.x4.shared.b16 {%0,%1,%2,%3}, [%4];"
        : "=r"(r0), "=r"(r1), "=r"(r2), "=r"(r3) : "r"(addr) : "memory");
}
__device__ __forceinline__ void ldsm_x2(u32& r0, u32& r1, u32 addr) {
    asm volatile("ldmatrix.sync.aligned.m8n8.x2.shared.b16 {%0,%1}, [%2];"
        : "=r"(r0), "=r"(r1) : "r"(addr) : "memory");
}
__device__ __forceinline__ void mma_bf16(float* c, u32 a0, u32 a1, u32 a2, u32 a3, u32 b0, u32 b1) {
    asm volatile("mma.sync.aligned.m16n8k16.row.col.f32.bf16.bf16.f32 "
        "{%0,%1,%2,%3}, {%4,%5,%6,%7}, {%8,%9}, {%0,%1,%2,%3};"
        : "+f"(c[0]), "+f"(c[1]), "+f"(c[2]), "+f"(c[3])
        : "r"(a0), "r"(a1), "r"(a2), "r"(a3), "r"(b0), "r"(b1));
}
__device__ __forceinline__ void f2bf2(float v, u16& h, u16& l) {
    __nv_bfloat16 bh = __float2bfloat16(v);
    float fh = __bfloat162float(bh);
    __nv_bfloat16 bl = __float2bfloat16(v - fh);
    h = __bfloat16_as_ushort(bh);
    l = __bfloat16_as_ushort(bl);
}

// ---------------- constants ----------------
__global__ void k_consts() {
    int idx = blockIdx.x * blockDim.x + threadIdx.x;
    if (idx < 640) {
        int k = idx / 5, h = idx % 5;
        g_D5[idx] = (float)(2.0 * cos(M_PI * (2.0*h + 1.0) * k / 256.0));
    }
    if (idx >= 8192) return;
    int r = idx >> 6, cp = idx & 63;
    int c0 = 2*cp, c1 = 2*cp + 1;
    u16 h0, l0, h1, l1;
    float d0 = (float)(2.0 * cos(M_PI * (2.0*c0 + 1.0) * r / 256.0));
    float d1 = (float)(2.0 * cos(M_PI * (2.0*c1 + 1.0) * r / 256.0));
    f2bf2(d0, h0, l0); f2bf2(d1, h1, l1);
    g_Dh[idx] = (u32)h0 | ((u32)h1 << 16);
    g_Dl[idx] = (u32)l0 | ((u32)l1 << 16);
    float m0 = (float)(cos(M_PI * (2.0*r + 1.0) * c0 / 256.0) * ((c0 == 0) ? 0.5 : 1.0) / 256.0);
    float m1 = (float)(cos(M_PI * (2.0*r + 1.0) * c1 / 256.0) / 256.0);
    f2bf2(m0, h0, l0); f2bf2(m1, h1, l1);
    g_Mh[idx] = (u32)h0 | ((u32)h1 << 16);
    g_Ml[idx] = (u32)l0 | ((u32)l1 << 16);
}

// ---------------- weight transform: wd[k][j][o][c] = sum_h D[k,h]*W[o,c,h,j] ----------------
__global__ void k_wtrans(const float* __restrict__ wgt) {
    __shared__ float sw[5*64];
    int j = blockIdx.x >> 7, o = blockIdx.x & 127;
    int tid = threadIdx.x;
    for (int i = tid; i < 320; i += 256) {           // FIX: full 5x64 coverage with 256 threads
        int h = i >> 6, c = i & 63;
        sw[h*64 + c] = wgt[((o*64 + c)*5 + h)*5 + j];
    }
    __syncthreads();
    for (int i = tid; i < 4096; i += 256) {
        int k = i >> 5, cp = i & 31;
        float a0 = 0.f, a1 = 0.f;
#pragma unroll
        for (int h = 0; h < 5; h++) {
            float d = g_D5[k*5 + h];
            a0 = fmaf(d, sw[h*64 + 2*cp],     a0);
            a1 = fmaf(d, sw[h*64 + 2*cp + 1], a1);
        }
        u16 h0, l0, h1, l1; f2bf2(a0, h0, l0); f2bf2(a1, h1, l1);
        u32 oi = (u32)(k*5 + j)*4096 + o*32 + cp;
        g_wdh[oi] = (u32)h0 | ((u32)h1 << 16);
        g_wdl[oi] = (u32)l0 | ((u32)l1 << 16);
    }
}

// ---------------- generic 128x128x128 mma GEMM ----------------
// MODE 0 (stage 1): A=D planes, B from fp32 x slice [h][w]; split-store to g_xd planes
// MODE 1 (stage 4): A=M planes, B from g_y planes slice [k][w]; fp32 + bias store to out
#define TS1 272   // bf16 row stride bytes (136 bf16 = 68 u32), K=128 tiles
template<int MODE>
__global__ __launch_bounds__(256, 1)
void k_gemm(const float* __restrict__ xsrc, const float* __restrict__ bias, float* __restrict__ outp) {
    extern __shared__ __align__(16) char sm[];
    const u32 OFF_AH = 0, OFF_AL = 34816, OFF_BH = 69632, OFF_BL = 104448, OFF_ST = 139264;
    u32 sb = smem_u32(sm);
    int tid = threadIdx.x, wid = tid >> 5, lane = tid & 31;

    // A tiles: rows r (M), cols = K (contiguous pairs)
    {
        const u32* Ah = MODE ? g_Mh : g_Dh;
        const u32* Al = MODE ? g_Ml : g_Dl;
        u32* dAh = (u32*)(sm + OFF_AH);
        u32* dAl = (u32*)(sm + OFF_AL);
        for (int i = tid; i < 8192; i += 256) {
            int r = i >> 6, cp = i & 63;
            dAh[r*68 + cp] = Ah[i];
            dAl[r*68 + cp] = Al[i];
        }
    }
    // stage B source
    if (MODE == 0) {
        const float4* s4 = (const float4*)(xsrc + (size_t)blockIdx.x * 16384);
        float4* d4 = (float4*)(sm + OFF_ST);
        for (int i = tid; i < 4096; i += 256) d4[i] = s4[i];
    } else {
        const u32* yh = g_yh + (size_t)blockIdx.x * 8192;
        const u32* yl = g_yl + (size_t)blockIdx.x * 8192;
        u32* st = (u32*)(sm + OFF_ST);
        for (int i = tid; i < 8192; i += 256) { st[i] = yh[i]; st[8192 + i] = yl[i]; }
    }
    __syncthreads();
    // build B^T tiles: B[w][h] from staged [h][w]
    {
        u32* dBh = (u32*)(sm + OFF_BH);
        u32* dBl = (u32*)(sm + OFF_BL);
        for (int i = tid; i < 8192; i += 256) {
            int w = i & 127, hp = i >> 7;
            if (MODE == 0) {
                const float* st = (const float*)(sm + OFF_ST);
                u16 h0, l0, h1, l1;
                f2bf2(st[(2*hp)*128 + w],     h0, l0);
                f2bf2(st[(2*hp + 1)*128 + w], h1, l1);
                dBh[w*68 + hp] = (u32)h0 | ((u32)h1 << 16);
                dBl[w*68 + hp] = (u32)l0 | ((u32)l1 << 16);
            } else {
                const u16* sh = (const u16*)(sm + OFF_ST);
                const u16* sl = sh + 16384;
                dBh[w*68 + hp] = (u32)sh[(2*hp)*128 + w] | ((u32)sh[(2*hp + 1)*128 + w] << 16);
                dBl[w*68 + hp] = (u32)sl[(2*hp)*128 + w] | ((u32)sl[(2*hp + 1)*128 + w] << 16);
            }
        }
    }
    __syncthreads();

    // warp tiles: 4x2 grid of (M=32, N=64)
    int m0 = (wid >> 1) * 32, n0 = (wid & 1) * 64;
    int rowA = lane & 15;
    int kA = (lane & 16) ? 8 : 0;
    int rowB = lane & 7;
    int kB = (lane & 8) ? 8 : 0;

    float acc[2][8][4];
#pragma unroll
    for (int mt = 0; mt < 2; mt++)
#pragma unroll
        for (int nt = 0; nt < 8; nt++)
#pragma unroll
            for (int q = 0; q < 4; q++) acc[mt][nt][q] = 0.f;

    for (int ks = 0; ks < 8; ks++) {
        int k0 = ks * 16;
        u32 ah[2][4], al[2][4];
#pragma unroll
        for (int mt = 0; mt < 2; mt++) {
            u32 base = (u32)((m0 + mt*16 + rowA) * TS1 + (k0 + kA) * 2);
            ldsm_x4(ah[mt][0], ah[mt][1], ah[mt][2], ah[mt][3], sb + OFF_AH + base);
            ldsm_x4(al[mt][0], al[mt][1], al[mt][2], al[mt][3], sb + OFF_AL + base);
        }
#pragma unroll
        for (int nt = 0; nt < 8; nt++) {
            u32 base = (u32)((n0 + nt*8 + rowB) * TS1 + (k0 + kB) * 2);
            u32 bh0, bh1, bl0, bl1;
            ldsm_x2(bh0, bh1, sb + OFF_BH + base);
            ldsm_x2(bl0, bl1, sb + OFF_BL + base);
#pragma unroll
            for (int mt = 0; mt < 2; mt++) {
                mma_bf16(acc[mt][nt], ah[mt][0], ah[mt][1], ah[mt][2], ah[mt][3], bh0, bh1);
                mma_bf16(acc[mt][nt], ah[mt][0], ah[mt][1], ah[mt][2], ah[mt][3], bl0, bl1);
                mma_bf16(acc[mt][nt], al[mt][0], al[mt][1], al[mt][2], al[mt][3], bh0, bh1);
            }
        }
    }

    // epilogue through fp32 staging
    __syncthreads();
    float* se = (float*)(sm + OFF_ST);   // [128][129]
#pragma unroll
    for (int mt = 0; mt < 2; mt++)
#pragma unroll
        for (int nt = 0; nt < 8; nt++) {
            int r = m0 + mt*16 + (lane >> 2);
            int c = n0 + nt*8 + 2*(lane & 3);
            se[r*129 + c]           = acc[mt][nt][0];
            se[r*129 + c + 1]       = acc[mt][nt][1];
            se[(r + 8)*129 + c]     = acc[mt][nt][2];
            se[(r + 8)*129 + c + 1] = acc[mt][nt][3];
        }
    __syncthreads();

    if (MODE == 0) {
        u32* oh = g_xdh + (size_t)blockIdx.x * 8192;
        u32* ol = g_xdl + (size_t)blockIdx.x * 8192;
        for (int i = tid; i < 8192; i += 256) {
            int r = i >> 6, np = i & 63;
            u16 h0, l0, h1, l1;
            f2bf2(se[r*129 + 2*np],     h0, l0);
            f2bf2(se[r*129 + 2*np + 1], h1, l1);
            oh[r*64 + np] = (u32)h0 | ((u32)h1 << 16);
            ol[r*64 + np] = (u32)l0 | ((u32)l1 << 16);
        }
    } else {
        float bv = bias[blockIdx.x & 127];
        float* op = outp + (size_t)blockIdx.x * 16384;
        for (int i = tid; i < 16384; i += 256) {
            int r = i >> 7, n = i & 127;
            op[r*128 + n] = se[r*129 + n] + bv;
        }
    }
}

// ---------------- stage 3: per (b,k): y[o,w] = sum_{j,c} wd[k,j,o,c] * xd[b,c,k,(w-j)&127] ----------------
#define TS3 144   // bf16 row stride bytes (72 bf16 = 36 u32), K=64 tiles
__global__ __launch_bounds__(256, 1)
void k_conv_mma() {
    extern __shared__ __align__(16) char sm[];
    const u32 OFF_XH = 0, OFF_XL = 16384, OFF_AH = 32768, OFF_AL = 51200,
              OFF_BH = 69632, OFF_BL = 88064;
    u32 sb = smem_u32(sm);
    int tid = threadIdx.x, wid = tid >> 5, lane = tid & 31;
    int blk = blockIdx.x, b = blk >> 7, k = blk & 127;

    // stage xd slice: X[c][w] hi/lo packed u32 [64][64]
    {
        u32* shx = (u32*)(sm + OFF_XH);
        u32* slx = (u32*)(sm + OFF_XL);
        for (int i = tid; i < 4096; i += 256) {
            int c = i >> 6, wp = i & 63;
            size_t gi = ((size_t)(b*64 + c)*128 + k)*64 + wp;
            shx[i] = g_xdh[gi];
            slx[i] = g_xdl[gi];
        }
    }
    __syncthreads();
    // build B0[w][c] (128 x 64 bf16, stride 72 bf16) from X
    {
        const u16* sh = (const u16*)(sm + OFF_XH);
        const u16* sl = (const u16*)(sm + OFF_XL);
        u32* dBh = (u32*)(sm + OFF_BH);
        u32* dBl = (u32*)(sm + OFF_BL);
        for (int i = tid; i < 4096; i += 256) {
            int w = i & 127, cp = i >> 7;
            dBh[w*36 + cp] = (u32)sh[(2*cp)*128 + w] | ((u32)sh[(2*cp + 1)*128 + w] << 16);
            dBl[w*36 + cp] = (u32)sl[(2*cp)*128 + w] | ((u32)sl[(2*cp + 1)*128 + w] << 16);
        }
    }

    int m0 = (wid >> 1) * 32, n0 = (wid & 1) * 64;
    int rowA = lane & 15;
    int kA = (lane & 16) ? 8 : 0;
    int rowB = lane & 7;
    int kB = (lane & 8) ? 8 : 0;

    float acc[2][8][4];
#pragma unroll
    for (int mt = 0; mt < 2; mt++)
#pragma unroll
        for (int nt = 0; nt < 8; nt++)
#pragma unroll
            for (int q = 0; q < 4; q++) acc[mt][nt][q] = 0.f;

    for (int j = 0; j < 5; j++) {
        // A_j[o][c] (128 x 64 bf16, stride 72 bf16)
        __syncthreads();
        {
            size_t wbase = (size_t)(k*5 + j) * 4096;
            u32* dAh = (u32*)(sm + OFF_AH);
            u32* dAl = (u32*)(sm + OFF_AL);
            for (int i = tid; i < 4096; i += 256) {
                int o = i >> 5, cp = i & 31;
                dAh[o*36 + cp] = g_wdh[wbase + i];
                dAl[o*36 + cp] = g_wdl[wbase + i];
            }
        }
        __syncthreads();
#pragma unroll
        for (int ks = 0; ks < 4; ks++) {
            int k0 = ks * 16;
            u32 ah[2][4], al[2][4];
#pragma unroll
            for (int mt = 0; mt < 2; mt++) {
                u32 base = (u32)((m0 + mt*16 + rowA) * TS3 + (k0 + kA) * 2);
                ldsm_x4(ah[mt][0], ah[mt][1], ah[mt][2], ah[mt][3], sb + OFF_AH + base);
                ldsm_x4(al[mt][0], al[mt][1], al[mt][2], al[mt][3], sb + OFF_AL + base);
            }
#pragma unroll
            for (int nt = 0; nt < 8; nt++) {
                int wr = ((n0 + nt*8 + rowB) - j) & 127;          // circular shift along w
                u32 base = (u32)(wr * TS3 + (k0 + kB) * 2);
                u32 bh0, bh1, bl0, bl1;
                ldsm_x2(bh0, bh1, sb + OFF_BH + base);
                ldsm_x2(bl0, bl1, sb + OFF_BL + base);
#pragma unroll
                for (int mt = 0; mt < 2; mt++) {
                    mma_bf16(acc[mt][nt], ah[mt][0], ah[mt][1], ah[mt][2], ah[mt][3], bh0, bh1);
                    mma_bf16(acc[mt][nt], ah[mt][0], ah[mt][1], ah[mt][2], ah[mt][3], bl0, bl1);
                    mma_bf16(acc[mt][nt], al[mt][0], al[mt][1], al[mt][2], al[mt][3], bh0, bh1);
                }
            }
        }
    }

    // epilogue through fp32 staging (reuse A/B region)
    __syncthreads();
    float* se = (float*)(sm + OFF_AH);   // [128][129]
#pragma unroll
    for (int mt = 0; mt < 2; mt++)
#pragma unroll
        for (int nt = 0; nt < 8; nt++) {
            int r = m0 + mt*16 + (lane >> 2);
            int c = n0 + nt*8 + 2*(lane & 3);
            se[r*129 + c]           = acc[mt][nt][0];
            se[r*129 + c + 1]       = acc[mt][nt][1];
            se[(r + 8)*129 + c]     = acc[mt][nt][2];
            se[(r + 8)*129 + c + 1] = acc[mt][nt][3];
        }
    __syncthreads();
    for (int i = tid; i < 8192; i += 256) {
        int o = i >> 6, wp = i & 63;
        u16 h0, l0, h1, l1;
        f2bf2(se[o*129 + 2*wp],     h0, l0);
        f2bf2(se[o*129 + 2*wp + 1], h1, l1);
        size_t gi = ((size_t)(b*128 + o))*8192 + (size_t)k*64 + wp;
        g_yh[gi] = (u32)h0 | ((u32)h1 << 16);
        g_yl[gi] = (u32)l0 | ((u32)l1 << 16);
    }
}

// ---------------- launch ----------------
extern "C" void kernel_launch(void* const* d_in, const int* in_sizes, int n_in,
                              void* d_out, int out_size) {
    const float* x    = (const float*)d_in[0];   // (8,64,128,128)
    const float* wgt  = (const float*)d_in[1];   // (128,64,5,5)
    const float* bias = (const float*)d_in[2];   // (128,)
    float* out = (float*)d_out;                  // (8,128,128,128)

    const int SM14 = 139264 + 66048;   // 205312
    const int SM3  = 106496;
    cudaFuncSetAttribute(k_gemm<0>,  cudaFuncAttributeMaxDynamicSharedMemorySize, SM14);
    cudaFuncSetAttribute(k_gemm<1>,  cudaFuncAttributeMaxDynamicSharedMemorySize, SM14);
    cudaFuncSetAttribute(k_conv_mma, cudaFuncAttributeMaxDynamicSharedMemorySize, SM3);

    k_consts  <<<32, 256>>>();
    k_wtrans  <<<640, 256>>>(wgt);
    k_gemm<0> <<<BATCH*CIN,  256, SM14>>>(x, nullptr, nullptr);
    k_conv_mma<<<BATCH*HH,   256, SM3 >>>();
    k_gemm<1> <<<BATCH*COUT, 256, SM14>>>(nullptr, bias, out);
}

// round 7
// speedup vs baseline: 3.2906x; 1.4199x over previous
#include <cuda_runtime.h>
#include <cuda_bf16.h>
#include <math.h>

typedef unsigned int       u32;
typedef unsigned short     u16;
typedef unsigned long long u64;

#define BATCH 8
#define CIN   64
#define COUT  128
#define HH    128
#define WW    128

// ---------------- device globals (packed bf16 split planes; u32 = 2 bf16 along last dim) ----------------
__device__ u32 g_Dh[8192], g_Dl[8192];        // DCT matrix  [k][h/2]
__device__ u32 g_Mh[8192], g_Ml[8192];        // iDCT matrix [n][k/2]
__device__ float g_D5[640];                   // first 5 cols of D
__device__ u32 g_wdh[128*5*4096], g_wdl[128*5*4096];              // [k][j] tiles of [o][c/2] (128x32 u32)
__device__ u32 g_xdh[BATCH*CIN*HH*64],  g_xdl[BATCH*CIN*HH*64];   // [b][c][k][w/2]
__device__ u32 g_yh [BATCH*COUT*HH*64], g_yl [BATCH*COUT*HH*64];  // [b][o][k][w/2]

// ---------------- helpers ----------------
__device__ __forceinline__ u32 smem_u32(const void* p) {
    u32 a; asm("{ .reg .u64 t; cvta.to.shared.u64 t, %1; cvt.u32.u64 %0, t; }" : "=r"(a) : "l"(p));
    return a;
}
__device__ __forceinline__ void ldsm_x4(u32& r0, u32& r1, u32& r2, u32& r3, u32 addr) {
    asm volatile("ldmatrix.sync.aligned.m8n8.x4.shared.b16 {%0,%1,%2,%3}, [%4];"
        : "=r"(r0), "=r"(r1), "=r"(r2), "=r"(r3) : "r"(addr) : "memory");
}
__device__ __forceinline__ void ldsm_x2(u32& r0, u32& r1, u32 addr) {
    asm volatile("ldmatrix.sync.aligned.m8n8.x2.shared.b16 {%0,%1}, [%2];"
        : "=r"(r0), "=r"(r1) : "r"(addr) : "memory");
}
__device__ __forceinline__ void mma_bf16(float* c, u32 a0, u32 a1, u32 a2, u32 a3, u32 b0, u32 b1) {
    asm volatile("mma.sync.aligned.m16n8k16.row.col.f32.bf16.bf16.f32 "
        "{%0,%1,%2,%3}, {%4,%5,%6,%7}, {%8,%9}, {%0,%1,%2,%3};"
        : "+f"(c[0]), "+f"(c[1]), "+f"(c[2]), "+f"(c[3])
        : "r"(a0), "r"(a1), "r"(a2), "r"(a3), "r"(b0), "r"(b1));
}
__device__ __forceinline__ void f2bf2(float v, u16& h, u16& l) {
    __nv_bfloat16 bh = __float2bfloat16(v);
    float fh = __bfloat162float(bh);
    __nv_bfloat16 bl = __float2bfloat16(v - fh);
    h = __bfloat16_as_ushort(bh);
    l = __bfloat16_as_ushort(bl);
}

// ---------------- constants ----------------
__global__ void k_consts() {
    int idx = blockIdx.x * blockDim.x + threadIdx.x;
    if (idx < 640) {
        int k = idx / 5, h = idx % 5;
        g_D5[idx] = (float)(2.0 * cos(M_PI * (2.0*h + 1.0) * k / 256.0));
    }
    if (idx >= 8192) return;
    int r = idx >> 6, cp = idx & 63;
    int c0 = 2*cp, c1 = 2*cp + 1;
    u16 h0, l0, h1, l1;
    float d0 = (float)(2.0 * cos(M_PI * (2.0*c0 + 1.0) * r / 256.0));
    float d1 = (float)(2.0 * cos(M_PI * (2.0*c1 + 1.0) * r / 256.0));
    f2bf2(d0, h0, l0); f2bf2(d1, h1, l1);
    g_Dh[idx] = (u32)h0 | ((u32)h1 << 16);
    g_Dl[idx] = (u32)l0 | ((u32)l1 << 16);
    float m0 = (float)(cos(M_PI * (2.0*r + 1.0) * c0 / 256.0) * ((c0 == 0) ? 0.5 : 1.0) / 256.0);
    float m1 = (float)(cos(M_PI * (2.0*r + 1.0) * c1 / 256.0) / 256.0);
    f2bf2(m0, h0, l0); f2bf2(m1, h1, l1);
    g_Mh[idx] = (u32)h0 | ((u32)h1 << 16);
    g_Ml[idx] = (u32)l0 | ((u32)l1 << 16);
}

// ---------------- weight transform: wd[k][j][o][c] = sum_h D[k,h]*W[o,c,h,j] ----------------
__global__ void k_wtrans(const float* __restrict__ wgt) {
    __shared__ float sw[5*64];
    int j = blockIdx.x >> 7, o = blockIdx.x & 127;
    int tid = threadIdx.x;
    for (int i = tid; i < 320; i += 256) {
        int h = i >> 6, c = i & 63;
        sw[h*64 + c] = wgt[((o*64 + c)*5 + h)*5 + j];
    }
    __syncthreads();
    for (int i = tid; i < 4096; i += 256) {
        int k = i >> 5, cp = i & 31;
        float a0 = 0.f, a1 = 0.f;
#pragma unroll
        for (int h = 0; h < 5; h++) {
            float d = g_D5[k*5 + h];
            a0 = fmaf(d, sw[h*64 + 2*cp],     a0);
            a1 = fmaf(d, sw[h*64 + 2*cp + 1], a1);
        }
        u16 h0, l0, h1, l1; f2bf2(a0, h0, l0); f2bf2(a1, h1, l1);
        u32 oi = (u32)(k*5 + j)*4096 + o*32 + cp;
        g_wdh[oi] = (u32)h0 | ((u32)h1 << 16);
        g_wdl[oi] = (u32)l0 | ((u32)l1 << 16);
    }
}

// ---------------- generic 128x128x128 mma GEMM, K split into 2x64 chunks ----------------
// MODE 0 (stage 1): A=D planes, B from fp32 x slice [h][w]; split-store to g_xd planes
// MODE 1 (stage 4): A=M planes, B from g_y planes slice [k][w]; fp32 + bias store to out
// smem: A/B tiles 128 rows x 64 bf16, row stride 144B (18432B each); staging 32KB. total 106496.
#define TSB 144
template<int MODE>
__global__ __launch_bounds__(256, 2)
void k_gemm(const float* __restrict__ xsrc, const float* __restrict__ bias, float* __restrict__ outp) {
    extern __shared__ __align__(16) char sm[];
    const u32 OFF_AH = 0, OFF_AL = 18432, OFF_BH = 36864, OFF_BL = 55296, OFF_ST = 73728;
    u32 sb = smem_u32(sm);
    int tid = threadIdx.x, wid = tid >> 5, lane = tid & 31;

    int m0 = (wid >> 1) * 32, n0 = (wid & 1) * 64;
    int rowA = lane & 15;
    int kA = (lane & 16) ? 8 : 0;
    int rowB = lane & 7;
    int kB = (lane & 8) ? 8 : 0;

    float acc[2][8][4];
#pragma unroll
    for (int mt = 0; mt < 2; mt++)
#pragma unroll
        for (int nt = 0; nt < 8; nt++)
#pragma unroll
            for (int q = 0; q < 4; q++) acc[mt][nt][q] = 0.f;

    for (int kk = 0; kk < 2; kk++) {
        __syncthreads();   // prev chunk's MMAs done before restaging
        // stage B source half
        if (MODE == 0) {
            const float4* s4 = (const float4*)(xsrc + (size_t)blockIdx.x * 16384 + (size_t)kk * 8192);
            float4* d4 = (float4*)(sm + OFF_ST);
            for (int i = tid; i < 2048; i += 256) d4[i] = s4[i];
        } else {
            const u32* yh = g_yh + (size_t)blockIdx.x * 8192 + (size_t)kk * 4096;
            const u32* yl = g_yl + (size_t)blockIdx.x * 8192 + (size_t)kk * 4096;
            u32* st = (u32*)(sm + OFF_ST);
            for (int i = tid; i < 4096; i += 256) { st[i] = yh[i]; st[4096 + i] = yl[i]; }
        }
        // A half tiles (independent of staging)
        {
            const u32* Ah = MODE ? g_Mh : g_Dh;
            const u32* Al = MODE ? g_Ml : g_Dl;
            u32* dAh = (u32*)(sm + OFF_AH);
            u32* dAl = (u32*)(sm + OFF_AL);
            for (int i = tid; i < 4096; i += 256) {
                int r = i >> 5, cp = i & 31;
                dAh[r*36 + cp] = Ah[r*64 + kk*32 + cp];
                dAl[r*36 + cp] = Al[r*64 + kk*32 + cp];
            }
        }
        __syncthreads();
        // build B^T half: B[w][h-local] from staged [h-local][w]
        {
            u32* dBh = (u32*)(sm + OFF_BH);
            u32* dBl = (u32*)(sm + OFF_BL);
            for (int i = tid; i < 4096; i += 256) {
                int w = i & 127, hp = i >> 7;      // hp = 0..31 (pairs within this 64-half)
                if (MODE == 0) {
                    const float* st = (const float*)(sm + OFF_ST);
                    u16 h0, l0, h1, l1;
                    f2bf2(st[(2*hp)*128 + w],     h0, l0);
                    f2bf2(st[(2*hp + 1)*128 + w], h1, l1);
                    dBh[w*36 + hp] = (u32)h0 | ((u32)h1 << 16);
                    dBl[w*36 + hp] = (u32)l0 | ((u32)l1 << 16);
                } else {
                    const u16* sh = (const u16*)(sm + OFF_ST);
                    const u16* sl = sh + 8192;
                    dBh[w*36 + hp] = (u32)sh[(2*hp)*128 + w] | ((u32)sh[(2*hp + 1)*128 + w] << 16);
                    dBl[w*36 + hp] = (u32)sl[(2*hp)*128 + w] | ((u32)sl[(2*hp + 1)*128 + w] << 16);
                }
            }
        }
        __syncthreads();
#pragma unroll
        for (int ks = 0; ks < 4; ks++) {
            int k0 = ks * 16;
            u32 ah[2][4], al[2][4];
#pragma unroll
            for (int mt = 0; mt < 2; mt++) {
                u32 base = (u32)((m0 + mt*16 + rowA) * TSB + (k0 + kA) * 2);
                ldsm_x4(ah[mt][0], ah[mt][1], ah[mt][2], ah[mt][3], sb + OFF_AH + base);
                ldsm_x4(al[mt][0], al[mt][1], al[mt][2], al[mt][3], sb + OFF_AL + base);
            }
#pragma unroll
            for (int nt = 0; nt < 8; nt++) {
                u32 base = (u32)((n0 + nt*8 + rowB) * TSB + (k0 + kB) * 2);
                u32 bh0, bh1, bl0, bl1;
                ldsm_x2(bh0, bh1, sb + OFF_BH + base);
                ldsm_x2(bl0, bl1, sb + OFF_BL + base);
#pragma unroll
                for (int mt = 0; mt < 2; mt++) {
                    mma_bf16(acc[mt][nt], ah[mt][0], ah[mt][1], ah[mt][2], ah[mt][3], bh0, bh1);
                    mma_bf16(acc[mt][nt], ah[mt][0], ah[mt][1], ah[mt][2], ah[mt][3], bl0, bl1);
                    mma_bf16(acc[mt][nt], al[mt][0], al[mt][1], al[mt][2], al[mt][3], bh0, bh1);
                }
            }
        }
    }

    // epilogue through fp32 staging (reuse tile region: 66048 <= 73728)
    __syncthreads();
    float* se = (float*)(sm + OFF_AH);   // [128][129]
#pragma unroll
    for (int mt = 0; mt < 2; mt++)
#pragma unroll
        for (int nt = 0; nt < 8; nt++) {
            int r = m0 + mt*16 + (lane >> 2);
            int c = n0 + nt*8 + 2*(lane & 3);
            se[r*129 + c]           = acc[mt][nt][0];
            se[r*129 + c + 1]       = acc[mt][nt][1];
            se[(r + 8)*129 + c]     = acc[mt][nt][2];
            se[(r + 8)*129 + c + 1] = acc[mt][nt][3];
        }
    __syncthreads();

    if (MODE == 0) {
        u32* oh = g_xdh + (size_t)blockIdx.x * 8192;
        u32* ol = g_xdl + (size_t)blockIdx.x * 8192;
        for (int i = tid; i < 8192; i += 256) {
            int r = i >> 6, np = i & 63;
            u16 h0, l0, h1, l1;
            f2bf2(se[r*129 + 2*np],     h0, l0);
            f2bf2(se[r*129 + 2*np + 1], h1, l1);
            oh[r*64 + np] = (u32)h0 | ((u32)h1 << 16);
            ol[r*64 + np] = (u32)l0 | ((u32)l1 << 16);
        }
    } else {
        float bv = bias[blockIdx.x & 127];
        float* op = outp + (size_t)blockIdx.x * 16384;
        for (int i = tid; i < 16384; i += 256) {
            int r = i >> 7, n = i & 127;
            op[r*128 + n] = se[r*129 + n] + bv;
        }
    }
}

// ---------------- stage 3: per (b,k): y[o,w] = sum_{j,c} wd[k,j,o,c] * xd[b,c,k,(w-j)&127] ----------------
#define TS3 144   // bf16 row stride bytes (72 bf16 = 36 u32), K=64 tiles
__global__ __launch_bounds__(256, 2)
void k_conv_mma() {
    extern __shared__ __align__(16) char sm[];
    const u32 OFF_XH = 0, OFF_XL = 16384, OFF_AH = 32768, OFF_AL = 51200,
              OFF_BH = 69632, OFF_BL = 88064;
    u32 sb = smem_u32(sm);
    int tid = threadIdx.x, wid = tid >> 5, lane = tid & 31;
    int blk = blockIdx.x, b = blk >> 7, k = blk & 127;

    // stage xd slice: X[c][w] hi/lo packed u32 [64][64]
    {
        u32* shx = (u32*)(sm + OFF_XH);
        u32* slx = (u32*)(sm + OFF_XL);
        for (int i = tid; i < 4096; i += 256) {
            int c = i >> 6, wp = i & 63;
            size_t gi = ((size_t)(b*64 + c)*128 + k)*64 + wp;
            shx[i] = g_xdh[gi];
            slx[i] = g_xdl[gi];
        }
    }
    __syncthreads();
    // build B0[w][c] (128 x 64 bf16, stride 72 bf16) from X
    {
        const u16* sh = (const u16*)(sm + OFF_XH);
        const u16* sl = (const u16*)(sm + OFF_XL);
        u32* dBh = (u32*)(sm + OFF_BH);
        u32* dBl = (u32*)(sm + OFF_BL);
        for (int i = tid; i < 4096; i += 256) {
            int w = i & 127, cp = i >> 7;
            dBh[w*36 + cp] = (u32)sh[(2*cp)*128 + w] | ((u32)sh[(2*cp + 1)*128 + w] << 16);
            dBl[w*36 + cp] = (u32)sl[(2*cp)*128 + w] | ((u32)sl[(2*cp + 1)*128 + w] << 16);
        }
    }

    int m0 = (wid >> 1) * 32, n0 = (wid & 1) * 64;
    int rowA = lane & 15;
    int kA = (lane & 16) ? 8 : 0;
    int rowB = lane & 7;
    int kB = (lane & 8) ? 8 : 0;

    float acc[2][8][4];
#pragma unroll
    for (int mt = 0; mt < 2; mt++)
#pragma unroll
        for (int nt = 0; nt < 8; nt++)
#pragma unroll
            for (int q = 0; q < 4; q++) acc[mt][nt][q] = 0.f;

    for (int j = 0; j < 5; j++) {
        // A_j[o][c] (128 x 64 bf16, stride 72 bf16)
        __syncthreads();
        {
            size_t wbase = (size_t)(k*5 + j) * 4096;
            u32* dAh = (u32*)(sm + OFF_AH);
            u32* dAl = (u32*)(sm + OFF_AL);
            for (int i = tid; i < 4096; i += 256) {
                int o = i >> 5, cp = i & 31;
                dAh[o*36 + cp] = g_wdh[wbase + i];
                dAl[o*36 + cp] = g_wdl[wbase + i];
            }
        }
        __syncthreads();
#pragma unroll
        for (int ks = 0; ks < 4; ks++) {
            int k0 = ks * 16;
            u32 ah[2][4], al[2][4];
#pragma unroll
            for (int mt = 0; mt < 2; mt++) {
                u32 base = (u32)((m0 + mt*16 + rowA) * TS3 + (k0 + kA) * 2);
                ldsm_x4(ah[mt][0], ah[mt][1], ah[mt][2], ah[mt][3], sb + OFF_AH + base);
                ldsm_x4(al[mt][0], al[mt][1], al[mt][2], al[mt][3], sb + OFF_AL + base);
            }
#pragma unroll
            for (int nt = 0; nt < 8; nt++) {
                int wr = ((n0 + nt*8 + rowB) - j) & 127;          // circular shift along w
                u32 base = (u32)(wr * TS3 + (k0 + kB) * 2);
                u32 bh0, bh1, bl0, bl1;
                ldsm_x2(bh0, bh1, sb + OFF_BH + base);
                ldsm_x2(bl0, bl1, sb + OFF_BL + base);
#pragma unroll
                for (int mt = 0; mt < 2; mt++) {
                    mma_bf16(acc[mt][nt], ah[mt][0], ah[mt][1], ah[mt][2], ah[mt][3], bh0, bh1);
                    mma_bf16(acc[mt][nt], ah[mt][0], ah[mt][1], ah[mt][2], ah[mt][3], bl0, bl1);
                    mma_bf16(acc[mt][nt], al[mt][0], al[mt][1], al[mt][2], al[mt][3], bh0, bh1);
                }
            }
        }
    }

    // epilogue through fp32 staging (reuse A/B region)
    __syncthreads();
    float* se = (float*)(sm + OFF_AH);   // [128][129]
#pragma unroll
    for (int mt = 0; mt < 2; mt++)
#pragma unroll
        for (int nt = 0; nt < 8; nt++) {
            int r = m0 + mt*16 + (lane >> 2);
            int c = n0 + nt*8 + 2*(lane & 3);
            se[r*129 + c]           = acc[mt][nt][0];
            se[r*129 + c + 1]       = acc[mt][nt][1];
            se[(r + 8)*129 + c]     = acc[mt][nt][2];
            se[(r + 8)*129 + c + 1] = acc[mt][nt][3];
        }
    __syncthreads();
    for (int i = tid; i < 8192; i += 256) {
        int o = i >> 6, wp = i & 63;
        u16 h0, l0, h1, l1;
        f2bf2(se[o*129 + 2*wp],     h0, l0);
        f2bf2(se[o*129 + 2*wp + 1], h1, l1);
        size_t gi = ((size_t)(b*128 + o))*8192 + (size_t)k*64 + wp;
        g_yh[gi] = (u32)h0 | ((u32)h1 << 16);
        g_yl[gi] = (u32)l0 | ((u32)l1 << 16);
    }
}

// ---------------- launch ----------------
extern "C" void kernel_launch(void* const* d_in, const int* in_sizes, int n_in,
                              void* d_out, int out_size) {
    const float* x    = (const float*)d_in[0];   // (8,64,128,128)
    const float* wgt  = (const float*)d_in[1];   // (128,64,5,5)
    const float* bias = (const float*)d_in[2];   // (128,)
    float* out = (float*)d_out;                  // (8,128,128,128)

    const int SM14 = 106496;
    const int SM3  = 106496;
    cudaFuncSetAttribute(k_gemm<0>,  cudaFuncAttributeMaxDynamicSharedMemorySize, SM14);
    cudaFuncSetAttribute(k_gemm<1>,  cudaFuncAttributeMaxDynamicSharedMemorySize, SM14);
    cudaFuncSetAttribute(k_conv_mma, cudaFuncAttributeMaxDynamicSharedMemorySize, SM3);

    k_consts  <<<32, 256>>>();
    k_wtrans  <<<640, 256>>>(wgt);
    k_gemm<0> <<<BATCH*CIN,  256, SM14>>>(x, nullptr, nullptr);
    k_conv_mma<<<BATCH*HH,   256, SM3 >>>();
    k_gemm<1> <<<BATCH*COUT, 256, SM14>>>(nullptr, bias, out);
}

// round 8
// speedup vs baseline: 4.3433x; 1.3199x over previous
#include <cuda_runtime.h>
#include <cuda_bf16.h>
#include <math.h>

typedef unsigned int       u32;
typedef unsigned short     u16;
typedef unsigned long long u64;

#define BATCH 8
#define CIN   64
#define COUT  128
#define HH    128
#define WW    128

// ---------------- device globals (packed bf16 split planes; u32 = 2 bf16 along last dim) ----------------
__device__ u32 g_Dh[8192], g_Dl[8192];        // DCT matrix  [k][h/2]
__device__ u32 g_Mh[8192], g_Ml[8192];        // iDCT matrix [n][k/2]
__device__ float g_D5[640];                   // first 5 cols of D
__device__ u32 g_wdh[128*5*4096], g_wdl[128*5*4096];              // [k][j] tiles of [o][c/2] (128x32 u32)
__device__ u32 g_xdh[BATCH*CIN*HH*64],  g_xdl[BATCH*CIN*HH*64];   // [b][c][k][w/2]
__device__ u32 g_yh [BATCH*COUT*HH*64], g_yl [BATCH*COUT*HH*64];  // [b][o][k][w/2]

// ---------------- helpers ----------------
__device__ __forceinline__ u32 smem_u32(const void* p) {
    u32 a; asm("{ .reg .u64 t; cvta.to.shared.u64 t, %1; cvt.u32.u64 %0, t; }" : "=r"(a) : "l"(p));
    return a;
}
__device__ __forceinline__ void cp16(u32 dst, const void* src) {
    asm volatile("cp.async.cg.shared.global [%0], [%1], 16;" :: "r"(dst), "l"(src) : "memory");
}
#define CP_COMMIT() asm volatile("cp.async.commit_group;" ::: "memory")
#define CP_WAIT(n)  asm volatile("cp.async.wait_group %0;" :: "n"(n) : "memory")

__device__ __forceinline__ void ldsm_x4(u32& r0, u32& r1, u32& r2, u32& r3, u32 addr) {
    asm volatile("ldmatrix.sync.aligned.m8n8.x4.shared.b16 {%0,%1,%2,%3}, [%4];"
        : "=r"(r0), "=r"(r1), "=r"(r2), "=r"(r3) : "r"(addr) : "memory");
}
__device__ __forceinline__ void ldsm_x2(u32& r0, u32& r1, u32 addr) {
    asm volatile("ldmatrix.sync.aligned.m8n8.x2.shared.b16 {%0,%1}, [%2];"
        : "=r"(r0), "=r"(r1) : "r"(addr) : "memory");
}
__device__ __forceinline__ void mma_bf16(float* c, u32 a0, u32 a1, u32 a2, u32 a3, u32 b0, u32 b1) {
    asm volatile("mma.sync.aligned.m16n8k16.row.col.f32.bf16.bf16.f32 "
        "{%0,%1,%2,%3}, {%4,%5,%6,%7}, {%8,%9}, {%0,%1,%2,%3};"
        : "+f"(c[0]), "+f"(c[1]), "+f"(c[2]), "+f"(c[3])
        : "r"(a0), "r"(a1), "r"(a2), "r"(a3), "r"(b0), "r"(b1));
}
__device__ __forceinline__ void f2bf2(float v, u16& h, u16& l) {
    __nv_bfloat16 bh = __float2bfloat16(v);
    float fh = __bfloat162float(bh);
    __nv_bfloat16 bl = __float2bfloat16(v - fh);
    h = __bfloat16_as_ushort(bh);
    l = __bfloat16_as_ushort(bl);
}

// ---------------- constants ----------------
__global__ void k_consts() {
    int idx = blockIdx.x * blockDim.x + threadIdx.x;
    if (idx < 640) {
        int k = idx / 5, h = idx % 5;
        g_D5[idx] = (float)(2.0 * cos(M_PI * (2.0*h + 1.0) * k / 256.0));
    }
    if (idx >= 8192) return;
    int r = idx >> 6, cp = idx & 63;
    int c0 = 2*cp, c1 = 2*cp + 1;
    u16 h0, l0, h1, l1;
    float d0 = (float)(2.0 * cos(M_PI * (2.0*c0 + 1.0) * r / 256.0));
    float d1 = (float)(2.0 * cos(M_PI * (2.0*c1 + 1.0) * r / 256.0));
    f2bf2(d0, h0, l0); f2bf2(d1, h1, l1);
    g_Dh[idx] = (u32)h0 | ((u32)h1 << 16);
    g_Dl[idx] = (u32)l0 | ((u32)l1 << 16);
    float m0 = (float)(cos(M_PI * (2.0*r + 1.0) * c0 / 256.0) * ((c0 == 0) ? 0.5 : 1.0) / 256.0);
    float m1 = (float)(cos(M_PI * (2.0*r + 1.0) * c1 / 256.0) / 256.0);
    f2bf2(m0, h0, l0); f2bf2(m1, h1, l1);
    g_Mh[idx] = (u32)h0 | ((u32)h1 << 16);
    g_Ml[idx] = (u32)l0 | ((u32)l1 << 16);
}

// ---------------- weight transform: wd[k][j][o][c] = sum_h D[k,h]*W[o,c,h,j] ----------------
__global__ void k_wtrans(const float* __restrict__ wgt) {
    __shared__ float sw[5*64];
    int j = blockIdx.x >> 7, o = blockIdx.x & 127;
    int tid = threadIdx.x;
    for (int i = tid; i < 320; i += 256) {
        int h = i >> 6, c = i & 63;
        sw[h*64 + c] = wgt[((o*64 + c)*5 + h)*5 + j];
    }
    __syncthreads();
    for (int i = tid; i < 4096; i += 256) {
        int k = i >> 5, cp = i & 31;
        float a0 = 0.f, a1 = 0.f;
#pragma unroll
        for (int h = 0; h < 5; h++) {
            float d = g_D5[k*5 + h];
            a0 = fmaf(d, sw[h*64 + 2*cp],     a0);
            a1 = fmaf(d, sw[h*64 + 2*cp + 1], a1);
        }
        u16 h0, l0, h1, l1; f2bf2(a0, h0, l0); f2bf2(a1, h1, l1);
        u32 oi = (u32)(k*5 + j)*4096 + o*32 + cp;
        g_wdh[oi] = (u32)h0 | ((u32)h1 << 16);
        g_wdl[oi] = (u32)l0 | ((u32)l1 << 16);
    }
}

// ---------------- generic 128x128x128 mma GEMM, K split into 2x64 chunks ----------------
#define TSB 144
template<int MODE>
__global__ __launch_bounds__(256, 2)
void k_gemm(const float* __restrict__ xsrc, const float* __restrict__ bias, float* __restrict__ outp) {
    extern __shared__ __align__(16) char sm[];
    const u32 OFF_AH = 0, OFF_AL = 18432, OFF_BH = 36864, OFF_BL = 55296, OFF_ST = 73728;
    u32 sb = smem_u32(sm);
    int tid = threadIdx.x, wid = tid >> 5, lane = tid & 31;

    int m0 = (wid >> 1) * 32, n0 = (wid & 1) * 64;
    int rowA = lane & 15;
    int kA = (lane & 16) ? 8 : 0;
    int rowB = lane & 7;
    int kB = (lane & 8) ? 8 : 0;

    float acc[2][8][4];
#pragma unroll
    for (int mt = 0; mt < 2; mt++)
#pragma unroll
        for (int nt = 0; nt < 8; nt++)
#pragma unroll
            for (int q = 0; q < 4; q++) acc[mt][nt][q] = 0.f;

    for (int kk = 0; kk < 2; kk++) {
        __syncthreads();   // prev chunk's MMAs done before restaging
        // cp.async: stage B source half + A half tiles (all direct to smem)
        if (MODE == 0) {
            const char* src = (const char*)(xsrc + (size_t)blockIdx.x * 16384 + (size_t)kk * 8192);
            for (int i = tid; i < 2048; i += 256)
                cp16(sb + OFF_ST + i*16, src + i*16);
        } else {
            const char* yh = (const char*)(g_yh + (size_t)blockIdx.x * 8192 + (size_t)kk * 4096);
            const char* yl = (const char*)(g_yl + (size_t)blockIdx.x * 8192 + (size_t)kk * 4096);
            for (int i = tid; i < 1024; i += 256) {
                cp16(sb + OFF_ST + i*16,         yh + i*16);
                cp16(sb + OFF_ST + 16384 + i*16, yl + i*16);
            }
        }
        {
            const u32* Ah = MODE ? g_Mh : g_Dh;
            const u32* Al = MODE ? g_Ml : g_Dl;
            for (int i = tid; i < 1024; i += 256) {
                int r = i >> 3, ch = i & 7;   // row r: 32 u32 = 128B = 8x16B
                cp16(sb + OFF_AH + r*TSB + ch*16, Ah + r*64 + kk*32 + ch*4);
                cp16(sb + OFF_AL + r*TSB + ch*16, Al + r*64 + kk*32 + ch*4);
            }
        }
        CP_COMMIT();
        CP_WAIT(0);
        __syncthreads();
        // build B^T half: B[w][h-local] from staged [h-local][w]
        {
            u32* dBh = (u32*)(sm + OFF_BH);
            u32* dBl = (u32*)(sm + OFF_BL);
            for (int i = tid; i < 4096; i += 256) {
                int w = i & 127, hp = i >> 7;
                if (MODE == 0) {
                    const float* st = (const float*)(sm + OFF_ST);
                    u16 h0, l0, h1, l1;
                    f2bf2(st[(2*hp)*128 + w],     h0, l0);
                    f2bf2(st[(2*hp + 1)*128 + w], h1, l1);
                    dBh[w*36 + hp] = (u32)h0 | ((u32)h1 << 16);
                    dBl[w*36 + hp] = (u32)l0 | ((u32)l1 << 16);
                } else {
                    const u16* sh = (const u16*)(sm + OFF_ST);
                    const u16* sl = sh + 8192;
                    dBh[w*36 + hp] = (u32)sh[(2*hp)*128 + w] | ((u32)sh[(2*hp + 1)*128 + w] << 16);
                    dBl[w*36 + hp] = (u32)sl[(2*hp)*128 + w] | ((u32)sl[(2*hp + 1)*128 + w] << 16);
                }
            }
        }
        __syncthreads();
#pragma unroll
        for (int ks = 0; ks < 4; ks++) {
            int k0 = ks * 16;
            u32 ah[2][4], al[2][4];
#pragma unroll
            for (int mt = 0; mt < 2; mt++) {
                u32 base = (u32)((m0 + mt*16 + rowA) * TSB + (k0 + kA) * 2);
                ldsm_x4(ah[mt][0], ah[mt][1], ah[mt][2], ah[mt][3], sb + OFF_AH + base);
                ldsm_x4(al[mt][0], al[mt][1], al[mt][2], al[mt][3], sb + OFF_AL + base);
            }
#pragma unroll
            for (int nt = 0; nt < 8; nt++) {
                u32 base = (u32)((n0 + nt*8 + rowB) * TSB + (k0 + kB) * 2);
                u32 bh0, bh1, bl0, bl1;
                ldsm_x2(bh0, bh1, sb + OFF_BH + base);
                ldsm_x2(bl0, bl1, sb + OFF_BL + base);
#pragma unroll
                for (int mt = 0; mt < 2; mt++) {
                    mma_bf16(acc[mt][nt], ah[mt][0], ah[mt][1], ah[mt][2], ah[mt][3], bh0, bh1);
                    mma_bf16(acc[mt][nt], ah[mt][0], ah[mt][1], ah[mt][2], ah[mt][3], bl0, bl1);
                    mma_bf16(acc[mt][nt], al[mt][0], al[mt][1], al[mt][2], al[mt][3], bh0, bh1);
                }
            }
        }
    }

    // epilogue through fp32 staging
    __syncthreads();
    float* se = (float*)(sm + OFF_AH);   // [128][129]
#pragma unroll
    for (int mt = 0; mt < 2; mt++)
#pragma unroll
        for (int nt = 0; nt < 8; nt++) {
            int r = m0 + mt*16 + (lane >> 2);
            int c = n0 + nt*8 + 2*(lane & 3);
            se[r*129 + c]           = acc[mt][nt][0];
            se[r*129 + c + 1]       = acc[mt][nt][1];
            se[(r + 8)*129 + c]     = acc[mt][nt][2];
            se[(r + 8)*129 + c + 1] = acc[mt][nt][3];
        }
    __syncthreads();

    if (MODE == 0) {
        u32* oh = g_xdh + (size_t)blockIdx.x * 8192;
        u32* ol = g_xdl + (size_t)blockIdx.x * 8192;
        for (int i = tid; i < 8192; i += 256) {
            int r = i >> 6, np = i & 63;
            u16 h0, l0, h1, l1;
            f2bf2(se[r*129 + 2*np],     h0, l0);
            f2bf2(se[r*129 + 2*np + 1], h1, l1);
            oh[r*64 + np] = (u32)h0 | ((u32)h1 << 16);
            ol[r*64 + np] = (u32)l0 | ((u32)l1 << 16);
        }
    } else {
        float bv = bias[blockIdx.x & 127];
        float* op = outp + (size_t)blockIdx.x * 16384;
        for (int i = tid; i < 16384; i += 256) {
            int r = i >> 7, n = i & 127;
            op[r*128 + n] = se[r*129 + n] + bv;
        }
    }
}

// ---------------- stage 3: per (b,k): y[o,w] = sum_{j,c} wd[k,j,o,c] * xd[b,c,k,(w-j)&127] ----------------
// Double-buffered A tiles via cp.async; B built once with shift folded into ldsm addressing.
// smem: BH 0, BL 18432, bufA0 36864 (AH/AL), bufA1 73728 (AH/AL; X staged here first). total 110592.
#define TS3 144
__global__ __launch_bounds__(256, 2)
void k_conv_mma() {
    extern __shared__ __align__(16) char sm[];
    const u32 OFF_BH = 0, OFF_BL = 18432, OFF_A0 = 36864, OFF_A1 = 73728;
    u32 sb = smem_u32(sm);
    int tid = threadIdx.x, wid = tid >> 5, lane = tid & 31;
    int blk = blockIdx.x, b = blk >> 7, k = blk & 127;

    // 1. cp.async X slice into buf1 region: XH at OFF_A1, XL at OFF_A1+16384
    for (int i = tid; i < 1024; i += 256) {
        int c = i >> 4, ch = i & 15;                 // row c: 64 u32 = 256B = 16x16B
        size_t gi = ((size_t)(b*64 + c)*128 + k)*64 + ch*4;
        cp16(sb + OFF_A1 +         i*16, g_xdh + gi);
        cp16(sb + OFF_A1 + 16384 + i*16, g_xdl + gi);
    }
    CP_COMMIT();
    // 2. cp.async A_0 into buf0 (overlaps with X wait + B build)
    {
        size_t wbase = (size_t)(k*5 + 0) * 4096;
        for (int i = tid; i < 1024; i += 256) {
            int o = i >> 3, ch = i & 7;              // row o: 32 u32 = 128B = 8x16B
            cp16(sb + OFF_A0 +         o*TS3 + ch*16, g_wdh + wbase + o*32 + ch*4);
            cp16(sb + OFF_A0 + 18432 + o*TS3 + ch*16, g_wdl + wbase + o*32 + ch*4);
        }
        CP_COMMIT();
    }
    CP_WAIT(1);            // X landed (A0 may still fly)
    __syncthreads();
    // 3. build B[w][c] once from X (A0 copy in flight)
    {
        const u16* sh = (const u16*)(sm + OFF_A1);
        const u16* sl = (const u16*)(sm + OFF_A1 + 16384);
        u32* dBh = (u32*)(sm + OFF_BH);
        u32* dBl = (u32*)(sm + OFF_BL);
        for (int i = tid; i < 4096; i += 256) {
            int w = i & 127, cp = i >> 7;
            dBh[w*36 + cp] = (u32)sh[(2*cp)*128 + w] | ((u32)sh[(2*cp + 1)*128 + w] << 16);
            dBl[w*36 + cp] = (u32)sl[(2*cp)*128 + w] | ((u32)sl[(2*cp + 1)*128 + w] << 16);
        }
    }
    CP_WAIT(0);            // A0 landed
    __syncthreads();       // B + A0 visible to all warps

    int m0 = (wid >> 1) * 32, n0 = (wid & 1) * 64;
    int rowA = lane & 15;
    int kA = (lane & 16) ? 8 : 0;
    int rowB = lane & 7;
    int kB = (lane & 8) ? 8 : 0;

    float acc[2][8][4];
#pragma unroll
    for (int mt = 0; mt < 2; mt++)
#pragma unroll
        for (int nt = 0; nt < 8; nt++)
#pragma unroll
            for (int q = 0; q < 4; q++) acc[mt][nt][q] = 0.f;

#pragma unroll
    for (int j = 0; j < 5; j++) {
        // prefetch A_{j+1} into the other buffer (its last reader finished before the
        // wait+sync at the end of iteration j-1)
        if (j < 4) {
            size_t wbase = (size_t)(k*5 + j + 1) * 4096;
            u32 dst = sb + (((j + 1) & 1) ? OFF_A1 : OFF_A0);
            for (int i = tid; i < 1024; i += 256) {
                int o = i >> 3, ch = i & 7;
                cp16(dst +         o*TS3 + ch*16, g_wdh + wbase + o*32 + ch*4);
                cp16(dst + 18432 + o*TS3 + ch*16, g_wdl + wbase + o*32 + ch*4);
            }
            CP_COMMIT();
        }
        u32 aBase = sb + ((j & 1) ? OFF_A1 : OFF_A0);
#pragma unroll
        for (int ks = 0; ks < 4; ks++) {
            int k0 = ks * 16;
            u32 ah[2][4], al[2][4];
#pragma unroll
            for (int mt = 0; mt < 2; mt++) {
                u32 base = (u32)((m0 + mt*16 + rowA) * TS3 + (k0 + kA) * 2);
                ldsm_x4(ah[mt][0], ah[mt][1], ah[mt][2], ah[mt][3], aBase + base);
                ldsm_x4(al[mt][0], al[mt][1], al[mt][2], al[mt][3], aBase + 18432 + base);
            }
#pragma unroll
            for (int nt = 0; nt < 8; nt++) {
                int wr = ((n0 + nt*8 + rowB) - j) & 127;          // circular shift along w
                u32 base = (u32)(wr * TS3 + (k0 + kB) * 2);
                u32 bh0, bh1, bl0, bl1;
                ldsm_x2(bh0, bh1, sb + OFF_BH + base);
                ldsm_x2(bl0, bl1, sb + OFF_BL + base);
#pragma unroll
                for (int mt = 0; mt < 2; mt++) {
                    mma_bf16(acc[mt][nt], ah[mt][0], ah[mt][1], ah[mt][2], ah[mt][3], bh0, bh1);
                    mma_bf16(acc[mt][nt], ah[mt][0], ah[mt][1], ah[mt][2], ah[mt][3], bl0, bl1);
                    mma_bf16(acc[mt][nt], al[mt][0], al[mt][1], al[mt][2], al[mt][3], bh0, bh1);
                }
            }
        }
        if (j < 4) { CP_WAIT(0); __syncthreads(); }
    }

    // epilogue through fp32 staging (reuse B + buf0 region; all MMAs done after sync)
    __syncthreads();
    float* se = (float*)(sm);   // [128][129] = 66048 bytes
#pragma unroll
    for (int mt = 0; mt < 2; mt++)
#pragma unroll
        for (int nt = 0; nt < 8; nt++) {
            int r = m0 + mt*16 + (lane >> 2);
            int c = n0 + nt*8 + 2*(lane & 3);
            se[r*129 + c]           = acc[mt][nt][0];
            se[r*129 + c + 1]       = acc[mt][nt][1];
            se[(r + 8)*129 + c]     = acc[mt][nt][2];
            se[(r + 8)*129 + c + 1] = acc[mt][nt][3];
        }
    __syncthreads();
    for (int i = tid; i < 8192; i += 256) {
        int o = i >> 6, wp = i & 63;
        u16 h0, l0, h1, l1;
        f2bf2(se[o*129 + 2*wp],     h0, l0);
        f2bf2(se[o*129 + 2*wp + 1], h1, l1);
        size_t gi = ((size_t)(b*128 + o))*8192 + (size_t)k*64 + wp;
        g_yh[gi] = (u32)h0 | ((u32)h1 << 16);
        g_yl[gi] = (u32)l0 | ((u32)l1 << 16);
    }
}

// ---------------- launch ----------------
extern "C" void kernel_launch(void* const* d_in, const int* in_sizes, int n_in,
                              void* d_out, int out_size) {
    const float* x    = (const float*)d_in[0];   // (8,64,128,128)
    const float* wgt  = (const float*)d_in[1];   // (128,64,5,5)
    const float* bias = (const float*)d_in[2];   // (128,)
    float* out = (float*)d_out;                  // (8,128,128,128)

    const int SM14 = 106496;
    const int SM3  = 110592;
    cudaFuncSetAttribute(k_gemm<0>,  cudaFuncAttributeMaxDynamicSharedMemorySize, SM14);
    cudaFuncSetAttribute(k_gemm<1>,  cudaFuncAttributeMaxDynamicSharedMemorySize, SM14);
    cudaFuncSetAttribute(k_conv_mma, cudaFuncAttributeMaxDynamicSharedMemorySize, SM3);

    k_consts  <<<32, 256>>>();
    k_wtrans  <<<640, 256>>>(wgt);
    k_gemm<0> <<<BATCH*CIN,  256, SM14>>>(x, nullptr, nullptr);
    k_conv_mma<<<BATCH*HH,   256, SM3 >>>();
    k_gemm<1> <<<BATCH*COUT, 256, SM14>>>(nullptr, bias, out);
}

// round 9
// speedup vs baseline: 4.5681x; 1.0518x over previous
#include <cuda_runtime.h>
#include <cuda_bf16.h>
#include <math.h>

typedef unsigned int       u32;
typedef unsigned short     u16;
typedef unsigned long long u64;

#define BATCH 8
#define CIN   64
#define COUT  128
#define HH    128
#define WW    128

// ---------------- device globals (packed bf16 split planes; u32 = 2 bf16 along last dim) ----------------
__device__ u32 g_Dh[8192], g_Dl[8192];        // DCT matrix  [k][h/2]
__device__ u32 g_Mh[8192], g_Ml[8192];        // iDCT matrix [n][k/2]
__device__ float g_D5[640];                   // first 5 cols of D
__device__ u32 g_wdh[128*5*4096], g_wdl[128*5*4096];              // [k][j] tiles of [o][c/2] (128x32 u32)
__device__ u32 g_xdh[BATCH*CIN*HH*64],  g_xdl[BATCH*CIN*HH*64];   // [b][c][k][w/2]
__device__ u32 g_yh [BATCH*COUT*HH*64], g_yl [BATCH*COUT*HH*64];  // [b][o][k][w/2]

// ---------------- helpers ----------------
__device__ __forceinline__ u32 smem_u32(const void* p) {
    u32 a; asm("{ .reg .u64 t; cvta.to.shared.u64 t, %1; cvt.u32.u64 %0, t; }" : "=r"(a) : "l"(p));
    return a;
}
__device__ __forceinline__ void cp16(u32 dst, const void* src) {
    asm volatile("cp.async.cg.shared.global [%0], [%1], 16;" :: "r"(dst), "l"(src) : "memory");
}
#define CP_COMMIT() asm volatile("cp.async.commit_group;" ::: "memory")
#define CP_WAIT(n)  asm volatile("cp.async.wait_group %0;" :: "n"(n) : "memory")

__device__ __forceinline__ void ldsm_x4(u32& r0, u32& r1, u32& r2, u32& r3, u32 addr) {
    asm volatile("ldmatrix.sync.aligned.m8n8.x4.shared.b16 {%0,%1,%2,%3}, [%4];"
        : "=r"(r0), "=r"(r1), "=r"(r2), "=r"(r3) : "r"(addr) : "memory");
}
__device__ __forceinline__ void ldsm_x2(u32& r0, u32& r1, u32 addr) {
    asm volatile("ldmatrix.sync.aligned.m8n8.x2.shared.b16 {%0,%1}, [%2];"
        : "=r"(r0), "=r"(r1) : "r"(addr) : "memory");
}
__device__ __forceinline__ void ldsm_x2t(u32& r0, u32& r1, u32 addr) {
    asm volatile("ldmatrix.sync.aligned.m8n8.x2.trans.shared.b16 {%0,%1}, [%2];"
        : "=r"(r0), "=r"(r1) : "r"(addr) : "memory");
}
__device__ __forceinline__ void mma_bf16(float* c, u32 a0, u32 a1, u32 a2, u32 a3, u32 b0, u32 b1) {
    asm volatile("mma.sync.aligned.m16n8k16.row.col.f32.bf16.bf16.f32 "
        "{%0,%1,%2,%3}, {%4,%5,%6,%7}, {%8,%9}, {%0,%1,%2,%3};"
        : "+f"(c[0]), "+f"(c[1]), "+f"(c[2]), "+f"(c[3])
        : "r"(a0), "r"(a1), "r"(a2), "r"(a3), "r"(b0), "r"(b1));
}
__device__ __forceinline__ void f2bf2(float v, u16& h, u16& l) {
    __nv_bfloat16 bh = __float2bfloat16(v);
    float fh = __bfloat162float(bh);
    __nv_bfloat16 bl = __float2bfloat16(v - fh);
    h = __bfloat16_as_ushort(bh);
    l = __bfloat16_as_ushort(bl);
}

// ---------------- constants ----------------
__global__ void k_consts() {
    int idx = blockIdx.x * blockDim.x + threadIdx.x;
    if (idx < 640) {
        int k = idx / 5, h = idx % 5;
        g_D5[idx] = (float)(2.0 * cos(M_PI * (2.0*h + 1.0) * k / 256.0));
    }
    if (idx >= 8192) return;
    int r = idx >> 6, cp = idx & 63;
    int c0 = 2*cp, c1 = 2*cp + 1;
    u16 h0, l0, h1, l1;
    float d0 = (float)(2.0 * cos(M_PI * (2.0*c0 + 1.0) * r / 256.0));
    float d1 = (float)(2.0 * cos(M_PI * (2.0*c1 + 1.0) * r / 256.0));
    f2bf2(d0, h0, l0); f2bf2(d1, h1, l1);
    g_Dh[idx] = (u32)h0 | ((u32)h1 << 16);
    g_Dl[idx] = (u32)l0 | ((u32)l1 << 16);
    float m0 = (float)(cos(M_PI * (2.0*r + 1.0) * c0 / 256.0) * ((c0 == 0) ? 0.5 : 1.0) / 256.0);
    float m1 = (float)(cos(M_PI * (2.0*r + 1.0) * c1 / 256.0) / 256.0);
    f2bf2(m0, h0, l0); f2bf2(m1, h1, l1);
    g_Mh[idx] = (u32)h0 | ((u32)h1 << 16);
    g_Ml[idx] = (u32)l0 | ((u32)l1 << 16);
}

// ---------------- weight transform: wd[k][j][o][c] = sum_h D[k,h]*W[o,c,h,j] ----------------
__global__ void k_wtrans(const float* __restrict__ wgt) {
    __shared__ float sw[5*64];
    int j = blockIdx.x >> 7, o = blockIdx.x & 127;
    int tid = threadIdx.x;
    for (int i = tid; i < 320; i += 256) {
        int h = i >> 6, c = i & 63;
        sw[h*64 + c] = wgt[((o*64 + c)*5 + h)*5 + j];
    }
    __syncthreads();
    for (int i = tid; i < 4096; i += 256) {
        int k = i >> 5, cp = i & 31;
        float a0 = 0.f, a1 = 0.f;
#pragma unroll
        for (int h = 0; h < 5; h++) {
            float d = g_D5[k*5 + h];
            a0 = fmaf(d, sw[h*64 + 2*cp],     a0);
            a1 = fmaf(d, sw[h*64 + 2*cp + 1], a1);
        }
        u16 h0, l0, h1, l1; f2bf2(a0, h0, l0); f2bf2(a1, h1, l1);
        u32 oi = (u32)(k*5 + j)*4096 + o*32 + cp;
        g_wdh[oi] = (u32)h0 | ((u32)h1 << 16);
        g_wdl[oi] = (u32)l0 | ((u32)l1 << 16);
    }
}

// ---------------- generic 128x128x128 mma GEMM, K split into 2x64 chunks ----------------
// B stored [k][n] row-major (stride 272B), fragments via ldmatrix.trans (no transpose build).
// MODE 0 (stage 1): B from fp32 x slice [h][w] (staged + split-converted in-layout); epilogue -> g_xd planes
// MODE 1 (stage 4): B = y planes cp.async'd DIRECTLY into tiles; epilogue = direct fp32+bias gmem stores
#define TSA 144   // A row stride bytes
#define TSB2 272  // B row stride bytes (128 n-cols bf16 = 256B data)
template<int MODE>
__global__ __launch_bounds__(256, 2)
void k_gemm(const float* __restrict__ xsrc, const float* __restrict__ bias, float* __restrict__ outp) {
    extern __shared__ __align__(16) char sm[];
    const u32 OFF_AH = 0, OFF_AL = 18432, OFF_BH = 36864, OFF_BL = 54272, OFF_ST = 71680;
    u32 sb = smem_u32(sm);
    int tid = threadIdx.x, wid = tid >> 5, lane = tid & 31;

    int m0 = (wid >> 1) * 32, n0 = (wid & 1) * 64;
    int rowA = lane & 15;
    int kA = (lane & 16) ? 8 : 0;
    int rowK = lane & 15;              // B trans: lane -> k-row within 16-row fragment

    float acc[2][8][4];
#pragma unroll
    for (int mt = 0; mt < 2; mt++)
#pragma unroll
        for (int nt = 0; nt < 8; nt++)
#pragma unroll
            for (int q = 0; q < 4; q++) acc[mt][nt][q] = 0.f;

    for (int kk = 0; kk < 2; kk++) {
        __syncthreads();   // prev chunk's MMAs done before restaging
        if (MODE == 0) {
            // stage fp32 x half [64 h][128 w] = 32KB
            const char* src = (const char*)(xsrc + (size_t)blockIdx.x * 16384 + (size_t)kk * 8192);
            for (int i = tid; i < 2048; i += 256)
                cp16(sb + OFF_ST + i*16, src + i*16);
        } else {
            // cp y planes straight into B tiles [k][n]
            const u32* yh = g_yh + (size_t)blockIdx.x * 8192 + (size_t)kk * 4096;
            const u32* yl = g_yl + (size_t)blockIdx.x * 8192 + (size_t)kk * 4096;
            for (int i = tid; i < 1024; i += 256) {
                int r = i >> 4, ch = i & 15;     // row r: 64 u32 = 256B = 16x16B
                cp16(sb + OFF_BH + r*TSB2 + ch*16, yh + r*64 + ch*4);
                cp16(sb + OFF_BL + r*TSB2 + ch*16, yl + r*64 + ch*4);
            }
        }
        {
            const u32* Ah = MODE ? g_Mh : g_Dh;
            const u32* Al = MODE ? g_Ml : g_Dl;
            for (int i = tid; i < 1024; i += 256) {
                int r = i >> 3, ch = i & 7;      // row r: 32 u32 = 128B = 8x16B
                cp16(sb + OFF_AH + r*TSA + ch*16, Ah + r*64 + kk*32 + ch*4);
                cp16(sb + OFF_AL + r*TSA + ch*16, Al + r*64 + kk*32 + ch*4);
            }
        }
        CP_COMMIT();
        CP_WAIT(0);
        __syncthreads();
        if (MODE == 0) {
            // convert staged fp32 [h][w] -> Bh/Bl in SAME layout (no transpose)
            const float* st = (const float*)(sm + OFF_ST);
            u32* dBh = (u32*)(sm + OFF_BH);
            u32* dBl = (u32*)(sm + OFF_BL);
            for (int i = tid; i < 4096; i += 256) {
                int h = i >> 6, wp = i & 63;
                u16 h0, l0, h1, l1;
                f2bf2(st[h*128 + 2*wp],     h0, l0);
                f2bf2(st[h*128 + 2*wp + 1], h1, l1);
                dBh[h*68 + wp] = (u32)h0 | ((u32)h1 << 16);
                dBl[h*68 + wp] = (u32)l0 | ((u32)l1 << 16);
            }
            __syncthreads();
        }
#pragma unroll
        for (int ks = 0; ks < 4; ks++) {
            int k0 = ks * 16;
            u32 ah[2][4], al[2][4];
#pragma unroll
            for (int mt = 0; mt < 2; mt++) {
                u32 base = (u32)((m0 + mt*16 + rowA) * TSA + (k0 + kA) * 2);
                ldsm_x4(ah[mt][0], ah[mt][1], ah[mt][2], ah[mt][3], sb + OFF_AH + base);
                ldsm_x4(al[mt][0], al[mt][1], al[mt][2], al[mt][3], sb + OFF_AL + base);
            }
            u32 rbase = (u32)((k0 + rowK) * TSB2);
#pragma unroll
            for (int nt = 0; nt < 8; nt++) {
                u32 off = rbase + (u32)((n0 + nt*8) * 2);
                u32 bh0, bh1, bl0, bl1;
                ldsm_x2t(bh0, bh1, sb + OFF_BH + off);
                ldsm_x2t(bl0, bl1, sb + OFF_BL + off);
#pragma unroll
                for (int mt = 0; mt < 2; mt++) {
                    mma_bf16(acc[mt][nt], ah[mt][0], ah[mt][1], ah[mt][2], ah[mt][3], bh0, bh1);
                    mma_bf16(acc[mt][nt], ah[mt][0], ah[mt][1], ah[mt][2], ah[mt][3], bl0, bl1);
                    mma_bf16(acc[mt][nt], al[mt][0], al[mt][1], al[mt][2], al[mt][3], bh0, bh1);
                }
            }
        }
    }

    if (MODE == 0) {
        // epilogue through fp32 staging, pack to split planes (coalesced u32 stores)
        __syncthreads();
        float* se = (float*)(sm);   // [128][129] = 66048 <= 104448
#pragma unroll
        for (int mt = 0; mt < 2; mt++)
#pragma unroll
            for (int nt = 0; nt < 8; nt++) {
                int r = m0 + mt*16 + (lane >> 2);
                int c = n0 + nt*8 + 2*(lane & 3);
                se[r*129 + c]           = acc[mt][nt][0];
                se[r*129 + c + 1]       = acc[mt][nt][1];
                se[(r + 8)*129 + c]     = acc[mt][nt][2];
                se[(r + 8)*129 + c + 1] = acc[mt][nt][3];
            }
        __syncthreads();
        u32* oh = g_xdh + (size_t)blockIdx.x * 8192;
        u32* ol = g_xdl + (size_t)blockIdx.x * 8192;
        for (int i = tid; i < 8192; i += 256) {
            int r = i >> 6, np = i & 63;
            u16 h0, l0, h1, l1;
            f2bf2(se[r*129 + 2*np],     h0, l0);
            f2bf2(se[r*129 + 2*np + 1], h1, l1);
            oh[r*64 + np] = (u32)h0 | ((u32)h1 << 16);
            ol[r*64 + np] = (u32)l0 | ((u32)l1 << 16);
        }
    } else {
        // direct fp32 + bias stores (no smem round-trip)
        float bv = bias[blockIdx.x & 127];
        float* op = outp + (size_t)blockIdx.x * 16384;
#pragma unroll
        for (int mt = 0; mt < 2; mt++)
#pragma unroll
            for (int nt = 0; nt < 8; nt++) {
                int r = m0 + mt*16 + (lane >> 2);
                int c = n0 + nt*8 + 2*(lane & 3);
                float2 v0 = { acc[mt][nt][0] + bv, acc[mt][nt][1] + bv };
                float2 v1 = { acc[mt][nt][2] + bv, acc[mt][nt][3] + bv };
                *(float2*)(op + r*128 + c)       = v0;
                *(float2*)(op + (r + 8)*128 + c) = v1;
            }
    }
}

// ---------------- stage 3: per (b,k): y[o,w] = sum_{j,c} wd[k,j,o,c] * xd[b,c,k,(w-j)&127] ----------------
// Double-buffered A tiles via cp.async; B built once with shift folded into ldsm addressing.
#define TS3 144
__global__ __launch_bounds__(256, 2)
void k_conv_mma() {
    extern __shared__ __align__(16) char sm[];
    const u32 OFF_BH = 0, OFF_BL = 18432, OFF_A0 = 36864, OFF_A1 = 73728;
    u32 sb = smem_u32(sm);
    int tid = threadIdx.x, wid = tid >> 5, lane = tid & 31;
    int blk = blockIdx.x, b = blk >> 7, k = blk & 127;

    // 1. cp.async X slice into buf1 region: XH at OFF_A1, XL at OFF_A1+16384
    for (int i = tid; i < 1024; i += 256) {
        int c = i >> 4, ch = i & 15;
        size_t gi = ((size_t)(b*64 + c)*128 + k)*64 + ch*4;
        cp16(sb + OFF_A1 +         i*16, g_xdh + gi);
        cp16(sb + OFF_A1 + 16384 + i*16, g_xdl + gi);
    }
    CP_COMMIT();
    // 2. cp.async A_0 into buf0
    {
        size_t wbase = (size_t)(k*5 + 0) * 4096;
        for (int i = tid; i < 1024; i += 256) {
            int o = i >> 3, ch = i & 7;
            cp16(sb + OFF_A0 +         o*TS3 + ch*16, g_wdh + wbase + o*32 + ch*4);
            cp16(sb + OFF_A0 + 18432 + o*TS3 + ch*16, g_wdl + wbase + o*32 + ch*4);
        }
        CP_COMMIT();
    }
    CP_WAIT(1);
    __syncthreads();
    // 3. build B[w][c] once from X (shift applied on row index at ldsm time)
    {
        const u16* sh = (const u16*)(sm + OFF_A1);
        const u16* sl = (const u16*)(sm + OFF_A1 + 16384);
        u32* dBh = (u32*)(sm + OFF_BH);
        u32* dBl = (u32*)(sm + OFF_BL);
        for (int i = tid; i < 4096; i += 256) {
            int w = i & 127, cp = i >> 7;
            dBh[w*36 + cp] = (u32)sh[(2*cp)*128 + w] | ((u32)sh[(2*cp + 1)*128 + w] << 16);
            dBl[w*36 + cp] = (u32)sl[(2*cp)*128 + w] | ((u32)sl[(2*cp + 1)*128 + w] << 16);
        }
    }
    CP_WAIT(0);
    __syncthreads();

    int m0 = (wid >> 1) * 32, n0 = (wid & 1) * 64;
    int rowA = lane & 15;
    int kA = (lane & 16) ? 8 : 0;
    int rowB = lane & 7;
    int kB = (lane & 8) ? 8 : 0;

    float acc[2][8][4];
#pragma unroll
    for (int mt = 0; mt < 2; mt++)
#pragma unroll
        for (int nt = 0; nt < 8; nt++)
#pragma unroll
            for (int q = 0; q < 4; q++) acc[mt][nt][q] = 0.f;

#pragma unroll
    for (int j = 0; j < 5; j++) {
        if (j < 4) {
            size_t wbase = (size_t)(k*5 + j + 1) * 4096;
            u32 dst = sb + (((j + 1) & 1) ? OFF_A1 : OFF_A0);
            for (int i = tid; i < 1024; i += 256) {
                int o = i >> 3, ch = i & 7;
                cp16(dst +         o*TS3 + ch*16, g_wdh + wbase + o*32 + ch*4);
                cp16(dst + 18432 + o*TS3 + ch*16, g_wdl + wbase + o*32 + ch*4);
            }
            CP_COMMIT();
        }
        u32 aBase = sb + ((j & 1) ? OFF_A1 : OFF_A0);
#pragma unroll
        for (int ks = 0; ks < 4; ks++) {
            int k0 = ks * 16;
            u32 ah[2][4], al[2][4];
#pragma unroll
            for (int mt = 0; mt < 2; mt++) {
                u32 base = (u32)((m0 + mt*16 + rowA) * TS3 + (k0 + kA) * 2);
                ldsm_x4(ah[mt][0], ah[mt][1], ah[mt][2], ah[mt][3], aBase + base);
                ldsm_x4(al[mt][0], al[mt][1], al[mt][2], al[mt][3], aBase + 18432 + base);
            }
#pragma unroll
            for (int nt = 0; nt < 8; nt++) {
                int wr = ((n0 + nt*8 + rowB) - j) & 127;
                u32 base = (u32)(wr * TS3 + (k0 + kB) * 2);
                u32 bh0, bh1, bl0, bl1;
                ldsm_x2(bh0, bh1, sb + OFF_BH + base);
                ldsm_x2(bl0, bl1, sb + OFF_BL + base);
#pragma unroll
                for (int mt = 0; mt < 2; mt++) {
                    mma_bf16(acc[mt][nt], ah[mt][0], ah[mt][1], ah[mt][2], ah[mt][3], bh0, bh1);
                    mma_bf16(acc[mt][nt], ah[mt][0], ah[mt][1], ah[mt][2], ah[mt][3], bl0, bl1);
                    mma_bf16(acc[mt][nt], al[mt][0], al[mt][1], al[mt][2], al[mt][3], bh0, bh1);
                }
            }
        }
        if (j < 4) { CP_WAIT(0); __syncthreads(); }
    }

    // epilogue through fp32 staging
    __syncthreads();
    float* se = (float*)(sm);   // [128][129]
#pragma unroll
    for (int mt = 0; mt < 2; mt++)
#pragma unroll
        for (int nt = 0; nt < 8; nt++) {
            int r = m0 + mt*16 + (lane >> 2);
            int c = n0 + nt*8 + 2*(lane & 3);
            se[r*129 + c]           = acc[mt][nt][0];
            se[r*129 + c + 1]       = acc[mt][nt][1];
            se[(r + 8)*129 + c]     = acc[mt][nt][2];
            se[(r + 8)*129 + c + 1] = acc[mt][nt][3];
        }
    __syncthreads();
    for (int i = tid; i < 8192; i += 256) {
        int o = i >> 6, wp = i & 63;
        u16 h0, l0, h1, l1;
        f2bf2(se[o*129 + 2*wp],     h0, l0);
        f2bf2(se[o*129 + 2*wp + 1], h1, l1);
        size_t gi = ((size_t)(b*128 + o))*8192 + (size_t)k*64 + wp;
        g_yh[gi] = (u32)h0 | ((u32)h1 << 16);
        g_yl[gi] = (u32)l0 | ((u32)l1 << 16);
    }
}

// ---------------- launch ----------------
extern "C" void kernel_launch(void* const* d_in, const int* in_sizes, int n_in,
                              void* d_out, int out_size) {
    const float* x    = (const float*)d_in[0];   // (8,64,128,128)
    const float* wgt  = (const float*)d_in[1];   // (128,64,5,5)
    const float* bias = (const float*)d_in[2];   // (128,)
    float* out = (float*)d_out;                  // (8,128,128,128)

    const int SMG = 104448;
    const int SM3 = 110592;
    cudaFuncSetAttribute(k_gemm<0>,  cudaFuncAttributeMaxDynamicSharedMemorySize, SMG);
    cudaFuncSetAttribute(k_gemm<1>,  cudaFuncAttributeMaxDynamicSharedMemorySize, SMG);
    cudaFuncSetAttribute(k_conv_mma, cudaFuncAttributeMaxDynamicSharedMemorySize, SM3);

    k_consts  <<<32, 256>>>();
    k_wtrans  <<<640, 256>>>(wgt);
    k_gemm<0> <<<BATCH*CIN,  256, SMG>>>(x, nullptr, nullptr);
    k_conv_mma<<<BATCH*HH,   256, SM3>>>();
    k_gemm<1> <<<BATCH*COUT, 256, SMG>>>(nullptr, bias, out);
}

// round 10
// speedup vs baseline: 4.8167x; 1.0544x over previous
#include <cuda_runtime.h>
#include <cuda_bf16.h>
#include <math.h>

typedef unsigned int       u32;
typedef unsigned short     u16;
typedef unsigned long long u64;

#define BATCH 8
#define CIN   64
#define COUT  128
#define HH    128
#define WW    128

// ---------------- device globals (packed bf16 split planes; u32 = 2 bf16 along last dim) ----------------
__device__ u32 g_Dh[8192], g_Dl[8192];        // DCT matrix  [k][h/2]
__device__ u32 g_Mh[8192], g_Ml[8192];        // iDCT matrix [n][k/2]
__device__ float g_D5[640];                   // first 5 cols of D
__device__ u32 g_wdh[128*5*4096], g_wdl[128*5*4096];              // [k][j] tiles of [o][c/2] (128x32 u32)
__device__ u32 g_xdh[BATCH*CIN*HH*64],  g_xdl[BATCH*CIN*HH*64];   // [b][c][k][w/2]
__device__ u32 g_yh [BATCH*COUT*HH*64], g_yl [BATCH*COUT*HH*64];  // [b][o][k][w/2]

// ---------------- helpers ----------------
__device__ __forceinline__ u32 smem_u32(const void* p) {
    u32 a; asm("{ .reg .u64 t; cvta.to.shared.u64 t, %1; cvt.u32.u64 %0, t; }" : "=r"(a) : "l"(p));
    return a;
}
__device__ __forceinline__ void cp16(u32 dst, const void* src) {
    asm volatile("cp.async.cg.shared.global [%0], [%1], 16;" :: "r"(dst), "l"(src) : "memory");
}
#define CP_COMMIT() asm volatile("cp.async.commit_group;" ::: "memory")
#define CP_WAIT(n)  asm volatile("cp.async.wait_group %0;" :: "n"(n) : "memory")

__device__ __forceinline__ void ldsm_x4(u32& r0, u32& r1, u32& r2, u32& r3, u32 addr) {
    asm volatile("ldmatrix.sync.aligned.m8n8.x4.shared.b16 {%0,%1,%2,%3}, [%4];"
        : "=r"(r0), "=r"(r1), "=r"(r2), "=r"(r3) : "r"(addr) : "memory");
}
__device__ __forceinline__ void ldsm_x4t(u32& r0, u32& r1, u32& r2, u32& r3, u32 addr) {
    asm volatile("ldmatrix.sync.aligned.m8n8.x4.trans.shared.b16 {%0,%1,%2,%3}, [%4];"
        : "=r"(r0), "=r"(r1), "=r"(r2), "=r"(r3) : "r"(addr) : "memory");
}
__device__ __forceinline__ void mma_bf16(float* c, u32 a0, u32 a1, u32 a2, u32 a3, u32 b0, u32 b1) {
    asm volatile("mma.sync.aligned.m16n8k16.row.col.f32.bf16.bf16.f32 "
        "{%0,%1,%2,%3}, {%4,%5,%6,%7}, {%8,%9}, {%0,%1,%2,%3};"
        : "+f"(c[0]), "+f"(c[1]), "+f"(c[2]), "+f"(c[3])
        : "r"(a0), "r"(a1), "r"(a2), "r"(a3), "r"(b0), "r"(b1));
}
__device__ __forceinline__ void f2bf2(float v, u16& h, u16& l) {
    __nv_bfloat16 bh = __float2bfloat16(v);
    float fh = __bfloat162float(bh);
    __nv_bfloat16 bl = __float2bfloat16(v - fh);
    h = __bfloat16_as_ushort(bh);
    l = __bfloat16_as_ushort(bl);
}

// ---------------- constants ----------------
__global__ void k_consts() {
    int idx = blockIdx.x * blockDim.x + threadIdx.x;
    if (idx < 640) {
        int k = idx / 5, h = idx % 5;
        g_D5[idx] = (float)(2.0 * cos(M_PI * (2.0*h + 1.0) * k / 256.0));
    }
    if (idx >= 8192) return;
    int r = idx >> 6, cp = idx & 63;
    int c0 = 2*cp, c1 = 2*cp + 1;
    u16 h0, l0, h1, l1;
    float d0 = (float)(2.0 * cos(M_PI * (2.0*c0 + 1.0) * r / 256.0));
    float d1 = (float)(2.0 * cos(M_PI * (2.0*c1 + 1.0) * r / 256.0));
    f2bf2(d0, h0, l0); f2bf2(d1, h1, l1);
    g_Dh[idx] = (u32)h0 | ((u32)h1 << 16);
    g_Dl[idx] = (u32)l0 | ((u32)l1 << 16);
    float m0 = (float)(cos(M_PI * (2.0*r + 1.0) * c0 / 256.0) * ((c0 == 0) ? 0.5 : 1.0) / 256.0);
    float m1 = (float)(cos(M_PI * (2.0*r + 1.0) * c1 / 256.0) / 256.0);
    f2bf2(m0, h0, l0); f2bf2(m1, h1, l1);
    g_Mh[idx] = (u32)h0 | ((u32)h1 << 16);
    g_Ml[idx] = (u32)l0 | ((u32)l1 << 16);
}

// ---------------- weight transform: wd[k][j][o][c] = sum_h D[k,h]*W[o,c,h,j] ----------------
__global__ void k_wtrans(const float* __restrict__ wgt) {
    __shared__ float sw[5*64];
    int j = blockIdx.x >> 7, o = blockIdx.x & 127;
    int tid = threadIdx.x;
    for (int i = tid; i < 320; i += 256) {
        int h = i >> 6, c = i & 63;
        sw[h*64 + c] = wgt[((o*64 + c)*5 + h)*5 + j];
    }
    __syncthreads();
    for (int i = tid; i < 4096; i += 256) {
        int k = i >> 5, cp = i & 31;
        float a0 = 0.f, a1 = 0.f;
#pragma unroll
        for (int h = 0; h < 5; h++) {
            float d = g_D5[k*5 + h];
            a0 = fmaf(d, sw[h*64 + 2*cp],     a0);
            a1 = fmaf(d, sw[h*64 + 2*cp + 1], a1);
        }
        u16 h0, l0, h1, l1; f2bf2(a0, h0, l0); f2bf2(a1, h1, l1);
        u32 oi = (u32)(k*5 + j)*4096 + o*32 + cp;
        g_wdh[oi] = (u32)h0 | ((u32)h1 << 16);
        g_wdl[oi] = (u32)l0 | ((u32)l1 << 16);
    }
}

// ---------------- generic 128x128x128 mma GEMM, K split into 2x64 chunks ----------------
// B stored [k][n] row-major (stride 272B), fragments via ldmatrix.x4.trans (paired n-tiles).
// MODE 0 (stage 1): B built by direct LDG float4 + split-convert (no staging); epilogue -> g_xd planes
// MODE 1 (stage 4): B = y planes cp.async'd DIRECTLY into tiles; epilogue = direct fp32+bias gmem stores
#define TSA 144   // A row stride bytes (64 k-cols bf16 = 128B data)
#define TSB2 272  // B row stride bytes (128 n-cols bf16 = 256B data)
template<int MODE>
__global__ __launch_bounds__(256, 2)
void k_gemm(const float* __restrict__ xsrc, const float* __restrict__ bias, float* __restrict__ outp) {
    extern __shared__ __align__(16) char sm[];
    const u32 OFF_AH = 0, OFF_AL = 18432, OFF_BH = 36864,
              OFF_BL = MODE ? 36864 + 34816 : 36864 + 17408;
    u32 sb = smem_u32(sm);
    int tid = threadIdx.x, wid = tid >> 5, lane = tid & 31;

    int m0 = (wid >> 1) * 32, n0 = (wid & 1) * 64;
    int rowA = lane & 15;
    int kA = (lane & 16) ? 8 : 0;
    int rowK = lane & 15;                       // B trans: k-row within 16
    int ntAdd = (lane & 16) ? 8 : 0;            // paired n-tile select

    float acc[2][8][4];
#pragma unroll
    for (int mt = 0; mt < 2; mt++)
#pragma unroll
        for (int nt = 0; nt < 8; nt++)
#pragma unroll
            for (int q = 0; q < 4; q++) acc[mt][nt][q] = 0.f;

    for (int kk = 0; kk < 2; kk++) {
        __syncthreads();   // prev chunk's MMAs done before restaging
        // A half tiles via cp.async
        {
            const u32* Ah = MODE ? g_Mh : g_Dh;
            const u32* Al = MODE ? g_Ml : g_Dl;
            for (int i = tid; i < 1024; i += 256) {
                int r = i >> 3, ch = i & 7;      // row r: 32 u32 = 128B = 8x16B
                cp16(sb + OFF_AH + r*TSA + ch*16, Ah + r*64 + kk*32 + ch*4);
                cp16(sb + OFF_AL + r*TSA + ch*16, Al + r*64 + kk*32 + ch*4);
            }
        }
        if (MODE == 1) {
            // cp y planes straight into B tiles [k=64 rows][n]
            const u32* yh = g_yh + (size_t)blockIdx.x * 8192 + (size_t)kk * 4096;
            const u32* yl = g_yl + (size_t)blockIdx.x * 8192 + (size_t)kk * 4096;
            for (int i = tid; i < 1024; i += 256) {
                int r = i >> 4, ch = i & 15;     // row r: 64 u32 = 256B = 16x16B
                cp16(sb + OFF_BH + r*TSB2 + ch*16, yh + r*64 + ch*4);
                cp16(sb + OFF_BL + r*TSB2 + ch*16, yl + r*64 + ch*4);
            }
        }
        CP_COMMIT();
        if (MODE == 0) {
            // direct LDG fp32 x half [64 h][128 w] -> split-convert -> B tiles (overlaps A cp.async)
            const float4* xs = (const float4*)(xsrc + (size_t)blockIdx.x * 16384 + (size_t)kk * 8192);
            char* dBh = sm + OFF_BH;
            char* dBl = sm + OFF_BL;
            for (int i = tid; i < 2048; i += 256) {
                int h = i >> 5, w4 = i & 31;
                float4 v = xs[i];
                u16 a0, b0, a1, b1, a2, b2, a3, b3;
                f2bf2(v.x, a0, b0); f2bf2(v.y, a1, b1);
                f2bf2(v.z, a2, b2); f2bf2(v.w, a3, b3);
                *(uint2*)(dBh + h*TSB2 + w4*8) = make_uint2((u32)a0 | ((u32)a1 << 16), (u32)a2 | ((u32)a3 << 16));
                *(uint2*)(dBl + h*TSB2 + w4*8) = make_uint2((u32)b0 | ((u32)b1 << 16), (u32)b2 | ((u32)b3 << 16));
            }
        }
        CP_WAIT(0);
        __syncthreads();
#pragma unroll
        for (int ks = 0; ks < 4; ks++) {
            int k0 = ks * 16;
            u32 ah[2][4], al[2][4];
#pragma unroll
            for (int mt = 0; mt < 2; mt++) {
                u32 base = (u32)((m0 + mt*16 + rowA) * TSA + (k0 + kA) * 2);
                ldsm_x4(ah[mt][0], ah[mt][1], ah[mt][2], ah[mt][3], sb + OFF_AH + base);
                ldsm_x4(al[mt][0], al[mt][1], al[mt][2], al[mt][3], sb + OFF_AL + base);
            }
            u32 rbase = (u32)((k0 + rowK) * TSB2);
#pragma unroll
            for (int nt = 0; nt < 8; nt += 2) {
                u32 off = rbase + (u32)((n0 + nt*8 + ntAdd) * 2);
                u32 bh[4], bl[4];
                ldsm_x4t(bh[0], bh[1], bh[2], bh[3], sb + OFF_BH + off);
                ldsm_x4t(bl[0], bl[1], bl[2], bl[3], sb + OFF_BL + off);
#pragma unroll
                for (int q = 0; q < 2; q++)
#pragma unroll
                    for (int mt = 0; mt < 2; mt++) {
                        mma_bf16(acc[mt][nt + q], ah[mt][0], ah[mt][1], ah[mt][2], ah[mt][3], bh[2*q], bh[2*q + 1]);
                        mma_bf16(acc[mt][nt + q], ah[mt][0], ah[mt][1], ah[mt][2], ah[mt][3], bl[2*q], bl[2*q + 1]);
                        mma_bf16(acc[mt][nt + q], al[mt][0], al[mt][1], al[mt][2], al[mt][3], bh[2*q], bh[2*q + 1]);
                    }
            }
        }
    }

    if (MODE == 0) {
        // epilogue through fp32 staging, pack to split planes (coalesced u32 stores)
        __syncthreads();
        float* se = (float*)(sm);   // [128][129] = 66048 <= 71680
#pragma unroll
        for (int mt = 0; mt < 2; mt++)
#pragma unroll
            for (int nt = 0; nt < 8; nt++) {
                int r = m0 + mt*16 + (lane >> 2);
                int c = n0 + nt*8 + 2*(lane & 3);
                se[r*129 + c]           = acc[mt][nt][0];
                se[r*129 + c + 1]       = acc[mt][nt][1];
                se[(r + 8)*129 + c]     = acc[mt][nt][2];
                se[(r + 8)*129 + c + 1] = acc[mt][nt][3];
            }
        __syncthreads();
        u32* oh = g_xdh + (size_t)blockIdx.x * 8192;
        u32* ol = g_xdl + (size_t)blockIdx.x * 8192;
        for (int i = tid; i < 8192; i += 256) {
            int r = i >> 6, np = i & 63;
            u16 h0, l0, h1, l1;
            f2bf2(se[r*129 + 2*np],     h0, l0);
            f2bf2(se[r*129 + 2*np + 1], h1, l1);
            oh[r*64 + np] = (u32)h0 | ((u32)h1 << 16);
            ol[r*64 + np] = (u32)l0 | ((u32)l1 << 16);
        }
    } else {
        // direct fp32 + bias stores
        float bv = bias[blockIdx.x & 127];
        float* op = outp + (size_t)blockIdx.x * 16384;
#pragma unroll
        for (int mt = 0; mt < 2; mt++)
#pragma unroll
            for (int nt = 0; nt < 8; nt++) {
                int r = m0 + mt*16 + (lane >> 2);
                int c = n0 + nt*8 + 2*(lane & 3);
                float2 v0 = { acc[mt][nt][0] + bv, acc[mt][nt][1] + bv };
                float2 v1 = { acc[mt][nt][2] + bv, acc[mt][nt][3] + bv };
                *(float2*)(op + r*128 + c)       = v0;
                *(float2*)(op + (r + 8)*128 + c) = v1;
            }
    }
}

// ---------------- stage 3: per (b,k): y[o,w] = sum_{j,c} wd[k,j,o,c] * xd[b,c,k,(w-j)&127] ----------------
// Double-buffered A tiles via cp.async; B built once with shift folded into ldsm addressing.
#define TS3 144
__global__ __launch_bounds__(256, 2)
void k_conv_mma() {
    extern __shared__ __align__(16) char sm[];
    const u32 OFF_BH = 0, OFF_BL = 18432, OFF_A0 = 36864, OFF_A1 = 73728;
    u32 sb = smem_u32(sm);
    int tid = threadIdx.x, wid = tid >> 5, lane = tid & 31;
    int blk = blockIdx.x, b = blk >> 7, k = blk & 127;

    // 1. cp.async X slice into buf1 region: XH at OFF_A1, XL at OFF_A1+16384
    for (int i = tid; i < 1024; i += 256) {
        int c = i >> 4, ch = i & 15;
        size_t gi = ((size_t)(b*64 + c)*128 + k)*64 + ch*4;
        cp16(sb + OFF_A1 +         i*16, g_xdh + gi);
        cp16(sb + OFF_A1 + 16384 + i*16, g_xdl + gi);
    }
    CP_COMMIT();
    // 2. cp.async A_0 into buf0
    {
        size_t wbase = (size_t)(k*5 + 0) * 4096;
        for (int i = tid; i < 1024; i += 256) {
            int o = i >> 3, ch = i & 7;
            cp16(sb + OFF_A0 +         o*TS3 + ch*16, g_wdh + wbase + o*32 + ch*4);
            cp16(sb + OFF_A0 + 18432 + o*TS3 + ch*16, g_wdl + wbase + o*32 + ch*4);
        }
        CP_COMMIT();
    }
    CP_WAIT(1);
    __syncthreads();
    // 3. build B[w][c] once from X
    {
        const u16* sh = (const u16*)(sm + OFF_A1);
        const u16* sl = (const u16*)(sm + OFF_A1 + 16384);
        u32* dBh = (u32*)(sm + OFF_BH);
        u32* dBl = (u32*)(sm + OFF_BL);
        for (int i = tid; i < 4096; i += 256) {
            int w = i & 127, cp = i >> 7;
            dBh[w*36 + cp] = (u32)sh[(2*cp)*128 + w] | ((u32)sh[(2*cp + 1)*128 + w] << 16);
            dBl[w*36 + cp] = (u32)sl[(2*cp)*128 + w] | ((u32)sl[(2*cp + 1)*128 + w] << 16);
        }
    }
    CP_WAIT(0);
    __syncthreads();

    int m0 = (wid >> 1) * 32, n0 = (wid & 1) * 64;
    int rowA = lane & 15;
    int kA = (lane & 16) ? 8 : 0;
    int rowB = lane & 7;
    int kB = (lane & 8) ? 8 : 0;
    int ntAdd = (lane & 16) ? 8 : 0;            // paired n-tile select (x4 B loads)

    float acc[2][8][4];
#pragma unroll
    for (int mt = 0; mt < 2; mt++)
#pragma unroll
        for (int nt = 0; nt < 8; nt++)
#pragma unroll
            for (int q = 0; q < 4; q++) acc[mt][nt][q] = 0.f;

#pragma unroll
    for (int j = 0; j < 5; j++) {
        if (j < 4) {
            size_t wbase = (size_t)(k*5 + j + 1) * 4096;
            u32 dst = sb + (((j + 1) & 1) ? OFF_A1 : OFF_A0);
            for (int i = tid; i < 1024; i += 256) {
                int o = i >> 3, ch = i & 7;
                cp16(dst +         o*TS3 + ch*16, g_wdh + wbase + o*32 + ch*4);
                cp16(dst + 18432 + o*TS3 + ch*16, g_wdl + wbase + o*32 + ch*4);
            }
            CP_COMMIT();
        }
        u32 aBase = sb + ((j & 1) ? OFF_A1 : OFF_A0);
#pragma unroll
        for (int ks = 0; ks < 4; ks++) {
            int k0 = ks * 16;
            u32 ah[2][4], al[2][4];
#pragma unroll
            for (int mt = 0; mt < 2; mt++) {
                u32 base = (u32)((m0 + mt*16 + rowA) * TS3 + (k0 + kA) * 2);
                ldsm_x4(ah[mt][0], ah[mt][1], ah[mt][2], ah[mt][3], aBase + base);
                ldsm_x4(al[mt][0], al[mt][1], al[mt][2], al[mt][3], aBase + 18432 + base);
            }
#pragma unroll
            for (int nt = 0; nt < 8; nt += 2) {
                int wr = ((n0 + nt*8 + ntAdd + rowB) - j) & 127;   // circular shift on row index
                u32 base = (u32)(wr * TS3 + (k0 + kB) * 2);
                u32 bh[4], bl[4];
                ldsm_x4(bh[0], bh[1], bh[2], bh[3], sb + OFF_BH + base);
                ldsm_x4(bl[0], bl[1], bl[2], bl[3], sb + OFF_BL + base);
#pragma unroll
                for (int q = 0; q < 2; q++)
#pragma unroll
                    for (int mt = 0; mt < 2; mt++) {
                        mma_bf16(acc[mt][nt + q], ah[mt][0], ah[mt][1], ah[mt][2], ah[mt][3], bh[2*q], bh[2*q + 1]);
                        mma_bf16(acc[mt][nt + q], ah[mt][0], ah[mt][1], ah[mt][2], ah[mt][3], bl[2*q], bl[2*q + 1]);
                        mma_bf16(acc[mt][nt + q], al[mt][0], al[mt][1], al[mt][2], al[mt][3], bh[2*q], bh[2*q + 1]);
                    }
            }
        }
        if (j < 4) { CP_WAIT(0); __syncthreads(); }
    }

    // epilogue through fp32 staging
    __syncthreads();
    float* se = (float*)(sm);   // [128][129]
#pragma unroll
    for (int mt = 0; mt < 2; mt++)
#pragma unroll
        for (int nt = 0; nt < 8; nt++) {
            int r = m0 + mt*16 + (lane >> 2);
            int c = n0 + nt*8 + 2*(lane & 3);
            se[r*129 + c]           = acc[mt][nt][0];
            se[r*129 + c + 1]       = acc[mt][nt][1];
            se[(r + 8)*129 + c]     = acc[mt][nt][2];
            se[(r + 8)*129 + c + 1] = acc[mt][nt][3];
        }
    __syncthreads();
    for (int i = tid; i < 8192; i += 256) {
        int o = i >> 6, wp = i & 63;
        u16 h0, l0, h1, l1;
        f2bf2(se[o*129 + 2*wp],     h0, l0);
        f2bf2(se[o*129 + 2*wp + 1], h1, l1);
        size_t gi = ((size_t)(b*128 + o))*8192 + (size_t)k*64 + wp;
        g_yh[gi] = (u32)h0 | ((u32)h1 << 16);
        g_yl[gi] = (u32)l0 | ((u32)l1 << 16);
    }
}

// ---------------- launch ----------------
extern "C" void kernel_launch(void* const* d_in, const int* in_sizes, int n_in,
                              void* d_out, int out_size) {
    const float* x    = (const float*)d_in[0];   // (8,64,128,128)
    const float* wgt  = (const float*)d_in[1];   // (128,64,5,5)
    const float* bias = (const float*)d_in[2];   // (128,)
    float* out = (float*)d_out;                  // (8,128,128,128)

    const int SMG0 = 71680;    // A 36864 + B 2x17408
    const int SMG1 = 106496;   // A 36864 + B 2x34816
    const int SM3  = 110592;
    cudaFuncSetAttribute(k_gemm<0>,  cudaFuncAttributeMaxDynamicSharedMemorySize, SMG0);
    cudaFuncSetAttribute(k_gemm<1>,  cudaFuncAttributeMaxDynamicSharedMemorySize, SMG1);
    cudaFuncSetAttribute(k_conv_mma, cudaFuncAttributeMaxDynamicSharedMemorySize, SM3);

    k_consts  <<<32, 256>>>();
    k_wtrans  <<<640, 256>>>(wgt);
    k_gemm<0> <<<BATCH*CIN,  256, SMG0>>>(x, nullptr, nullptr);
    k_conv_mma<<<BATCH*HH,   256, SM3>>>();
    k_gemm<1> <<<BATCH*COUT, 256, SMG1>>>(nullptr, bias, out);
}

// round 11
// speedup vs baseline: 5.0191x; 1.0420x over previous
#include <cuda_runtime.h>
#include <cuda_bf16.h>
#include <math.h>

typedef unsigned int       u32;
typedef unsigned short     u16;
typedef unsigned long long u64;

#define BATCH 8
#define CIN   64
#define COUT  128
#define HH    128
#define WW    128

// ---------------- device globals (packed bf16 split planes; u32 = 2 bf16 along last dim) ----------------
__device__ u32 g_Dh[8192], g_Dl[8192];        // DCT matrix  [k][h/2]
__device__ u32 g_Mh[8192], g_Ml[8192];        // iDCT matrix [n][k/2]
__device__ float g_D5[640];                   // first 5 cols of D
__device__ u32 g_wdh[128*5*4096], g_wdl[128*5*4096];              // [k][j] tiles of [o][c/2] (128x32 u32)
__device__ u32 g_xdh[BATCH*CIN*HH*64],  g_xdl[BATCH*CIN*HH*64];   // [b][c][k][w/2]
__device__ u32 g_yh [BATCH*COUT*HH*64], g_yl [BATCH*COUT*HH*64];  // [b][o][k][w/2]

// ---------------- helpers ----------------
__device__ __forceinline__ u32 smem_u32(const void* p) {
    u32 a; asm("{ .reg .u64 t; cvta.to.shared.u64 t, %1; cvt.u32.u64 %0, t; }" : "=r"(a) : "l"(p));
    return a;
}
__device__ __forceinline__ void cp16(u32 dst, const void* src) {
    asm volatile("cp.async.cg.shared.global [%0], [%1], 16;" :: "r"(dst), "l"(src) : "memory");
}
#define CP_COMMIT() asm volatile("cp.async.commit_group;" ::: "memory")
#define CP_WAIT(n)  asm volatile("cp.async.wait_group %0;" :: "n"(n) : "memory")

__device__ __forceinline__ void ldsm_x4(u32& r0, u32& r1, u32& r2, u32& r3, u32 addr) {
    asm volatile("ldmatrix.sync.aligned.m8n8.x4.shared.b16 {%0,%1,%2,%3}, [%4];"
        : "=r"(r0), "=r"(r1), "=r"(r2), "=r"(r3) : "r"(addr) : "memory");
}
__device__ __forceinline__ void ldsm_x4t(u32& r0, u32& r1, u32& r2, u32& r3, u32 addr) {
    asm volatile("ldmatrix.sync.aligned.m8n8.x4.trans.shared.b16 {%0,%1,%2,%3}, [%4];"
        : "=r"(r0), "=r"(r1), "=r"(r2), "=r"(r3) : "r"(addr) : "memory");
}
__device__ __forceinline__ void mma_bf16(float* c, u32 a0, u32 a1, u32 a2, u32 a3, u32 b0, u32 b1) {
    asm volatile("mma.sync.aligned.m16n8k16.row.col.f32.bf16.bf16.f32 "
        "{%0,%1,%2,%3}, {%4,%5,%6,%7}, {%8,%9}, {%0,%1,%2,%3};"
        : "+f"(c[0]), "+f"(c[1]), "+f"(c[2]), "+f"(c[3])
        : "r"(a0), "r"(a1), "r"(a2), "r"(a3), "r"(b0), "r"(b1));
}
__device__ __forceinline__ void f2bf2(float v, u16& h, u16& l) {
    __nv_bfloat16 bh = __float2bfloat16(v);
    float fh = __bfloat162float(bh);
    __nv_bfloat16 bl = __float2bfloat16(v - fh);
    h = __bfloat16_as_ushort(bh);
    l = __bfloat16_as_ushort(bl);
}

// ---------------- constants ----------------
__global__ void k_consts() {
    int idx = blockIdx.x * blockDim.x + threadIdx.x;
    if (idx < 640) {
        int k = idx / 5, h = idx % 5;
        g_D5[idx] = (float)(2.0 * cos(M_PI * (2.0*h + 1.0) * k / 256.0));
    }
    if (idx >= 8192) return;
    int r = idx >> 6, cp = idx & 63;
    int c0 = 2*cp, c1 = 2*cp + 1;
    u16 h0, l0, h1, l1;
    float d0 = (float)(2.0 * cos(M_PI * (2.0*c0 + 1.0) * r / 256.0));
    float d1 = (float)(2.0 * cos(M_PI * (2.0*c1 + 1.0) * r / 256.0));
    f2bf2(d0, h0, l0); f2bf2(d1, h1, l1);
    g_Dh[idx] = (u32)h0 | ((u32)h1 << 16);
    g_Dl[idx] = (u32)l0 | ((u32)l1 << 16);
    float m0 = (float)(cos(M_PI * (2.0*r + 1.0) * c0 / 256.0) * ((c0 == 0) ? 0.5 : 1.0) / 256.0);
    float m1 = (float)(cos(M_PI * (2.0*r + 1.0) * c1 / 256.0) / 256.0);
    f2bf2(m0, h0, l0); f2bf2(m1, h1, l1);
    g_Mh[idx] = (u32)h0 | ((u32)h1 << 16);
    g_Ml[idx] = (u32)l0 | ((u32)l1 << 16);
}

// ---------------- weight transform: wd[k][j][o][c] = sum_h D[k,h]*W[o,c,h,j] ----------------
__global__ void k_wtrans(const float* __restrict__ wgt) {
    __shared__ float sw[5*64];
    int j = blockIdx.x >> 7, o = blockIdx.x & 127;
    int tid = threadIdx.x;
    for (int i = tid; i < 320; i += 256) {
        int h = i >> 6, c = i & 63;
        sw[h*64 + c] = wgt[((o*64 + c)*5 + h)*5 + j];
    }
    __syncthreads();
    for (int i = tid; i < 4096; i += 256) {
        int k = i >> 5, cp = i & 31;
        float a0 = 0.f, a1 = 0.f;
#pragma unroll
        for (int h = 0; h < 5; h++) {
            float d = g_D5[k*5 + h];
            a0 = fmaf(d, sw[h*64 + 2*cp],     a0);
            a1 = fmaf(d, sw[h*64 + 2*cp + 1], a1);
        }
        u16 h0, l0, h1, l1; f2bf2(a0, h0, l0); f2bf2(a1, h1, l1);
        u32 oi = (u32)(k*5 + j)*4096 + o*32 + cp;
        g_wdh[oi] = (u32)h0 | ((u32)h1 << 16);
        g_wdl[oi] = (u32)l0 | ((u32)l1 << 16);
    }
}

// ---------------- generic 128x128x128 mma GEMM, K split into 4 chunks of 32, 2-stage pipeline ----
// A chunk tile: 128 rows x 32 k-bf16, stride 80B (conflict-free). B chunk: [32 k-rows][128 n], stride 272B.
// MODE 0 (stage 1): x fp32 cp.async'd to stage buf, per-thread converted (no extra sync); -> g_xd planes
// MODE 1 (stage 4): B = y planes cp.async'd directly; epilogue = direct fp32+bias gmem stores
#define TSA4 80   // A chunk row stride bytes (32 bf16 = 64B data)
#define TSB2 272  // B row stride bytes (128 n-cols bf16 = 256B data)
template<int MODE>
__global__ __launch_bounds__(256, 2)
void k_gemm(const float* __restrict__ xsrc, const float* __restrict__ bias, float* __restrict__ outp) {
    extern __shared__ __align__(16) char sm[];
    // stages: A at s*20480 (planes +0/+10240); B at 40960+s*17408 (planes +0/+8704); X at 75776+s*16384
    u32 sb = smem_u32(sm);
    int tid = threadIdx.x, wid = tid >> 5, lane = tid & 31;

    int m0 = (wid >> 1) * 32, n0 = (wid & 1) * 64;
    int rowA = lane & 15;
    int kA = (lane & 16) ? 8 : 0;
    int rowK = lane & 15;                       // B trans: k-row within 16
    int ntAdd = (lane & 16) ? 8 : 0;            // paired n-tile select

    const u32* Ah = MODE ? g_Mh : g_Dh;
    const u32* Al = MODE ? g_Ml : g_Dl;
    const u32* yh = MODE ? g_yh + (size_t)blockIdx.x * 8192 : nullptr;
    const u32* yl = MODE ? g_yl + (size_t)blockIdx.x * 8192 : nullptr;
    const char* xblk = MODE ? nullptr : (const char*)(xsrc + (size_t)blockIdx.x * 16384);

    // ---- load chunk c into stage s: A (+ B or x-stage) via cp.async ----
    auto load_chunk = [&](int c, int s) {
        u32 aBase = sb + s*20480;
        for (int i = tid; i < 1024; i += 256) {
            int p = i >> 9, ii = i & 511;
            int r = ii >> 2, ch = ii & 3;
            cp16(aBase + p*10240 + r*TSA4 + ch*16, (p ? Al : Ah) + r*64 + c*16 + ch*4);
        }
        if (MODE == 1) {
            u32 bBase = sb + 40960 + s*17408;
            for (int i = tid; i < 1024; i += 256) {
                int p = i >> 9, ii = i & 511;
                int r = ii >> 4, ch = ii & 15;
                cp16(bBase + p*8704 + r*TSB2 + ch*16, (p ? yl : yh) + (c*32 + r)*64 + ch*4);
            }
        } else {
            u32 xBase = sb + 75776 + s*16384;
            const char* src = xblk + (size_t)c * 16384;
            for (int i = tid; i < 1024; i += 256)
                cp16(xBase + i*16, src + i*16);
        }
        CP_COMMIT();
    };
    // ---- MODE0: convert own staged fp32 bytes -> B tiles of stage s (call after CP_WAIT) ----
    auto convert_chunk = [&](int s) {
        const char* xBase = sm + 75776 + s*16384;
        char* dBh = sm + 40960 + s*17408;
        char* dBl = dBh + 8704;
        for (int i = tid; i < 1024; i += 256) {
            float4 v = *(const float4*)(xBase + i*16);
            int h = i >> 5, w4 = i & 31;
            u16 a0, b0, a1, b1, a2, b2, a3, b3;
            f2bf2(v.x, a0, b0); f2bf2(v.y, a1, b1);
            f2bf2(v.z, a2, b2); f2bf2(v.w, a3, b3);
            *(uint2*)(dBh + h*TSB2 + w4*8) = make_uint2((u32)a0 | ((u32)a1 << 16), (u32)a2 | ((u32)a3 << 16));
            *(uint2*)(dBl + h*TSB2 + w4*8) = make_uint2((u32)b0 | ((u32)b1 << 16), (u32)b2 | ((u32)b3 << 16));
        }
    };

    float acc[2][8][4];
#pragma unroll
    for (int mt = 0; mt < 2; mt++)
#pragma unroll
        for (int nt = 0; nt < 8; nt++)
#pragma unroll
            for (int q = 0; q < 4; q++) acc[mt][nt][q] = 0.f;

    // prologue: chunk 0 -> stage 0
    load_chunk(0, 0);
    CP_WAIT(0);
    if (MODE == 0) convert_chunk(0);
    __syncthreads();

#pragma unroll
    for (int c = 0; c < 4; c++) {
        int s = c & 1;
        if (c < 3) load_chunk(c + 1, 1 - s);
        u32 aBase = sb + s*20480;
        u32 bBase = sb + 40960 + s*17408;
#pragma unroll
        for (int ks = 0; ks < 2; ks++) {
            int k0 = ks * 16;
            u32 ah[2][4], al[2][4];
#pragma unroll
            for (int mt = 0; mt < 2; mt++) {
                u32 base = (u32)((m0 + mt*16 + rowA) * TSA4 + (k0 + kA) * 2);
                ldsm_x4(ah[mt][0], ah[mt][1], ah[mt][2], ah[mt][3], aBase + base);
                ldsm_x4(al[mt][0], al[mt][1], al[mt][2], al[mt][3], aBase + 10240 + base);
            }
            u32 rbase = (u32)((k0 + rowK) * TSB2);
#pragma unroll
            for (int nt = 0; nt < 8; nt += 2) {
                u32 off = rbase + (u32)((n0 + nt*8 + ntAdd) * 2);
                u32 bh[4], bl[4];
                ldsm_x4t(bh[0], bh[1], bh[2], bh[3], bBase + off);
                ldsm_x4t(bl[0], bl[1], bl[2], bl[3], bBase + 8704 + off);
#pragma unroll
                for (int q = 0; q < 2; q++)
#pragma unroll
                    for (int mt = 0; mt < 2; mt++) {
                        mma_bf16(acc[mt][nt + q], ah[mt][0], ah[mt][1], ah[mt][2], ah[mt][3], bh[2*q], bh[2*q + 1]);
                        mma_bf16(acc[mt][nt + q], ah[mt][0], ah[mt][1], ah[mt][2], ah[mt][3], bl[2*q], bl[2*q + 1]);
                        mma_bf16(acc[mt][nt + q], al[mt][0], al[mt][1], al[mt][2], al[mt][3], bh[2*q], bh[2*q + 1]);
                    }
            }
        }
        if (c < 3) {
            CP_WAIT(0);
            if (MODE == 0) convert_chunk(1 - s);
            __syncthreads();
        }
    }

    if (MODE == 0) {
        // epilogue through fp32 staging, pack to split planes (coalesced u32 stores)
        __syncthreads();
        float* se = (float*)(sm);   // [128][129] = 66048 <= 108544
#pragma unroll
        for (int mt = 0; mt < 2; mt++)
#pragma unroll
            for (int nt = 0; nt < 8; nt++) {
                int r = m0 + mt*16 + (lane >> 2);
                int c = n0 + nt*8 + 2*(lane & 3);
                se[r*129 + c]           = acc[mt][nt][0];
                se[r*129 + c + 1]       = acc[mt][nt][1];
                se[(r + 8)*129 + c]     = acc[mt][nt][2];
                se[(r + 8)*129 + c + 1] = acc[mt][nt][3];
            }
        __syncthreads();
        u32* oh = g_xdh + (size_t)blockIdx.x * 8192;
        u32* ol = g_xdl + (size_t)blockIdx.x * 8192;
        for (int i = tid; i < 8192; i += 256) {
            int r = i >> 6, np = i & 63;
            u16 h0, l0, h1, l1;
            f2bf2(se[r*129 + 2*np],     h0, l0);
            f2bf2(se[r*129 + 2*np + 1], h1, l1);
            oh[r*64 + np] = (u32)h0 | ((u32)h1 << 16);
            ol[r*64 + np] = (u32)l0 | ((u32)l1 << 16);
        }
    } else {
        // direct fp32 + bias stores
        float bv = bias[blockIdx.x & 127];
        float* op = outp + (size_t)blockIdx.x * 16384;
#pragma unroll
        for (int mt = 0; mt < 2; mt++)
#pragma unroll
            for (int nt = 0; nt < 8; nt++) {
                int r = m0 + mt*16 + (lane >> 2);
                int c = n0 + nt*8 + 2*(lane & 3);
                float2 v0 = { acc[mt][nt][0] + bv, acc[mt][nt][1] + bv };
                float2 v1 = { acc[mt][nt][2] + bv, acc[mt][nt][3] + bv };
                *(float2*)(op + r*128 + c)       = v0;
                *(float2*)(op + (r + 8)*128 + c) = v1;
            }
    }
}

// ---------------- stage 3: per (b,k): y[o,w] = sum_{j,c} wd[k,j,o,c] * xd[b,c,k,(w-j)&127] ----------------
// Double-buffered A tiles via cp.async; B built once with shift folded into ldsm addressing.
#define TS3 144
__global__ __launch_bounds__(256, 2)
void k_conv_mma() {
    extern __shared__ __align__(16) char sm[];
    const u32 OFF_BH = 0, OFF_BL = 18432, OFF_A0 = 36864, OFF_A1 = 73728;
    u32 sb = smem_u32(sm);
    int tid = threadIdx.x, wid = tid >> 5, lane = tid & 31;
    int blk = blockIdx.x, b = blk >> 7, k = blk & 127;

    // 1. cp.async X slice into buf1 region: XH at OFF_A1, XL at OFF_A1+16384
    for (int i = tid; i < 1024; i += 256) {
        int c = i >> 4, ch = i & 15;
        size_t gi = ((size_t)(b*64 + c)*128 + k)*64 + ch*4;
        cp16(sb + OFF_A1 +         i*16, g_xdh + gi);
        cp16(sb + OFF_A1 + 16384 + i*16, g_xdl + gi);
    }
    CP_COMMIT();
    // 2. cp.async A_0 into buf0
    {
        size_t wbase = (size_t)(k*5 + 0) * 4096;
        for (int i = tid; i < 1024; i += 256) {
            int o = i >> 3, ch = i & 7;
            cp16(sb + OFF_A0 +         o*TS3 + ch*16, g_wdh + wbase + o*32 + ch*4);
            cp16(sb + OFF_A0 + 18432 + o*TS3 + ch*16, g_wdl + wbase + o*32 + ch*4);
        }
        CP_COMMIT();
    }
    CP_WAIT(1);
    __syncthreads();
    // 3. build B[w][c] once from X
    {
        const u16* sh = (const u16*)(sm + OFF_A1);
        const u16* sl = (const u16*)(sm + OFF_A1 + 16384);
        u32* dBh = (u32*)(sm + OFF_BH);
        u32* dBl = (u32*)(sm + OFF_BL);
        for (int i = tid; i < 4096; i += 256) {
            int w = i & 127, cp = i >> 7;
            dBh[w*36 + cp] = (u32)sh[(2*cp)*128 + w] | ((u32)sh[(2*cp + 1)*128 + w] << 16);
            dBl[w*36 + cp] = (u32)sl[(2*cp)*128 + w] | ((u32)sl[(2*cp + 1)*128 + w] << 16);
        }
    }
    CP_WAIT(0);
    __syncthreads();

    int m0 = (wid >> 1) * 32, n0 = (wid & 1) * 64;
    int rowA = lane & 15;
    int kA = (lane & 16) ? 8 : 0;
    int rowB = lane & 7;
    int kB = (lane & 8) ? 8 : 0;
    int ntAdd = (lane & 16) ? 8 : 0;            // paired n-tile select (x4 B loads)

    float acc[2][8][4];
#pragma unroll
    for (int mt = 0; mt < 2; mt++)
#pragma unroll
        for (int nt = 0; nt < 8; nt++)
#pragma unroll
            for (int q = 0; q < 4; q++) acc[mt][nt][q] = 0.f;

#pragma unroll
    for (int j = 0; j < 5; j++) {
        if (j < 4) {
            size_t wbase = (size_t)(k*5 + j + 1) * 4096;
            u32 dst = sb + (((j + 1) & 1) ? OFF_A1 : OFF_A0);
            for (int i = tid; i < 1024; i += 256) {
                int o = i >> 3, ch = i & 7;
                cp16(dst +         o*TS3 + ch*16, g_wdh + wbase + o*32 + ch*4);
                cp16(dst + 18432 + o*TS3 + ch*16, g_wdl + wbase + o*32 + ch*4);
            }
            CP_COMMIT();
        }
        u32 aBase = sb + ((j & 1) ? OFF_A1 : OFF_A0);
#pragma unroll
        for (int ks = 0; ks < 4; ks++) {
            int k0 = ks * 16;
            u32 ah[2][4], al[2][4];
#pragma unroll
            for (int mt = 0; mt < 2; mt++) {
                u32 base = (u32)((m0 + mt*16 + rowA) * TS3 + (k0 + kA) * 2);
                ldsm_x4(ah[mt][0], ah[mt][1], ah[mt][2], ah[mt][3], aBase + base);
                ldsm_x4(al[mt][0], al[mt][1], al[mt][2], al[mt][3], aBase + 18432 + base);
            }
#pragma unroll
            for (int nt = 0; nt < 8; nt += 2) {
                int wr = ((n0 + nt*8 + ntAdd + rowB) - j) & 127;   // circular shift on row index
                u32 base = (u32)(wr * TS3 + (k0 + kB) * 2);
                u32 bh[4], bl[4];
                ldsm_x4(bh[0], bh[1], bh[2], bh[3], sb + OFF_BH + base);
                ldsm_x4(bl[0], bl[1], bl[2], bl[3], sb + OFF_BL + base);
#pragma unroll
                for (int q = 0; q < 2; q++)
#pragma unroll
                    for (int mt = 0; mt < 2; mt++) {
                        mma_bf16(acc[mt][nt + q], ah[mt][0], ah[mt][1], ah[mt][2], ah[mt][3], bh[2*q], bh[2*q + 1]);
                        mma_bf16(acc[mt][nt + q], ah[mt][0], ah[mt][1], ah[mt][2], ah[mt][3], bl[2*q], bl[2*q + 1]);
                        mma_bf16(acc[mt][nt + q], al[mt][0], al[mt][1], al[mt][2], al[mt][3], bh[2*q], bh[2*q + 1]);
                    }
            }
        }
        if (j < 4) { CP_WAIT(0); __syncthreads(); }
    }

    // epilogue through fp32 staging
    __syncthreads();
    float* se = (float*)(sm);   // [128][129]
#pragma unroll
    for (int mt = 0; mt < 2; mt++)
#pragma unroll
        for (int nt = 0; nt < 8; nt++) {
            int r = m0 + mt*16 + (lane >> 2);
            int c = n0 + nt*8 + 2*(lane & 3);
            se[r*129 + c]           = acc[mt][nt][0];
            se[r*129 + c + 1]       = acc[mt][nt][1];
            se[(r + 8)*129 + c]     = acc[mt][nt][2];
            se[(r + 8)*129 + c + 1] = acc[mt][nt][3];
        }
    __syncthreads();
    for (int i = tid; i < 8192; i += 256) {
        int o = i >> 6, wp = i & 63;
        u16 h0, l0, h1, l1;
        f2bf2(se[o*129 + 2*wp],     h0, l0);
        f2bf2(se[o*129 + 2*wp + 1], h1, l1);
        size_t gi = ((size_t)(b*128 + o))*8192 + (size_t)k*64 + wp;
        g_yh[gi] = (u32)h0 | ((u32)h1 << 16);
        g_yl[gi] = (u32)l0 | ((u32)l1 << 16);
    }
}

// ---------------- launch ----------------
extern "C" void kernel_launch(void* const* d_in, const int* in_sizes, int n_in,
                              void* d_out, int out_size) {
    const float* x    = (const float*)d_in[0];   // (8,64,128,128)
    const float* wgt  = (const float*)d_in[1];   // (128,64,5,5)
    const float* bias = (const float*)d_in[2];   // (128,)
    float* out = (float*)d_out;                  // (8,128,128,128)

    const int SMG0 = 108544;   // A 2x20480 + B 2x17408 + X 2x16384
    const int SMG1 = 75776;    // A 2x20480 + B 2x17408
    const int SM3  = 110592;
    cudaFuncSetAttribute(k_gemm<0>,  cudaFuncAttributeMaxDynamicSharedMemorySize, SMG0);
    cudaFuncSetAttribute(k_gemm<1>,  cudaFuncAttributeMaxDynamicSharedMemorySize, SMG1);
    cudaFuncSetAttribute(k_conv_mma, cudaFuncAttributeMaxDynamicSharedMemorySize, SM3);

    k_consts  <<<32, 256>>>();
    k_wtrans  <<<640, 256>>>(wgt);
    k_gemm<0> <<<BATCH*CIN,  256, SMG0>>>(x, nullptr, nullptr);
    k_conv_mma<<<BATCH*HH,   256, SM3>>>();
    k_gemm<1> <<<BATCH*COUT, 256, SMG1>>>(nullptr, bias, out);
}

// round 12
// speedup vs baseline: 5.0508x; 1.0063x over previous
#include <cuda_runtime.h>
#include <cuda_bf16.h>
#include <math.h>

typedef unsigned int       u32;
typedef unsigned short     u16;
typedef unsigned long long u64;

#define BATCH 8
#define CIN   64
#define COUT  128
#define HH    128
#define WW    128

// ---------------- device globals (packed bf16 split planes; u32 = 2 bf16 along last dim) ----------------
__device__ u32 g_Dh[8192], g_Dl[8192];        // DCT matrix  [k][h/2]
__device__ u32 g_Mh[8192], g_Ml[8192];        // iDCT matrix [n][k/2]
__device__ float g_D5[640];                   // first 5 cols of D
__device__ u32 g_wdh[128*5*4096], g_wdl[128*5*4096];              // [k][j] tiles of [o][c/2] (128x32 u32)
__device__ u32 g_xdh[BATCH*CIN*HH*64],  g_xdl[BATCH*CIN*HH*64];   // [b][c][k][w/2]
__device__ u32 g_yh [BATCH*COUT*HH*64], g_yl [BATCH*COUT*HH*64];  // [b][o][k][w/2]

// ---------------- helpers ----------------
__device__ __forceinline__ u32 smem_u32(const void* p) {
    u32 a; asm("{ .reg .u64 t; cvta.to.shared.u64 t, %1; cvt.u32.u64 %0, t; }" : "=r"(a) : "l"(p));
    return a;
}
__device__ __forceinline__ void cp16(u32 dst, const void* src) {
    asm volatile("cp.async.cg.shared.global [%0], [%1], 16;" :: "r"(dst), "l"(src) : "memory");
}
#define CP_COMMIT() asm volatile("cp.async.commit_group;" ::: "memory")
#define CP_WAIT(n)  asm volatile("cp.async.wait_group %0;" :: "n"(n) : "memory")

__device__ __forceinline__ void ldsm_x4(u32& r0, u32& r1, u32& r2, u32& r3, u32 addr) {
    asm volatile("ldmatrix.sync.aligned.m8n8.x4.shared.b16 {%0,%1,%2,%3}, [%4];"
        : "=r"(r0), "=r"(r1), "=r"(r2), "=r"(r3) : "r"(addr) : "memory");
}
__device__ __forceinline__ void ldsm_x4t(u32& r0, u32& r1, u32& r2, u32& r3, u32 addr) {
    asm volatile("ldmatrix.sync.aligned.m8n8.x4.trans.shared.b16 {%0,%1,%2,%3}, [%4];"
        : "=r"(r0), "=r"(r1), "=r"(r2), "=r"(r3) : "r"(addr) : "memory");
}
__device__ __forceinline__ void mma_bf16(float* c, u32 a0, u32 a1, u32 a2, u32 a3, u32 b0, u32 b1) {
    asm volatile("mma.sync.aligned.m16n8k16.row.col.f32.bf16.bf16.f32 "
        "{%0,%1,%2,%3}, {%4,%5,%6,%7}, {%8,%9}, {%0,%1,%2,%3};"
        : "+f"(c[0]), "+f"(c[1]), "+f"(c[2]), "+f"(c[3])
        : "r"(a0), "r"(a1), "r"(a2), "r"(a3), "r"(b0), "r"(b1));
}
__device__ __forceinline__ void f2bf2(float v, u16& h, u16& l) {
    __nv_bfloat16 bh = __float2bfloat16(v);
    float fh = __bfloat162float(bh);
    __nv_bfloat16 bl = __float2bfloat16(v - fh);
    h = __bfloat16_as_ushort(bh);
    l = __bfloat16_as_ushort(bl);
}

// ---------------- constants ----------------
__global__ void k_consts() {
    int idx = blockIdx.x * blockDim.x + threadIdx.x;
    if (idx < 640) {
        int k = idx / 5, h = idx % 5;
        g_D5[idx] = (float)(2.0 * cos(M_PI * (2.0*h + 1.0) * k / 256.0));
    }
    if (idx >= 8192) return;
    int r = idx >> 6, cp = idx & 63;
    int c0 = 2*cp, c1 = 2*cp + 1;
    u16 h0, l0, h1, l1;
    float d0 = (float)(2.0 * cos(M_PI * (2.0*c0 + 1.0) * r / 256.0));
    float d1 = (float)(2.0 * cos(M_PI * (2.0*c1 + 1.0) * r / 256.0));
    f2bf2(d0, h0, l0); f2bf2(d1, h1, l1);
    g_Dh[idx] = (u32)h0 | ((u32)h1 << 16);
    g_Dl[idx] = (u32)l0 | ((u32)l1 << 16);
    float m0 = (float)(cos(M_PI * (2.0*r + 1.0) * c0 / 256.0) * ((c0 == 0) ? 0.5 : 1.0) / 256.0);
    float m1 = (float)(cos(M_PI * (2.0*r + 1.0) * c1 / 256.0) / 256.0);
    f2bf2(m0, h0, l0); f2bf2(m1, h1, l1);
    g_Mh[idx] = (u32)h0 | ((u32)h1 << 16);
    g_Ml[idx] = (u32)l0 | ((u32)l1 << 16);
}

// ---------------- weight transform: wd[k][j][o][c] = sum_h D[k,h]*W[o,c,h,j] ----------------
__global__ void k_wtrans(const float* __restrict__ wgt) {
    __shared__ float sw[5*64];
    int j = blockIdx.x >> 7, o = blockIdx.x & 127;
    int tid = threadIdx.x;
    for (int i = tid; i < 320; i += 256) {
        int h = i >> 6, c = i & 63;
        sw[h*64 + c] = wgt[((o*64 + c)*5 + h)*5 + j];
    }
    __syncthreads();
    for (int i = tid; i < 4096; i += 256) {
        int k = i >> 5, cp = i & 31;
        float a0 = 0.f, a1 = 0.f;
#pragma unroll
        for (int h = 0; h < 5; h++) {
            float d = g_D5[k*5 + h];
            a0 = fmaf(d, sw[h*64 + 2*cp],     a0);
            a1 = fmaf(d, sw[h*64 + 2*cp + 1], a1);
        }
        u16 h0, l0, h1, l1; f2bf2(a0, h0, l0); f2bf2(a1, h1, l1);
        u32 oi = (u32)(k*5 + j)*4096 + o*32 + cp;
        g_wdh[oi] = (u32)h0 | ((u32)h1 << 16);
        g_wdl[oi] = (u32)l0 | ((u32)l1 << 16);
    }
}

// ---------------- stage 1: 128x128x128 GEMM, K split into 4 chunks of 32, 2-stage pipeline ----
// A chunk tile: 128 rows x 32 k-bf16, stride 80B. B chunk: [32 k-rows][128 n], stride 272B.
// x fp32 cp.async'd to stage buf, per-thread converted; epilogue -> g_xd planes.
#define TSA4 80
#define TSB2 272
__global__ __launch_bounds__(256, 2)
void k_dct_mma(const float* __restrict__ xsrc) {
    extern __shared__ __align__(16) char sm[];
    u32 sb = smem_u32(sm);
    int tid = threadIdx.x, wid = tid >> 5, lane = tid & 31;

    int m0 = (wid >> 1) * 32, n0 = (wid & 1) * 64;
    int rowA = lane & 15;
    int kA = (lane & 16) ? 8 : 0;
    int rowK = lane & 15;
    int ntAdd = (lane & 16) ? 8 : 0;

    const char* xblk = (const char*)(xsrc + (size_t)blockIdx.x * 16384);

    auto load_chunk = [&](int c, int s) {
        u32 aBase = sb + s*20480;
        for (int i = tid; i < 1024; i += 256) {
            int p = i >> 9, ii = i & 511;
            int r = ii >> 2, ch = ii & 3;
            cp16(aBase + p*10240 + r*TSA4 + ch*16, (p ? g_Dl : g_Dh) + r*64 + c*16 + ch*4);
        }
        u32 xBase = sb + 75776 + s*16384;
        const char* src = xblk + (size_t)c * 16384;
        for (int i = tid; i < 1024; i += 256)
            cp16(xBase + i*16, src + i*16);
        CP_COMMIT();
    };
    auto convert_chunk = [&](int s) {
        const char* xBase = sm + 75776 + s*16384;
        char* dBh = sm + 40960 + s*17408;
        char* dBl = dBh + 8704;
        for (int i = tid; i < 1024; i += 256) {
            float4 v = *(const float4*)(xBase + i*16);
            int h = i >> 5, w4 = i & 31;
            u16 a0, b0, a1, b1, a2, b2, a3, b3;
            f2bf2(v.x, a0, b0); f2bf2(v.y, a1, b1);
            f2bf2(v.z, a2, b2); f2bf2(v.w, a3, b3);
            *(uint2*)(dBh + h*TSB2 + w4*8) = make_uint2((u32)a0 | ((u32)a1 << 16), (u32)a2 | ((u32)a3 << 16));
            *(uint2*)(dBl + h*TSB2 + w4*8) = make_uint2((u32)b0 | ((u32)b1 << 16), (u32)b2 | ((u32)b3 << 16));
        }
    };

    float acc[2][8][4];
#pragma unroll
    for (int mt = 0; mt < 2; mt++)
#pragma unroll
        for (int nt = 0; nt < 8; nt++)
#pragma unroll
            for (int q = 0; q < 4; q++) acc[mt][nt][q] = 0.f;

    load_chunk(0, 0);
    CP_WAIT(0);
    convert_chunk(0);
    __syncthreads();

#pragma unroll
    for (int c = 0; c < 4; c++) {
        int s = c & 1;
        if (c < 3) load_chunk(c + 1, 1 - s);
        u32 aBase = sb + s*20480;
        u32 bBase = sb + 40960 + s*17408;
#pragma unroll
        for (int ks = 0; ks < 2; ks++) {
            int k0 = ks * 16;
            u32 ah[2][4], al[2][4];
#pragma unroll
            for (int mt = 0; mt < 2; mt++) {
                u32 base = (u32)((m0 + mt*16 + rowA) * TSA4 + (k0 + kA) * 2);
                ldsm_x4(ah[mt][0], ah[mt][1], ah[mt][2], ah[mt][3], aBase + base);
                ldsm_x4(al[mt][0], al[mt][1], al[mt][2], al[mt][3], aBase + 10240 + base);
            }
            u32 rbase = (u32)((k0 + rowK) * TSB2);
#pragma unroll
            for (int nt = 0; nt < 8; nt += 2) {
                u32 off = rbase + (u32)((n0 + nt*8 + ntAdd) * 2);
                u32 bh[4], bl[4];
                ldsm_x4t(bh[0], bh[1], bh[2], bh[3], bBase + off);
                ldsm_x4t(bl[0], bl[1], bl[2], bl[3], bBase + 8704 + off);
#pragma unroll
                for (int q = 0; q < 2; q++)
#pragma unroll
                    for (int mt = 0; mt < 2; mt++) {
                        mma_bf16(acc[mt][nt + q], ah[mt][0], ah[mt][1], ah[mt][2], ah[mt][3], bh[2*q], bh[2*q + 1]);
                        mma_bf16(acc[mt][nt + q], ah[mt][0], ah[mt][1], ah[mt][2], ah[mt][3], bl[2*q], bl[2*q + 1]);
                        mma_bf16(acc[mt][nt + q], al[mt][0], al[mt][1], al[mt][2], al[mt][3], bh[2*q], bh[2*q + 1]);
                    }
            }
        }
        if (c < 3) {
            CP_WAIT(0);
            convert_chunk(1 - s);
            __syncthreads();
        }
    }

    // epilogue through fp32 staging, pack to split planes
    __syncthreads();
    float* se = (float*)(sm);   // [128][129]
#pragma unroll
    for (int mt = 0; mt < 2; mt++)
#pragma unroll
        for (int nt = 0; nt < 8; nt++) {
            int r = m0 + mt*16 + (lane >> 2);
            int c = n0 + nt*8 + 2*(lane & 3);
            se[r*129 + c]           = acc[mt][nt][0];
            se[r*129 + c + 1]       = acc[mt][nt][1];
            se[(r + 8)*129 + c]     = acc[mt][nt][2];
            se[(r + 8)*129 + c + 1] = acc[mt][nt][3];
        }
    __syncthreads();
    u32* oh = g_xdh + (size_t)blockIdx.x * 8192;
    u32* ol = g_xdl + (size_t)blockIdx.x * 8192;
    for (int i = tid; i < 8192; i += 256) {
        int r = i >> 6, np = i & 63;
        u16 h0, l0, h1, l1;
        f2bf2(se[r*129 + 2*np],     h0, l0);
        f2bf2(se[r*129 + 2*np + 1], h1, l1);
        oh[r*64 + np] = (u32)h0 | ((u32)h1 << 16);
        ol[r*64 + np] = (u32)l0 | ((u32)l1 << 16);
    }
}

// ---------------- stage 4: out[b,o] = M @ y[b,o] + bias. 2 slices/CTA, resident full A ----
// A: full 128x128 bf16 x2 planes at stride 272 (34816 each). B: 2 stages of [32 k][128 n] (17408 each).
// Continuous 8-chunk B pipeline; slice-0 epilogue overlaps chunk-4 prefetch. smem total 104448.
#define TSAF 272
__global__ __launch_bounds__(256, 2)
void k_idct_mma(const float* __restrict__ bias, float* __restrict__ outp) {
    extern __shared__ __align__(16) char sm[];
    const u32 OFF_AH = 0, OFF_AL = 34816, OFF_B = 69632;   // B stage s: OFF_B + s*17408 (+8704 lo)
    u32 sb = smem_u32(sm);
    int tid = threadIdx.x, wid = tid >> 5, lane = tid & 31;

    int m0 = (wid >> 1) * 32, n0 = (wid & 1) * 64;
    int rowA = lane & 15;
    int kA = (lane & 16) ? 8 : 0;
    int rowK = lane & 15;
    int ntAdd = (lane & 16) ? 8 : 0;

    size_t slice0 = (size_t)blockIdx.x * 2;

    // B chunk loader: cc in 0..7 -> slice cc>>2, k-chunk cc&3
    auto load_b = [&](int cc, int s) {
        const u32* yh = g_yh + (slice0 + (cc >> 2)) * 8192 + (size_t)(cc & 3) * 2048;
        const u32* yl = g_yl + (slice0 + (cc >> 2)) * 8192 + (size_t)(cc & 3) * 2048;
        u32 bBase = sb + OFF_B + s*17408;
        for (int i = tid; i < 1024; i += 256) {
            int p = i >> 9, ii = i & 511;
            int r = ii >> 4, ch = ii & 15;
            cp16(bBase + p*8704 + r*TSB2 + ch*16, (p ? yl : yh) + r*64 + ch*4);
        }
        CP_COMMIT();
    };

    // prologue: full A + B chunk 0
    for (int i = tid; i < 4096; i += 256) {
        int p = i >> 11, ii = i & 2047;
        int r = ii >> 4, ch = ii & 15;
        cp16(sb + (p ? OFF_AL : OFF_AH) + r*TSAF + ch*16, (p ? g_Ml : g_Mh) + r*64 + ch*4);
    }
    load_b(0, 0);
    CP_WAIT(0);
    __syncthreads();

    float acc[2][8][4];
#pragma unroll
    for (int mt = 0; mt < 2; mt++)
#pragma unroll
        for (int nt = 0; nt < 8; nt++)
#pragma unroll
            for (int q = 0; q < 4; q++) acc[mt][nt][q] = 0.f;

    float bv0 = bias[(slice0)     & 127];
    float bv1 = bias[(slice0 + 1) & 127];

#pragma unroll
    for (int cc = 0; cc < 8; cc++) {
        int s = cc & 1;
        if (cc < 7) load_b(cc + 1, 1 - s);
        u32 bBase = sb + OFF_B + s*17408;
        int kc = (cc & 3) * 32;
#pragma unroll
        for (int ks = 0; ks < 2; ks++) {
            int k0g = kc + ks * 16;       // global K for A
            int k0b = ks * 16;            // local K row in B chunk
            u32 ah[2][4], al[2][4];
#pragma unroll
            for (int mt = 0; mt < 2; mt++) {
                u32 base = (u32)((m0 + mt*16 + rowA) * TSAF + (k0g + kA) * 2);
                ldsm_x4(ah[mt][0], ah[mt][1], ah[mt][2], ah[mt][3], sb + OFF_AH + base);
                ldsm_x4(al[mt][0], al[mt][1], al[mt][2], al[mt][3], sb + OFF_AL + base);
            }
            u32 rbase = (u32)((k0b + rowK) * TSB2);
#pragma unroll
            for (int nt = 0; nt < 8; nt += 2) {
                u32 off = rbase + (u32)((n0 + nt*8 + ntAdd) * 2);
                u32 bh[4], bl[4];
                ldsm_x4t(bh[0], bh[1], bh[2], bh[3], bBase + off);
                ldsm_x4t(bl[0], bl[1], bl[2], bl[3], bBase + 8704 + off);
#pragma unroll
                for (int q = 0; q < 2; q++)
#pragma unroll
                    for (int mt = 0; mt < 2; mt++) {
                        mma_bf16(acc[mt][nt + q], ah[mt][0], ah[mt][1], ah[mt][2], ah[mt][3], bh[2*q], bh[2*q + 1]);
                        mma_bf16(acc[mt][nt + q], ah[mt][0], ah[mt][1], ah[mt][2], ah[mt][3], bl[2*q], bl[2*q + 1]);
                        mma_bf16(acc[mt][nt + q], al[mt][0], al[mt][1], al[mt][2], al[mt][3], bh[2*q], bh[2*q + 1]);
                    }
            }
        }
        if (cc == 3 || cc == 7) {
            // drain this slice's accumulators straight to gmem (overlaps in-flight prefetch)
            float bv = (cc == 3) ? bv0 : bv1;
            float* op = outp + (slice0 + (cc >> 2)) * 16384;
#pragma unroll
            for (int mt = 0; mt < 2; mt++)
#pragma unroll
                for (int nt = 0; nt < 8; nt++) {
                    int r = m0 + mt*16 + (lane >> 2);
                    int c = n0 + nt*8 + 2*(lane & 3);
                    float2 v0 = { acc[mt][nt][0] + bv, acc[mt][nt][1] + bv };
                    float2 v1 = { acc[mt][nt][2] + bv, acc[mt][nt][3] + bv };
                    *(float2*)(op + r*128 + c)       = v0;
                    *(float2*)(op + (r + 8)*128 + c) = v1;
                    acc[mt][nt][0] = 0.f; acc[mt][nt][1] = 0.f;
                    acc[mt][nt][2] = 0.f; acc[mt][nt][3] = 0.f;
                }
        }
        if (cc < 7) { CP_WAIT(0); __syncthreads(); }
    }
}

// ---------------- stage 3: per (b,k): y[o,w] = sum_{j,c} wd[k,j,o,c] * xd[b,c,k,(w-j)&127] ----------------
#define TS3 144
__global__ __launch_bounds__(256, 2)
void k_conv_mma() {
    extern __shared__ __align__(16) char sm[];
    const u32 OFF_BH = 0, OFF_BL = 18432, OFF_A0 = 36864, OFF_A1 = 73728;
    u32 sb = smem_u32(sm);
    int tid = threadIdx.x, wid = tid >> 5, lane = tid & 31;
    int blk = blockIdx.x, b = blk >> 7, k = blk & 127;

    for (int i = tid; i < 1024; i += 256) {
        int c = i >> 4, ch = i & 15;
        size_t gi = ((size_t)(b*64 + c)*128 + k)*64 + ch*4;
        cp16(sb + OFF_A1 +         i*16, g_xdh + gi);
        cp16(sb + OFF_A1 + 16384 + i*16, g_xdl + gi);
    }
    CP_COMMIT();
    {
        size_t wbase = (size_t)(k*5 + 0) * 4096;
        for (int i = tid; i < 1024; i += 256) {
            int o = i >> 3, ch = i & 7;
            cp16(sb + OFF_A0 +         o*TS3 + ch*16, g_wdh + wbase + o*32 + ch*4);
            cp16(sb + OFF_A0 + 18432 + o*TS3 + ch*16, g_wdl + wbase + o*32 + ch*4);
        }
        CP_COMMIT();
    }
    CP_WAIT(1);
    __syncthreads();
    {
        const u16* sh = (const u16*)(sm + OFF_A1);
        const u16* sl = (const u16*)(sm + OFF_A1 + 16384);
        u32* dBh = (u32*)(sm + OFF_BH);
        u32* dBl = (u32*)(sm + OFF_BL);
        for (int i = tid; i < 4096; i += 256) {
            int w = i & 127, cp = i >> 7;
            dBh[w*36 + cp] = (u32)sh[(2*cp)*128 + w] | ((u32)sh[(2*cp + 1)*128 + w] << 16);
            dBl[w*36 + cp] = (u32)sl[(2*cp)*128 + w] | ((u32)sl[(2*cp + 1)*128 + w] << 16);
        }
    }
    CP_WAIT(0);
    __syncthreads();

    int m0 = (wid >> 1) * 32, n0 = (wid & 1) * 64;
    int rowA = lane & 15;
    int kA = (lane & 16) ? 8 : 0;
    int rowB = lane & 7;
    int kB = (lane & 8) ? 8 : 0;
    int ntAdd = (lane & 16) ? 8 : 0;

    float acc[2][8][4];
#pragma unroll
    for (int mt = 0; mt < 2; mt++)
#pragma unroll
        for (int nt = 0; nt < 8; nt++)
#pragma unroll
            for (int q = 0; q < 4; q++) acc[mt][nt][q] = 0.f;

#pragma unroll
    for (int j = 0; j < 5; j++) {
        if (j < 4) {
            size_t wbase = (size_t)(k*5 + j + 1) * 4096;
            u32 dst = sb + (((j + 1) & 1) ? OFF_A1 : OFF_A0);
            for (int i = tid; i < 1024; i += 256) {
                int o = i >> 3, ch = i & 7;
                cp16(dst +         o*TS3 + ch*16, g_wdh + wbase + o*32 + ch*4);
                cp16(dst + 18432 + o*TS3 + ch*16, g_wdl + wbase + o*32 + ch*4);
            }
            CP_COMMIT();
        }
        u32 aBase = sb + ((j & 1) ? OFF_A1 : OFF_A0);
#pragma unroll
        for (int ks = 0; ks < 4; ks++) {
            int k0 = ks * 16;
            u32 ah[2][4], al[2][4];
#pragma unroll
            for (int mt = 0; mt < 2; mt++) {
                u32 base = (u32)((m0 + mt*16 + rowA) * TS3 + (k0 + kA) * 2);
                ldsm_x4(ah[mt][0], ah[mt][1], ah[mt][2], ah[mt][3], aBase + base);
                ldsm_x4(al[mt][0], al[mt][1], al[mt][2], al[mt][3], aBase + 18432 + base);
            }
#pragma unroll
            for (int nt = 0; nt < 8; nt += 2) {
                int wr = ((n0 + nt*8 + ntAdd + rowB) - j) & 127;
                u32 base = (u32)(wr * TS3 + (k0 + kB) * 2);
                u32 bh[4], bl[4];
                ldsm_x4(bh[0], bh[1], bh[2], bh[3], sb + OFF_BH + base);
                ldsm_x4(bl[0], bl[1], bl[2], bl[3], sb + OFF_BL + base);
#pragma unroll
                for (int q = 0; q < 2; q++)
#pragma unroll
                    for (int mt = 0; mt < 2; mt++) {
                        mma_bf16(acc[mt][nt + q], ah[mt][0], ah[mt][1], ah[mt][2], ah[mt][3], bh[2*q], bh[2*q + 1]);
                        mma_bf16(acc[mt][nt + q], ah[mt][0], ah[mt][1], ah[mt][2], ah[mt][3], bl[2*q], bl[2*q + 1]);
                        mma_bf16(acc[mt][nt + q], al[mt][0], al[mt][1], al[mt][2], al[mt][3], bh[2*q], bh[2*q + 1]);
                    }
            }
        }
        if (j < 4) { CP_WAIT(0); __syncthreads(); }
    }

    __syncthreads();
    float* se = (float*)(sm);   // [128][129]
#pragma unroll
    for (int mt = 0; mt < 2; mt++)
#pragma unroll
        for (int nt = 0; nt < 8; nt++) {
            int r = m0 + mt*16 + (lane >> 2);
            int c = n0 + nt*8 + 2*(lane & 3);
            se[r*129 + c]           = acc[mt][nt][0];
            se[r*129 + c + 1]       = acc[mt][nt][1];
            se[(r + 8)*129 + c]     = acc[mt][nt][2];
            se[(r + 8)*129 + c + 1] = acc[mt][nt][3];
        }
    __syncthreads();
    for (int i = tid; i < 8192; i += 256) {
        int o = i >> 6, wp = i & 63;
        u16 h0, l0, h1, l1;
        f2bf2(se[o*129 + 2*wp],     h0, l0);
        f2bf2(se[o*129 + 2*wp + 1], h1, l1);
        size_t gi = ((size_t)(b*128 + o))*8192 + (size_t)k*64 + wp;
        g_yh[gi] = (u32)h0 | ((u32)h1 << 16);
        g_yl[gi] = (u32)l0 | ((u32)l1 << 16);
    }
}

// ---------------- launch ----------------
extern "C" void kernel_launch(void* const* d_in, const int* in_sizes, int n_in,
                              void* d_out, int out_size) {
    const float* x    = (const float*)d_in[0];   // (8,64,128,128)
    const float* wgt  = (const float*)d_in[1];   // (128,64,5,5)
    const float* bias = (const float*)d_in[2];   // (128,)
    float* out = (float*)d_out;                  // (8,128,128,128)

    const int SMG0 = 108544;   // A 2x20480 + B 2x17408 + X 2x16384
    const int SMI  = 104448;   // A 2x34816 + B 2x17408
    const int SM3  = 110592;
    cudaFuncSetAttribute(k_dct_mma,  cudaFuncAttributeMaxDynamicSharedMemorySize, SMG0);
    cudaFuncSetAttribute(k_idct_mma, cudaFuncAttributeMaxDynamicSharedMemorySize, SMI);
    cudaFuncSetAttribute(k_conv_mma, cudaFuncAttributeMaxDynamicSharedMemorySize, SM3);

    k_consts  <<<32, 256>>>();
    k_wtrans  <<<640, 256>>>(wgt);
    k_dct_mma <<<BATCH*CIN,     256, SMG0>>>(x);
    k_conv_mma<<<BATCH*HH,      256, SM3>>>();
    k_idct_mma<<<BATCH*COUT/2,  256, SMI>>>(bias, out);
}

// round 13
// speedup vs baseline: 6.3217x; 1.2516x over previous
#include <cuda_runtime.h>
#include <cuda_fp16.h>
#include <math.h>

typedef unsigned int       u32;
typedef unsigned short     u16;
typedef unsigned long long u64;

#define BATCH 8
#define CIN   64
#define COUT  128
#define HH    128
#define WW    128

// ---------------- device globals ----------------
// A-operand constants: fp16 hi/lo planes (exact to ~2^-22). Scales: wd x64, M x256 (undone in epilogues).
__device__ u32 g_Dh[8192], g_Dl[8192];        // DCT matrix  [k][h/2]
__device__ u32 g_Mh[8192], g_Ml[8192];        // iDCT matrix x256 [n][k/2]
__device__ float g_D5[640];                   // first 5 cols of D (fp32, for wtrans)
__device__ u32 g_wdh[128*5*4096], g_wdl[128*5*4096];   // x64 [k][j] tiles of [o][c/2]
// B-operand data: single fp16 plane (u32 = 2 fp16 along last dim)
__device__ u32 g_xd16[BATCH*CIN*HH*64];       // [b][c][k][w/2]
__device__ u32 g_y16 [BATCH*COUT*HH*64];      // [b][o][k][w/2]

// ---------------- helpers ----------------
__device__ __forceinline__ u32 smem_u32(const void* p) {
    u32 a; asm("{ .reg .u64 t; cvta.to.shared.u64 t, %1; cvt.u32.u64 %0, t; }" : "=r"(a) : "l"(p));
    return a;
}
__device__ __forceinline__ void cp16(u32 dst, const void* src) {
    asm volatile("cp.async.cg.shared.global [%0], [%1], 16;" :: "r"(dst), "l"(src) : "memory");
}
#define CP_COMMIT() asm volatile("cp.async.commit_group;" ::: "memory")
#define CP_WAIT(n)  asm volatile("cp.async.wait_group %0;" :: "n"(n) : "memory")

__device__ __forceinline__ void ldsm_x4(u32& r0, u32& r1, u32& r2, u32& r3, u32 addr) {
    asm volatile("ldmatrix.sync.aligned.m8n8.x4.shared.b16 {%0,%1,%2,%3}, [%4];"
        : "=r"(r0), "=r"(r1), "=r"(r2), "=r"(r3) : "r"(addr) : "memory");
}
__device__ __forceinline__ void ldsm_x4t(u32& r0, u32& r1, u32& r2, u32& r3, u32 addr) {
    asm volatile("ldmatrix.sync.aligned.m8n8.x4.trans.shared.b16 {%0,%1,%2,%3}, [%4];"
        : "=r"(r0), "=r"(r1), "=r"(r2), "=r"(r3) : "r"(addr) : "memory");
}
__device__ __forceinline__ void mma_f16(float* c, u32 a0, u32 a1, u32 a2, u32 a3, u32 b0, u32 b1) {
    asm volatile("mma.sync.aligned.m16n8k16.row.col.f32.f16.f16.f32 "
        "{%0,%1,%2,%3}, {%4,%5,%6,%7}, {%8,%9}, {%0,%1,%2,%3};"
        : "+f"(c[0]), "+f"(c[1]), "+f"(c[2]), "+f"(c[3])
        : "r"(a0), "r"(a1), "r"(a2), "r"(a3), "r"(b0), "r"(b1));
}
__device__ __forceinline__ void f2h2(float v, u16& h, u16& l) {
    __half hh = __float2half_rn(v);
    float fh = __half2float(hh);
    __half ll = __float2half_rn(v - fh);
    h = __half_as_ushort(hh);
    l = __half_as_ushort(ll);
}
__device__ __forceinline__ u16 f2h(float v) { return __half_as_ushort(__float2half_rn(v)); }

// ---------------- constants ----------------
__global__ void k_consts() {
    int idx = blockIdx.x * blockDim.x + threadIdx.x;
    if (idx < 640) {
        int k = idx / 5, h = idx % 5;
        g_D5[idx] = (float)(2.0 * cos(M_PI * (2.0*h + 1.0) * k / 256.0));
    }
    if (idx >= 8192) return;
    int r = idx >> 6, cp = idx & 63;
    int c0 = 2*cp, c1 = 2*cp + 1;
    u16 h0, l0, h1, l1;
    float d0 = (float)(2.0 * cos(M_PI * (2.0*c0 + 1.0) * r / 256.0));
    float d1 = (float)(2.0 * cos(M_PI * (2.0*c1 + 1.0) * r / 256.0));
    f2h2(d0, h0, l0); f2h2(d1, h1, l1);
    g_Dh[idx] = (u32)h0 | ((u32)h1 << 16);
    g_Dl[idx] = (u32)l0 | ((u32)l1 << 16);
    // M stored x256: cos * w_k (range ~[-1,1])
    float m0 = (float)(cos(M_PI * (2.0*r + 1.0) * c0 / 256.0) * ((c0 == 0) ? 0.5 : 1.0));
    float m1 = (float)(cos(M_PI * (2.0*r + 1.0) * c1 / 256.0));
    f2h2(m0, h0, l0); f2h2(m1, h1, l1);
    g_Mh[idx] = (u32)h0 | ((u32)h1 << 16);
    g_Ml[idx] = (u32)l0 | ((u32)l1 << 16);
}

// ---------------- weight transform: wd[k][j][o][c] = 64 * sum_h D[k,h]*W[o,c,h,j] ----------------
__global__ void k_wtrans(const float* __restrict__ wgt) {
    __shared__ float sw[5*64];
    int j = blockIdx.x >> 7, o = blockIdx.x & 127;
    int tid = threadIdx.x;
    for (int i = tid; i < 320; i += 256) {
        int h = i >> 6, c = i & 63;
        sw[h*64 + c] = wgt[((o*64 + c)*5 + h)*5 + j];
    }
    __syncthreads();
    for (int i = tid; i < 4096; i += 256) {
        int k = i >> 5, cp = i & 31;
        float a0 = 0.f, a1 = 0.f;
#pragma unroll
        for (int h = 0; h < 5; h++) {
            float d = g_D5[k*5 + h];
            a0 = fmaf(d, sw[h*64 + 2*cp],     a0);
            a1 = fmaf(d, sw[h*64 + 2*cp + 1], a1);
        }
        u16 h0, l0, h1, l1;
        f2h2(64.f * a0, h0, l0);
        f2h2(64.f * a1, h1, l1);
        u32 oi = (u32)(k*5 + j)*4096 + o*32 + cp;
        g_wdh[oi] = (u32)h0 | ((u32)h1 << 16);
        g_wdl[oi] = (u32)l0 | ((u32)l1 << 16);
    }
}

// ---------------- stage 1: xd = D @ x. K=4 chunks of 32, 2-stage pipeline -------------
// A chunk: 128 rows x 32 k-fp16 x2 planes, stride 80. B chunk: [32 k][128 n] single fp16, stride 272.
#define TSA4 80
#define TSB2 272
__global__ __launch_bounds__(256, 2)
void k_dct_mma(const float* __restrict__ xsrc) {
    extern __shared__ __align__(16) char sm[];
    // A: s*20480 (+10240 lo). B: 40960 + s*8704. X: 58368 + s*16384. total 91136.
    u32 sb = smem_u32(sm);
    int tid = threadIdx.x, wid = tid >> 5, lane = tid & 31;

    int m0 = (wid >> 1) * 32, n0 = (wid & 1) * 64;
    int rowA = lane & 15;
    int kA = (lane & 16) ? 8 : 0;
    int rowK = lane & 15;
    int ntAdd = (lane & 16) ? 8 : 0;

    const char* xblk = (const char*)(xsrc + (size_t)blockIdx.x * 16384);

    auto load_chunk = [&](int c, int s) {
        u32 aBase = sb + s*20480;
        for (int i = tid; i < 1024; i += 256) {
            int p = i >> 9, ii = i & 511;
            int r = ii >> 2, ch = ii & 3;
            cp16(aBase + p*10240 + r*TSA4 + ch*16, (p ? g_Dl : g_Dh) + r*64 + c*16 + ch*4);
        }
        u32 xBase = sb + 58368 + s*16384;
        const char* src = xblk + (size_t)c * 16384;
        for (int i = tid; i < 1024; i += 256)
            cp16(xBase + i*16, src + i*16);
        CP_COMMIT();
    };
    auto convert_chunk = [&](int s) {
        const char* xBase = sm + 58368 + s*16384;
        char* dB = sm + 40960 + s*8704;
        for (int i = tid; i < 1024; i += 256) {
            float4 v = *(const float4*)(xBase + i*16);
            int h = i >> 5, w4 = i & 31;
            u32 p0 = (u32)f2h(v.x) | ((u32)f2h(v.y) << 16);
            u32 p1 = (u32)f2h(v.z) | ((u32)f2h(v.w) << 16);
            *(uint2*)(dB + h*TSB2 + w4*8) = make_uint2(p0, p1);
        }
    };

    float acc[2][8][4];
#pragma unroll
    for (int mt = 0; mt < 2; mt++)
#pragma unroll
        for (int nt = 0; nt < 8; nt++)
#pragma unroll
            for (int q = 0; q < 4; q++) acc[mt][nt][q] = 0.f;

    load_chunk(0, 0);
    CP_WAIT(0);
    convert_chunk(0);
    __syncthreads();

#pragma unroll
    for (int c = 0; c < 4; c++) {
        int s = c & 1;
        if (c < 3) load_chunk(c + 1, 1 - s);
        u32 aBase = sb + s*20480;
        u32 bBase = sb + 40960 + s*8704;
#pragma unroll
        for (int ks = 0; ks < 2; ks++) {
            int k0 = ks * 16;
            u32 ah[2][4], al[2][4];
#pragma unroll
            for (int mt = 0; mt < 2; mt++) {
                u32 base = (u32)((m0 + mt*16 + rowA) * TSA4 + (k0 + kA) * 2);
                ldsm_x4(ah[mt][0], ah[mt][1], ah[mt][2], ah[mt][3], aBase + base);
                ldsm_x4(al[mt][0], al[mt][1], al[mt][2], al[mt][3], aBase + 10240 + base);
            }
            u32 rbase = (u32)((k0 + rowK) * TSB2);
#pragma unroll
            for (int nt = 0; nt < 8; nt += 2) {
                u32 off = rbase + (u32)((n0 + nt*8 + ntAdd) * 2);
                u32 bf[4];
                ldsm_x4t(bf[0], bf[1], bf[2], bf[3], bBase + off);
#pragma unroll
                for (int q = 0; q < 2; q++)
#pragma unroll
                    for (int mt = 0; mt < 2; mt++) {
                        mma_f16(acc[mt][nt + q], ah[mt][0], ah[mt][1], ah[mt][2], ah[mt][3], bf[2*q], bf[2*q + 1]);
                        mma_f16(acc[mt][nt + q], al[mt][0], al[mt][1], al[mt][2], al[mt][3], bf[2*q], bf[2*q + 1]);
                    }
            }
        }
        if (c < 3) {
            CP_WAIT(0);
            convert_chunk(1 - s);
            __syncthreads();
        }
    }

    // epilogue through fp32 staging, pack to single fp16 plane
    __syncthreads();
    float* se = (float*)(sm);   // [128][129] = 66048 <= 91136
#pragma unroll
    for (int mt = 0; mt < 2; mt++)
#pragma unroll
        for (int nt = 0; nt < 8; nt++) {
            int r = m0 + mt*16 + (lane >> 2);
            int c = n0 + nt*8 + 2*(lane & 3);
            se[r*129 + c]           = acc[mt][nt][0];
            se[r*129 + c + 1]       = acc[mt][nt][1];
            se[(r + 8)*129 + c]     = acc[mt][nt][2];
            se[(r + 8)*129 + c + 1] = acc[mt][nt][3];
        }
    __syncthreads();
    u32* od = g_xd16 + (size_t)blockIdx.x * 8192;
    for (int i = tid; i < 8192; i += 256) {
        int r = i >> 6, np = i & 63;
        od[r*64 + np] = (u32)f2h(se[r*129 + 2*np]) | ((u32)f2h(se[r*129 + 2*np + 1]) << 16);
    }
}

// ---------------- stage 4: out[b,o] = (M256 @ y)/256 + bias. 2 slices/CTA, resident full A ----
#define TSAF 272
__global__ __launch_bounds__(256, 2)
void k_idct_mma(const float* __restrict__ bias, float* __restrict__ outp) {
    extern __shared__ __align__(16) char sm[];
    const u32 OFF_AH = 0, OFF_AL = 34816, OFF_B = 69632;   // B stage s: +s*8704. total 87040.
    u32 sb = smem_u32(sm);
    int tid = threadIdx.x, wid = tid >> 5, lane = tid & 31;

    int m0 = (wid >> 1) * 32, n0 = (wid & 1) * 64;
    int rowA = lane & 15;
    int kA = (lane & 16) ? 8 : 0;
    int rowK = lane & 15;
    int ntAdd = (lane & 16) ? 8 : 0;

    size_t slice0 = (size_t)blockIdx.x * 2;

    auto load_b = [&](int cc, int s) {
        const u32* ys = g_y16 + (slice0 + (cc >> 2)) * 8192 + (size_t)(cc & 3) * 2048;
        u32 bBase = sb + OFF_B + s*8704;
        for (int i = tid; i < 512; i += 256) {
            int r = i >> 4, ch = i & 15;
            cp16(bBase + r*TSB2 + ch*16, ys + r*64 + ch*4);
        }
        CP_COMMIT();
    };

    // prologue: full A + B chunk 0
    for (int i = tid; i < 4096; i += 256) {
        int p = i >> 11, ii = i & 2047;
        int r = ii >> 4, ch = ii & 15;
        cp16(sb + (p ? OFF_AL : OFF_AH) + r*TSAF + ch*16, (p ? g_Ml : g_Mh) + r*64 + ch*4);
    }
    load_b(0, 0);
    CP_WAIT(0);
    __syncthreads();

    float acc[2][8][4];
#pragma unroll
    for (int mt = 0; mt < 2; mt++)
#pragma unroll
        for (int nt = 0; nt < 8; nt++)
#pragma unroll
            for (int q = 0; q < 4; q++) acc[mt][nt][q] = 0.f;

    float bv0 = bias[(slice0)     & 127];
    float bv1 = bias[(slice0 + 1) & 127];

#pragma unroll
    for (int cc = 0; cc < 8; cc++) {
        int s = cc & 1;
        if (cc < 7) load_b(cc + 1, 1 - s);
        u32 bBase = sb + OFF_B + s*8704;
        int kc = (cc & 3) * 32;
#pragma unroll
        for (int ks = 0; ks < 2; ks++) {
            int k0g = kc + ks * 16;
            int k0b = ks * 16;
            u32 ah[2][4], al[2][4];
#pragma unroll
            for (int mt = 0; mt < 2; mt++) {
                u32 base = (u32)((m0 + mt*16 + rowA) * TSAF + (k0g + kA) * 2);
                ldsm_x4(ah[mt][0], ah[mt][1], ah[mt][2], ah[mt][3], sb + OFF_AH + base);
                ldsm_x4(al[mt][0], al[mt][1], al[mt][2], al[mt][3], sb + OFF_AL + base);
            }
            u32 rbase = (u32)((k0b + rowK) * TSB2);
#pragma unroll
            for (int nt = 0; nt < 8; nt += 2) {
                u32 off = rbase + (u32)((n0 + nt*8 + ntAdd) * 2);
                u32 bf[4];
                ldsm_x4t(bf[0], bf[1], bf[2], bf[3], bBase + off);
#pragma unroll
                for (int q = 0; q < 2; q++)
#pragma unroll
                    for (int mt = 0; mt < 2; mt++) {
                        mma_f16(acc[mt][nt + q], ah[mt][0], ah[mt][1], ah[mt][2], ah[mt][3], bf[2*q], bf[2*q + 1]);
                        mma_f16(acc[mt][nt + q], al[mt][0], al[mt][1], al[mt][2], al[mt][3], bf[2*q], bf[2*q + 1]);
                    }
            }
        }
        if (cc == 3 || cc == 7) {
            float bv = (cc == 3) ? bv0 : bv1;
            const float is = 1.f / 256.f;
            float* op = outp + (slice0 + (cc >> 2)) * 16384;
#pragma unroll
            for (int mt = 0; mt < 2; mt++)
#pragma unroll
                for (int nt = 0; nt < 8; nt++) {
                    int r = m0 + mt*16 + (lane >> 2);
                    int c = n0 + nt*8 + 2*(lane & 3);
                    float2 v0 = { acc[mt][nt][0]*is + bv, acc[mt][nt][1]*is + bv };
                    float2 v1 = { acc[mt][nt][2]*is + bv, acc[mt][nt][3]*is + bv };
                    *(float2*)(op + r*128 + c)       = v0;
                    *(float2*)(op + (r + 8)*128 + c) = v1;
                    acc[mt][nt][0] = 0.f; acc[mt][nt][1] = 0.f;
                    acc[mt][nt][2] = 0.f; acc[mt][nt][3] = 0.f;
                }
        }
        if (cc < 7) { CP_WAIT(0); __syncthreads(); }
    }
}

// ---------------- stage 3: per (b,k): y = (wd64 conv xd)/64 -------------------------
// B single plane [w][c] stride 144; A hi/lo double-buffered.
#define TS3 144
__global__ __launch_bounds__(256, 2)
void k_conv_mma() {
    extern __shared__ __align__(16) char sm[];
    const u32 OFF_B = 0, OFF_A0 = 18432, OFF_A1 = 55296;   // A buf: hi +0, lo +18432. total 92160.
    u32 sb = smem_u32(sm);
    int tid = threadIdx.x, wid = tid >> 5, lane = tid & 31;
    int blk = blockIdx.x, b = blk >> 7, k = blk & 127;

    // 1. cp.async X slice (single plane, 16 KB) into A1 region
    for (int i = tid; i < 1024; i += 256) {
        int c = i >> 4, ch = i & 15;
        size_t gi = ((size_t)(b*64 + c)*128 + k)*64 + ch*4;
        cp16(sb + OFF_A1 + i*16, g_xd16 + gi);
    }
    CP_COMMIT();
    // 2. cp.async A_0 (2 planes) into buf0
    {
        size_t wbase = (size_t)(k*5 + 0) * 4096;
        for (int i = tid; i < 1024; i += 256) {
            int o = i >> 3, ch = i & 7;
            cp16(sb + OFF_A0 +         o*TS3 + ch*16, g_wdh + wbase + o*32 + ch*4);
            cp16(sb + OFF_A0 + 18432 + o*TS3 + ch*16, g_wdl + wbase + o*32 + ch*4);
        }
        CP_COMMIT();
    }
    CP_WAIT(1);
    __syncthreads();
    // 3. build B[w][c] once from X
    {
        const u16* sh = (const u16*)(sm + OFF_A1);
        u32* dB = (u32*)(sm + OFF_B);
        for (int i = tid; i < 4096; i += 256) {
            int w = i & 127, cp = i >> 7;
            dB[w*36 + cp] = (u32)sh[(2*cp)*128 + w] | ((u32)sh[(2*cp + 1)*128 + w] << 16);
        }
    }
    CP_WAIT(0);
    __syncthreads();

    int m0 = (wid >> 1) * 32, n0 = (wid & 1) * 64;
    int rowA = lane & 15;
    int kA = (lane & 16) ? 8 : 0;
    int rowB = lane & 7;
    int kB = (lane & 8) ? 8 : 0;
    int ntAdd = (lane & 16) ? 8 : 0;

    float acc[2][8][4];
#pragma unroll
    for (int mt = 0; mt < 2; mt++)
#pragma unroll
        for (int nt = 0; nt < 8; nt++)
#pragma unroll
            for (int q = 0; q < 4; q++) acc[mt][nt][q] = 0.f;

#pragma unroll
    for (int j = 0; j < 5; j++) {
        if (j < 4) {
            size_t wbase = (size_t)(k*5 + j + 1) * 4096;
            u32 dst = sb + (((j + 1) & 1) ? OFF_A1 : OFF_A0);
            for (int i = tid; i < 1024; i += 256) {
                int o = i >> 3, ch = i & 7;
                cp16(dst +         o*TS3 + ch*16, g_wdh + wbase + o*32 + ch*4);
                cp16(dst + 18432 + o*TS3 + ch*16, g_wdl + wbase + o*32 + ch*4);
            }
            CP_COMMIT();
        }
        u32 aBase = sb + ((j & 1) ? OFF_A1 : OFF_A0);
#pragma unroll
        for (int ks = 0; ks < 4; ks++) {
            int k0 = ks * 16;
            u32 ah[2][4], al[2][4];
#pragma unroll
            for (int mt = 0; mt < 2; mt++) {
                u32 base = (u32)((m0 + mt*16 + rowA) * TS3 + (k0 + kA) * 2);
                ldsm_x4(ah[mt][0], ah[mt][1], ah[mt][2], ah[mt][3], aBase + base);
                ldsm_x4(al[mt][0], al[mt][1], al[mt][2], al[mt][3], aBase + 18432 + base);
            }
#pragma unroll
            for (int nt = 0; nt < 8; nt += 2) {
                int wr = ((n0 + nt*8 + ntAdd + rowB) - j) & 127;
                u32 base = (u32)(wr * TS3 + (k0 + kB) * 2);
                u32 bf[4];
                ldsm_x4(bf[0], bf[1], bf[2], bf[3], sb + OFF_B + base);
#pragma unroll
                for (int q = 0; q < 2; q++)
#pragma unroll
                    for (int mt = 0; mt < 2; mt++) {
                        mma_f16(acc[mt][nt + q], ah[mt][0], ah[mt][1], ah[mt][2], ah[mt][3], bf[2*q], bf[2*q + 1]);
                        mma_f16(acc[mt][nt + q], al[mt][0], al[mt][1], al[mt][2], al[mt][3], bf[2*q], bf[2*q + 1]);
                    }
            }
        }
        if (j < 4) { CP_WAIT(0); __syncthreads(); }
    }

    // epilogue through fp32 staging; store y = acc/64 as single fp16 plane
    __syncthreads();
    float* se = (float*)(sm);   // [128][129] = 66048 <= 92160
#pragma unroll
    for (int mt = 0; mt < 2; mt++)
#pragma unroll
        for (int nt = 0; nt < 8; nt++) {
            int r = m0 + mt*16 + (lane >> 2);
            int c = n0 + nt*8 + 2*(lane & 3);
            se[r*129 + c]           = acc[mt][nt][0];
            se[r*129 + c + 1]       = acc[mt][nt][1];
            se[(r + 8)*129 + c]     = acc[mt][nt][2];
            se[(r + 8)*129 + c + 1] = acc[mt][nt][3];
        }
    __syncthreads();
    const float is = 1.f / 64.f;
    for (int i = tid; i < 8192; i += 256) {
        int o = i >> 6, wp = i & 63;
        size_t gi = ((size_t)(b*128 + o))*8192 + (size_t)k*64 + wp;
        g_y16[gi] = (u32)f2h(se[o*129 + 2*wp] * is) | ((u32)f2h(se[o*129 + 2*wp + 1] * is) << 16);
    }
}

// ---------------- launch ----------------
extern "C" void kernel_launch(void* const* d_in, const int* in_sizes, int n_in,
                              void* d_out, int out_size) {
    const float* x    = (const float*)d_in[0];   // (8,64,128,128)
    const float* wgt  = (const float*)d_in[1];   // (128,64,5,5)
    const float* bias = (const float*)d_in[2];   // (128,)
    float* out = (float*)d_out;                  // (8,128,128,128)

    const int SMD = 91136;    // A 2x20480 + B 2x8704 + X 2x16384
    const int SMI = 87040;    // A 2x34816 + B 2x8704
    const int SM3 = 92160;    // B 18432 + A 2x36864
    cudaFuncSetAttribute(k_dct_mma,  cudaFuncAttributeMaxDynamicSharedMemorySize, SMD);
    cudaFuncSetAttribute(k_idct_mma, cudaFuncAttributeMaxDynamicSharedMemorySize, SMI);
    cudaFuncSetAttribute(k_conv_mma, cudaFuncAttributeMaxDynamicSharedMemorySize, SM3);

    k_consts  <<<32, 256>>>();
    k_wtrans  <<<640, 256>>>(wgt);
    k_dct_mma <<<BATCH*CIN,     256, SMD>>>(x);
    k_conv_mma<<<BATCH*HH,      256, SM3>>>();
    k_idct_mma<<<BATCH*COUT/2,  256, SMI>>>(bias, out);
}

// round 15
// speedup vs baseline: 6.5291x; 1.0328x over previous
#include <cuda_runtime.h>
#include <cuda_fp16.h>
#include <math.h>

typedef unsigned int       u32;
typedef unsigned short     u16;
typedef unsigned long long u64;

#define BATCH 8
#define CIN   64
#define COUT  128
#define HH    128
#define WW    128

// ---------------- device globals ----------------
// Even/odd split constant matrices, fp16 hi/lo planes, packed [row][col/2] u32 (64x32).
__device__ u32 g_Deh[2048], g_Del[2048];   // De[k'][h'] = D[2k'][h']
__device__ u32 g_Doh[2048], g_Dol[2048];   // Do[k'][h'] = D[2k'+1][h']
__device__ u32 g_Meh[2048], g_Mel[2048];   // Me[n'][k'] = 256*M[n'][2k']
__device__ u32 g_Moh[2048], g_Mol[2048];   // Mo[n'][k'] = 256*M[n'][2k'+1]
__device__ float g_D5[640];                // first 5 cols of D (fp32, for wtrans)
__device__ u32 g_wdh[128*5*4096], g_wdl[128*5*4096];   // x64 [k][j] tiles of [o][c/2]
__device__ u32 g_xd16[BATCH*CIN*HH*64];    // [b][c][k][w/2] single fp16 plane
__device__ u32 g_y16 [BATCH*COUT*HH*64];   // [b][o][k][w/2]

// ---------------- helpers ----------------
__device__ __forceinline__ u32 smem_u32(const void* p) {
    u32 a; asm("{ .reg .u64 t; cvta.to.shared.u64 t, %1; cvt.u32.u64 %0, t; }" : "=r"(a) : "l"(p));
    return a;
}
__device__ __forceinline__ void cp16(u32 dst, const void* src) {
    asm volatile("cp.async.cg.shared.global [%0], [%1], 16;" :: "r"(dst), "l"(src) : "memory");
}
#define CP_COMMIT() asm volatile("cp.async.commit_group;" ::: "memory")
#define CP_WAIT(n)  asm volatile("cp.async.wait_group %0;" :: "n"(n) : "memory")

__device__ __forceinline__ void ldsm_x4(u32& r0, u32& r1, u32& r2, u32& r3, u32 addr) {
    asm volatile("ldmatrix.sync.aligned.m8n8.x4.shared.b16 {%0,%1,%2,%3}, [%4];"
        : "=r"(r0), "=r"(r1), "=r"(r2), "=r"(r3) : "r"(addr) : "memory");
}
__device__ __forceinline__ void ldsm_x4t(u32& r0, u32& r1, u32& r2, u32& r3, u32 addr) {
    asm volatile("ldmatrix.sync.aligned.m8n8.x4.trans.shared.b16 {%0,%1,%2,%3}, [%4];"
        : "=r"(r0), "=r"(r1), "=r"(r2), "=r"(r3) : "r"(addr) : "memory");
}
__device__ __forceinline__ void mma_f16(float* c, const u32* a, u32 b0, u32 b1) {
    asm volatile("mma.sync.aligned.m16n8k16.row.col.f32.f16.f16.f32 "
        "{%0,%1,%2,%3}, {%4,%5,%6,%7}, {%8,%9}, {%0,%1,%2,%3};"
        : "+f"(c[0]), "+f"(c[1]), "+f"(c[2]), "+f"(c[3])
        : "r"(a[0]), "r"(a[1]), "r"(a[2]), "r"(a[3]), "r"(b0), "r"(b1));
}
__device__ __forceinline__ void f2h2(float v, u16& h, u16& l) {
    __half hh = __float2half_rn(v);
    float fh = __half2float(hh);
    __half ll = __float2half_rn(v - fh);
    h = __half_as_ushort(hh);
    l = __half_as_ushort(ll);
}
__device__ __forceinline__ u16 f2h(float v) { return __half_as_ushort(__float2half_rn(v)); }

// ---------------- constants ----------------
__global__ void k_consts() {
    int idx = blockIdx.x * blockDim.x + threadIdx.x;
    if (idx < 640) {
        int k = idx / 5, h = idx % 5;
        g_D5[idx] = (float)(2.0 * cos(M_PI * (2.0*h + 1.0) * k / 256.0));
    }
    if (idx >= 2048) return;
    int r = idx >> 5, cp = idx & 31;
    int c0 = 2*cp, c1 = 2*cp + 1;
    u16 h0, l0, h1, l1;
    // De[r][c] = 2cos(pi*(2c+1)*(2r)/256); Do[r][c] = 2cos(pi*(2c+1)*(2r+1)/256)
    float de0 = (float)(2.0 * cos(M_PI * (2.0*c0 + 1.0) * (2.0*r) / 256.0));
    float de1 = (float)(2.0 * cos(M_PI * (2.0*c1 + 1.0) * (2.0*r) / 256.0));
    f2h2(de0, h0, l0); f2h2(de1, h1, l1);
    g_Deh[idx] = (u32)h0 | ((u32)h1 << 16);
    g_Del[idx] = (u32)l0 | ((u32)l1 << 16);
    float do0 = (float)(2.0 * cos(M_PI * (2.0*c0 + 1.0) * (2.0*r + 1.0) / 256.0));
    float do1 = (float)(2.0 * cos(M_PI * (2.0*c1 + 1.0) * (2.0*r + 1.0) / 256.0));
    f2h2(do0, h0, l0); f2h2(do1, h1, l1);
    g_Doh[idx] = (u32)h0 | ((u32)h1 << 16);
    g_Dol[idx] = (u32)l0 | ((u32)l1 << 16);
    // Me[r][c] = cos(pi*(2r+1)*(2c)/256)*w_{2c} (w_0=0.5); Mo[r][c] = cos(pi*(2r+1)*(2c+1)/256)
    float me0 = (float)(cos(M_PI * (2.0*r + 1.0) * (2.0*c0) / 256.0) * ((c0 == 0) ? 0.5 : 1.0));
    float me1 = (float)(cos(M_PI * (2.0*r + 1.0) * (2.0*c1) / 256.0));
    f2h2(me0, h0, l0); f2h2(me1, h1, l1);
    g_Meh[idx] = (u32)h0 | ((u32)h1 << 16);
    g_Mel[idx] = (u32)l0 | ((u32)l1 << 16);
    float mo0 = (float)(cos(M_PI * (2.0*r + 1.0) * (2.0*c0 + 1.0) / 256.0));
    float mo1 = (float)(cos(M_PI * (2.0*r + 1.0) * (2.0*c1 + 1.0) / 256.0));
    f2h2(mo0, h0, l0); f2h2(mo1, h1, l1);
    g_Moh[idx] = (u32)h0 | ((u32)h1 << 16);
    g_Mol[idx] = (u32)l0 | ((u32)l1 << 16);
}

// ---------------- weight transform: wd[k][j][o][c] = 64 * sum_h D[k,h]*W[o,c,h,j] ----------------
__global__ void k_wtrans(const float* __restrict__ wgt) {
    __shared__ float sw[5*64];
    int j = blockIdx.x >> 7, o = blockIdx.x & 127;
    int tid = threadIdx.x;
    for (int i = tid; i < 320; i += 256) {
        int h = i >> 6, c = i & 63;
        sw[h*64 + c] = wgt[((o*64 + c)*5 + h)*5 + j];
    }
    __syncthreads();
    for (int i = tid; i < 4096; i += 256) {
        int k = i >> 5, cp = i & 31;
        float a0 = 0.f, a1 = 0.f;
#pragma unroll
        for (int h = 0; h < 5; h++) {
            float d = g_D5[k*5 + h];
            a0 = fmaf(d, sw[h*64 + 2*cp],     a0);
            a1 = fmaf(d, sw[h*64 + 2*cp + 1], a1);
        }
        u16 h0, l0, h1, l1;
        f2h2(64.f * a0, h0, l0);
        f2h2(64.f * a1, h1, l1);
        u32 oi = (u32)(k*5 + j)*4096 + o*32 + cp;
        g_wdh[oi] = (u32)h0 | ((u32)h1 << 16);
        g_wdl[oi] = (u32)l0 | ((u32)l1 << 16);
    }
}

// ---------------- stage 1 (DCT, even/odd): two 64x128x64 GEMMs per slice ----------------
// A planes: De_h/De_l/Do_h/Do_l, 64 rows x 64 fp16, stride 144 (9216 B each).
// B tiles: Bs (x[h]+x[127-h]) and Bd (difference), 64 rows x 128 fp16, stride 272 (17408 B each).
#define TSA6 144
#define TSB2 272
__global__ __launch_bounds__(256, 2)
void k_dct_mma(const float* __restrict__ xsrc) {
    extern __shared__ __align__(16) char sm[];
    const u32 OFF_BS = 36864, OFF_BD = 54272;   // total 71680
    u32 sb = smem_u32(sm);
    int tid = threadIdx.x, wid = tid >> 5, lane = tid & 31;

    int m0 = (wid >> 1) * 16, n0 = (wid & 1) * 64;
    int rowA = lane & 15;
    int kA = (lane & 16) ? 8 : 0;
    int rowK = lane & 15;
    int ntAdd = (lane & 16) ? 8 : 0;

    // A planes via cp.async
    for (int i = tid; i < 2048; i += 256) {
        int p = i >> 9, ii = i & 511;
        int r = ii >> 3, ch = ii & 7;
        const u32* src = (p == 0) ? g_Deh : (p == 1) ? g_Del : (p == 2) ? g_Doh : g_Dol;
        cp16(sb + p*9216 + r*TSA6 + ch*16, src + r*32 + ch*4);
    }
    CP_COMMIT();
    // B build: direct LDG of x rows h and 127-h, sum/diff in fp32, convert fp16
    const float* xb = xsrc + (size_t)blockIdx.x * 16384;
    for (int i = tid; i < 2048; i += 256) {
        int h = i >> 5, w4 = i & 31;
        float4 a = ((const float4*)(xb + h*128))[w4];
        float4 b = ((const float4*)(xb + (127 - h)*128))[w4];
        u32 s0 = (u32)f2h(a.x + b.x) | ((u32)f2h(a.y + b.y) << 16);
        u32 s1 = (u32)f2h(a.z + b.z) | ((u32)f2h(a.w + b.w) << 16);
        u32 d0 = (u32)f2h(a.x - b.x) | ((u32)f2h(a.y - b.y) << 16);
        u32 d1 = (u32)f2h(a.z - b.z) | ((u32)f2h(a.w - b.w) << 16);
        *(uint2*)(sm + OFF_BS + h*TSB2 + w4*8) = make_uint2(s0, s1);
        *(uint2*)(sm + OFF_BD + h*TSB2 + w4*8) = make_uint2(d0, d1);
    }
    CP_WAIT(0);
    __syncthreads();

    float accE[8][4], accO[8][4];
#pragma unroll
    for (int nt = 0; nt < 8; nt++)
#pragma unroll
        for (int q = 0; q < 4; q++) { accE[nt][q] = 0.f; accO[nt][q] = 0.f; }

#pragma unroll
    for (int ks = 0; ks < 4; ks++) {
        int k0 = ks * 16;
        u32 aeh[4], ael[4], aoh[4], aol[4];
        u32 base = (u32)((m0 + rowA) * TSA6 + (k0 + kA) * 2);
        ldsm_x4(aeh[0], aeh[1], aeh[2], aeh[3], sb + 0     + base);
        ldsm_x4(ael[0], ael[1], ael[2], ael[3], sb + 9216  + base);
        ldsm_x4(aoh[0], aoh[1], aoh[2], aoh[3], sb + 18432 + base);
        ldsm_x4(aol[0], aol[1], aol[2], aol[3], sb + 27648 + base);
        u32 rbase = (u32)((k0 + rowK) * TSB2);
#pragma unroll
        for (int nt = 0; nt < 8; nt += 2) {
            u32 off = rbase + (u32)((n0 + nt*8 + ntAdd) * 2);
            u32 bs[4], bd[4];
            ldsm_x4t(bs[0], bs[1], bs[2], bs[3], sb + OFF_BS + off);
            ldsm_x4t(bd[0], bd[1], bd[2], bd[3], sb + OFF_BD + off);
#pragma unroll
            for (int q = 0; q < 2; q++) {
                mma_f16(accE[nt + q], aeh, bs[2*q], bs[2*q + 1]);
                mma_f16(accE[nt + q], ael, bs[2*q], bs[2*q + 1]);
                mma_f16(accO[nt + q], aoh, bd[2*q], bd[2*q + 1]);
                mma_f16(accO[nt + q], aol, bd[2*q], bd[2*q + 1]);
            }
        }
    }

    // epilogue: direct packed stores. E -> even k rows, O -> odd k rows.
    u32* od = g_xd16 + (size_t)blockIdx.x * 8192;
    int r = m0 + (lane >> 2);
#pragma unroll
    for (int nt = 0; nt < 8; nt++) {
        int c2 = (n0 + nt*8)/2 + (lane & 3);
        od[(2*r)*64      + c2] = (u32)f2h(accE[nt][0]) | ((u32)f2h(accE[nt][1]) << 16);
        od[(2*r + 1)*64  + c2] = (u32)f2h(accO[nt][0]) | ((u32)f2h(accO[nt][1]) << 16);
        od[(2*r + 16)*64 + c2] = (u32)f2h(accE[nt][2]) | ((u32)f2h(accE[nt][3]) << 16);
        od[(2*r + 17)*64 + c2] = (u32)f2h(accO[nt][2]) | ((u32)f2h(accO[nt][3]) << 16);
    }
}

// ---------------- stage 4 (iDCT, even/odd): E/O butterfly, 2 slices/CTA ----------------
// A planes: Me_h/Me_l/Mo_h/Mo_l 64x64 fp16 stride 144. B stage s: y_even / y_odd tiles (64x272 each).
__global__ __launch_bounds__(256, 2)
void k_idct_mma(const float* __restrict__ bias, float* __restrict__ outp) {
    extern __shared__ __align__(16) char sm[];
    const u32 OFF_B = 36864;   // stage s: OFF_B + s*34816; even +0, odd +17408. total 106496.
    u32 sb = smem_u32(sm);
    int tid = threadIdx.x, wid = tid >> 5, lane = tid & 31;

    int m0 = (wid >> 1) * 16, n0 = (wid & 1) * 64;
    int rowA = lane & 15;
    int kA = (lane & 16) ? 8 : 0;
    int rowK = lane & 15;
    int ntAdd = (lane & 16) ? 8 : 0;

    size_t slice0 = (size_t)blockIdx.x * 2;

    auto load_b = [&](int sl, int s) {
        const u32* ys = g_y16 + (slice0 + sl) * 8192;
        u32 bBase = sb + OFF_B + s*34816;
        for (int i = tid; i < 2048; i += 256) {
            int t = i >> 10, ii = i & 1023;
            int r = ii >> 4, ch = ii & 15;
            cp16(bBase + t*17408 + r*TSB2 + ch*16, ys + (size_t)(2*r + t)*64 + ch*4);
        }
        CP_COMMIT();
    };

    // A planes
    for (int i = tid; i < 2048; i += 256) {
        int p = i >> 9, ii = i & 511;
        int r = ii >> 3, ch = ii & 7;
        const u32* src = (p == 0) ? g_Meh : (p == 1) ? g_Mel : (p == 2) ? g_Moh : g_Mol;
        cp16(sb + p*9216 + r*TSA6 + ch*16, src + r*32 + ch*4);
    }
    CP_COMMIT();
    load_b(0, 0);
    CP_WAIT(0);
    __syncthreads();
    load_b(1, 1);

#pragma unroll
    for (int sl = 0; sl < 2; sl++) {
        u32 bBase = sb + OFF_B + sl*34816;
        float accE[8][4], accO[8][4];
#pragma unroll
        for (int nt = 0; nt < 8; nt++)
#pragma unroll
            for (int q = 0; q < 4; q++) { accE[nt][q] = 0.f; accO[nt][q] = 0.f; }

#pragma unroll
        for (int ks = 0; ks < 4; ks++) {
            int k0 = ks * 16;
            u32 aeh[4], ael[4], aoh[4], aol[4];
            u32 base = (u32)((m0 + rowA) * TSA6 + (k0 + kA) * 2);
            ldsm_x4(aeh[0], aeh[1], aeh[2], aeh[3], sb + 0     + base);
            ldsm_x4(ael[0], ael[1], ael[2], ael[3], sb + 9216  + base);
            ldsm_x4(aoh[0], aoh[1], aoh[2], aoh[3], sb + 18432 + base);
            ldsm_x4(aol[0], aol[1], aol[2], aol[3], sb + 27648 + base);
            u32 rbase = (u32)((k0 + rowK) * TSB2);
#pragma unroll
            for (int nt = 0; nt < 8; nt += 2) {
                u32 off = rbase + (u32)((n0 + nt*8 + ntAdd) * 2);
                u32 be[4], bo[4];
                ldsm_x4t(be[0], be[1], be[2], be[3], bBase + off);
                ldsm_x4t(bo[0], bo[1], bo[2], bo[3], bBase + 17408 + off);
#pragma unroll
                for (int q = 0; q < 2; q++) {
                    mma_f16(accE[nt + q], aeh, be[2*q], be[2*q + 1]);
                    mma_f16(accE[nt + q], ael, be[2*q], be[2*q + 1]);
                    mma_f16(accO[nt + q], aoh, bo[2*q], bo[2*q + 1]);
                    mma_f16(accO[nt + q], aol, bo[2*q], bo[2*q + 1]);
                }
            }
        }

        // epilogue: butterfly out[n] = E+O, out[127-n] = E-O
        {
            size_t o = slice0 + sl;
            float bv = bias[o & 127];
            const float is = 1.f / 256.f;
            float* op = outp + o * 16384;
            int n1 = m0 + (lane >> 2);
#pragma unroll
            for (int nt = 0; nt < 8; nt++) {
                int c = n0 + nt*8 + 2*(lane & 3);
                float e0 = accE[nt][0]*is, e1 = accE[nt][1]*is;
                float o0 = accO[nt][0]*is, o1 = accO[nt][1]*is;
                float e2 = accE[nt][2]*is, e3 = accE[nt][3]*is;
                float o2 = accO[nt][2]*is, o3 = accO[nt][3]*is;
                *(float2*)(op + n1*128 + c)         = make_float2(e0 + o0 + bv, e1 + o1 + bv);
                *(float2*)(op + (127 - n1)*128 + c) = make_float2(e0 - o0 + bv, e1 - o1 + bv);
                *(float2*)(op + (n1 + 8)*128 + c)   = make_float2(e2 + o2 + bv, e3 + o3 + bv);
                *(float2*)(op + (119 - n1)*128 + c) = make_float2(e2 - o2 + bv, e3 - o3 + bv);
            }
        }
        if (sl == 0) { CP_WAIT(0); __syncthreads(); }
    }
}

// ---------------- stage 3: per (b,k): y = (wd64 conv xd)/64 (unchanged) ----------------
#define TS3 144
__global__ __launch_bounds__(256, 2)
void k_conv_mma() {
    extern __shared__ __align__(16) char sm[];
    const u32 OFF_B = 0, OFF_A0 = 18432, OFF_A1 = 55296;
    u32 sb = smem_u32(sm);
    int tid = threadIdx.x, wid = tid >> 5, lane = tid & 31;
    int blk = blockIdx.x, b = blk >> 7, k = blk & 127;

    for (int i = tid; i < 1024; i += 256) {
        int c = i >> 4, ch = i & 15;
        size_t gi = ((size_t)(b*64 + c)*128 + k)*64 + ch*4;
        cp16(sb + OFF_A1 + i*16, g_xd16 + gi);
    }
    CP_COMMIT();
    {
        size_t wbase = (size_t)(k*5 + 0) * 4096;
        for (int i = tid; i < 1024; i += 256) {
            int o = i >> 3, ch = i & 7;
            cp16(sb + OFF_A0 +         o*TS3 + ch*16, g_wdh + wbase + o*32 + ch*4);
            cp16(sb + OFF_A0 + 18432 + o*TS3 + ch*16, g_wdl + wbase + o*32 + ch*4);
        }
        CP_COMMIT();
    }
    CP_WAIT(1);
    __syncthreads();
    {
        const u16* sh = (const u16*)(sm + OFF_A1);
        u32* dB = (u32*)(sm + OFF_B);
        for (int i = tid; i < 4096; i += 256) {
            int w = i & 127, cp = i >> 7;
            dB[w*36 + cp] = (u32)sh[(2*cp)*128 + w] | ((u32)sh[(2*cp + 1)*128 + w] << 16);
        }
    }
    CP_WAIT(0);
    __syncthreads();

    int m0 = (wid >> 1) * 32, n0 = (wid & 1) * 64;
    int rowA = lane & 15;
    int kA = (lane & 16) ? 8 : 0;
    int rowB = lane & 7;
    int kB = (lane & 8) ? 8 : 0;
    int ntAdd = (lane & 16) ? 8 : 0;

    float acc[2][8][4];
#pragma unroll
    for (int mt = 0; mt < 2; mt++)
#pragma unroll
        for (int nt = 0; nt < 8; nt++)
#pragma unroll
            for (int q = 0; q < 4; q++) acc[mt][nt][q] = 0.f;

#pragma unroll
    for (int j = 0; j < 5; j++) {
        if (j < 4) {
            size_t wbase = (size_t)(k*5 + j + 1) * 4096;
            u32 dst = sb + (((j + 1) & 1) ? OFF_A1 : OFF_A0);
            for (int i = tid; i < 1024; i += 256) {
                int o = i >> 3, ch = i & 7;
                cp16(dst +         o*TS3 + ch*16, g_wdh + wbase + o*32 + ch*4);
                cp16(dst + 18432 + o*TS3 + ch*16, g_wdl + wbase + o*32 + ch*4);
            }
            CP_COMMIT();
        }
        u32 aBase = sb + ((j & 1) ? OFF_A1 : OFF_A0);
#pragma unroll
        for (int ks = 0; ks < 4; ks++) {
            int k0 = ks * 16;
            u32 ah[2][4], al[2][4];
#pragma unroll
            for (int mt = 0; mt < 2; mt++) {
                u32 base = (u32)((m0 + mt*16 + rowA) * TS3 + (k0 + kA) * 2);
                ldsm_x4(ah[mt][0], ah[mt][1], ah[mt][2], ah[mt][3], aBase + base);
                ldsm_x4(al[mt][0], al[mt][1], al[mt][2], al[mt][3], aBase + 18432 + base);
            }
#pragma unroll
            for (int nt = 0; nt < 8; nt += 2) {
                int wr = ((n0 + nt*8 + ntAdd + rowB) - j) & 127;
                u32 base = (u32)(wr * TS3 + (k0 + kB) * 2);
                u32 bf[4];
                ldsm_x4(bf[0], bf[1], bf[2], bf[3], sb + OFF_B + base);
#pragma unroll
                for (int q = 0; q < 2; q++)
#pragma unroll
                    for (int mt = 0; mt < 2; mt++) {
                        mma_f16(acc[mt][nt + q], ah[mt], bf[2*q], bf[2*q + 1]);
                        mma_f16(acc[mt][nt + q], al[mt], bf[2*q], bf[2*q + 1]);
                    }
            }
        }
        if (j < 4) { CP_WAIT(0); __syncthreads(); }
    }

    __syncthreads();
    float* se = (float*)(sm);   // [128][129]
#pragma unroll
    for (int mt = 0; mt < 2; mt++)
#pragma unroll
        for (int nt = 0; nt < 8; nt++) {
            int r = m0 + mt*16 + (lane >> 2);
            int c = n0 + nt*8 + 2*(lane & 3);
            se[r*129 + c]           = acc[mt][nt][0];
            se[r*129 + c + 1]       = acc[mt][nt][1];
            se[(r + 8)*129 + c]     = acc[mt][nt][2];
            se[(r + 8)*129 + c + 1] = acc[mt][nt][3];
        }
    __syncthreads();
    const float is = 1.f / 64.f;
    for (int i = tid; i < 8192; i += 256) {
        int o = i >> 6, wp = i & 63;
        size_t gi = ((size_t)(b*128 + o))*8192 + (size_t)k*64 + wp;
        g_y16[gi] = (u32)f2h(se[o*129 + 2*wp] * is) | ((u32)f2h(se[o*129 + 2*wp + 1] * is) << 16);
    }
}

// ---------------- launch ----------------
extern "C" void kernel_launch(void* const* d_in, const int* in_sizes, int n_in,
                              void* d_out, int out_size) {
    const float* x    = (const float*)d_in[0];   // (8,64,128,128)
    const float* wgt  = (const float*)d_in[1];   // (128,64,5,5)
    const float* bias = (const float*)d_in[2];   // (128,)
    float* out = (float*)d_out;                  // (8,128,128,128)

    const int SMD = 71680;    // A 4x9216 + B 2x17408
    const int SMI = 106496;   // A 4x9216 + B 2x34816
    const int SM3 = 92160;
    cudaFuncSetAttribute(k_dct_mma,  cudaFuncAttributeMaxDynamicSharedMemorySize, SMD);
    cudaFuncSetAttribute(k_idct_mma, cudaFuncAttributeMaxDynamicSharedMemorySize, SMI);
    cudaFuncSetAttribute(k_conv_mma, cudaFuncAttributeMaxDynamicSharedMemorySize, SM3);

    k_consts  <<<32, 256>>>();
    k_wtrans  <<<640, 256>>>(wgt);
    k_dct_mma <<<BATCH*CIN,     256, SMD>>>(x);
    k_conv_mma<<<BATCH*HH,      256, SM3>>>();
    k_idct_mma<<<BATCH*COUT/2,  256, SMI>>>(bias, out);
}